// round 2
// baseline (speedup 1.0000x reference)
#include <cuda_runtime.h>

#define V 32768            // 32*32*32
#define CC 219             // concat channels

__device__ float g_x[CC * V];      // concat input [tgt(64), src(64), cost(27), Cup(64)]
__device__ float g_y[CC * V];      // conv1 output
__device__ float g_stats[CC * 2];  // per-channel (mean, rstd)

// ---------------- copy tgt,src into g_x ----------------
__global__ void copy_kernel(const float* __restrict__ tgt, const float* __restrict__ src) {
    int i = blockIdx.x * 256 + threadIdx.x;   // over 64*V/4 float4
    float4* dx = (float4*)g_x;
    dx[i] = ((const float4*)tgt)[i];
    dx[(64 * V) / 4 + i] = ((const float4*)src)[i];
}

// ---------------- correlation volume: cost -> g_x channels 128..154 ----------------
__global__ void __launch_bounds__(256) corr_kernel(const float* __restrict__ tgt,
                                                   const float* __restrict__ src) {
    __shared__ float sp[4 * 6 * 34];  // 816: src patch for one channel
    int tid = threadIdx.x;
    int z0 = (blockIdx.x >> 3) * 2;
    int y0 = (blockIdx.x & 7) * 4;
    int tz = tid >> 7, ty = (tid >> 5) & 3, tx = tid & 31;
    int z = z0 + tz, y = y0 + ty;
    int p = (z << 10) + (y << 5) + tx;

    int poff[4]; bool pval[4];
#pragma unroll
    for (int k = 0; k < 4; k++) {
        int i = k * 256 + tid;
        int pz = i / 204, r = i % 204, py = r / 34, px = r % 34;
        int gz = z0 + pz - 1, gy = y0 + py - 1, gx = px - 1;
        pval[k] = (i < 816) && ((unsigned)gz < 32u) && ((unsigned)gy < 32u) && ((unsigned)gx < 32u);
        poff[k] = (gz << 10) + (gy << 5) + gx;
    }

    float acc[27];
#pragma unroll
    for (int d = 0; d < 27; d++) acc[d] = 0.f;

    for (int c = 0; c < 64; c++) {
        __syncthreads();
#pragma unroll
        for (int k = 0; k < 4; k++) {
            int i = k * 256 + tid;
            if (i < 816) sp[i] = pval[k] ? src[c * V + poff[k]] : 0.f;
        }
        __syncthreads();
        float t = tgt[c * V + p];
#pragma unroll
        for (int dz = 0; dz < 3; dz++)
#pragma unroll
            for (int dy = 0; dy < 3; dy++) {
                int base = ((tz + dz) * 6 + (ty + dy)) * 34 + tx;
                acc[dz * 9 + dy * 3 + 0] += t * sp[base];
                acc[dz * 9 + dy * 3 + 1] += t * sp[base + 1];
                acc[dz * 9 + dy * 3 + 2] += t * sp[base + 2];
            }
    }
    const float inv = 1.f / 64.f;
#pragma unroll
    for (int d = 0; d < 27; d++) g_x[(size_t)(128 + d) * V + p] = acc[d] * inv;
}

// ---------------- conv transpose (upsample): C(411,16^3) -> g_x channels 155..218 ----------------
__global__ void __launch_bounds__(256) upsample_kernel(const float* __restrict__ Cin,
                                                       const float* __restrict__ w,
                                                       const float* __restrict__ bias) {
    __shared__ float swt[16 * 64];       // 16 co x 64 taps for current ci
    __shared__ float spatch[3 * 4 * 18]; // 216 input patch
    int tid = threadIdx.x;
    int z0 = (blockIdx.x >> 3) * 2;
    int y0 = (blockIdx.x & 7) * 4;
    int co0 = blockIdx.y * 16;
    int tz = tid >> 7, ty = (tid >> 5) & 3, tx = tid & 31;
    int oz = z0 + tz, oy = y0 + ty, ox = tx;
    int izb = (z0 >> 1) - 1, iyb = (y0 >> 1) - 1;

    // tap list: out[oz] gets in[iz] via weight kz when oz+1-kz even, iz=(oz+1-kz)/2 in [0,16)
    int taps[8]; int nt = 0;
    for (int kz = (oz + 1) & 1; kz < 4; kz += 2) {
        int iz = (oz + 1 - kz) >> 1; if (iz < 0 || iz >= 16) continue;
        for (int ky = (oy + 1) & 1; ky < 4; ky += 2) {
            int iy = (oy + 1 - ky) >> 1; if (iy < 0 || iy >= 16) continue;
            for (int kx = (ox + 1) & 1; kx < 4; kx += 2) {
                int ix = (ox + 1 - kx) >> 1; if (ix < 0 || ix >= 16) continue;
                int pofs = ((iz - izb) * 4 + (iy - iyb)) * 18 + (ix + 1);
                int wofs = (kz << 4) + (ky << 2) + kx;
                taps[nt++] = pofs | (wofs << 16);
            }
        }
    }

    int pl_off = 0; bool pl_val = false;
    if (tid < 216) {
        int pz = tid / 72, r = tid % 72, py = r / 18, px = r % 18;
        int gz = izb + pz, gy = iyb + py, gx = px - 1;
        pl_val = ((unsigned)gz < 16u) && ((unsigned)gy < 16u) && ((unsigned)gx < 16u);
        pl_off = (gz << 8) + (gy << 4) + gx;
    }

    float acc[16];
#pragma unroll
    for (int j = 0; j < 16; j++) acc[j] = 0.f;

    for (int ci = 0; ci < 411; ci++) {
        __syncthreads();
        if (tid < 216) spatch[tid] = pl_val ? Cin[ci * 4096 + pl_off] : 0.f;
        const float* wc = w + ((size_t)ci * 64 + co0) * 64;
#pragma unroll
        for (int k = 0; k < 4; k++) swt[k * 256 + tid] = wc[k * 256 + tid];
        __syncthreads();
        for (int t = 0; t < nt; t++) {
            int tp = taps[t];
            float v = spatch[tp & 0xffff];
            int wofs = tp >> 16;
#pragma unroll
            for (int j = 0; j < 16; j++) acc[j] += v * swt[(j << 6) + wofs];
        }
    }
    int p = (oz << 10) + (oy << 5) + ox;
#pragma unroll
    for (int j = 0; j < 16; j++)
        g_x[(size_t)(155 + co0 + j) * V + p] = acc[j] + bias[co0 + j];
}

// ---------------- instance norm stats: one block per channel ----------------
__global__ void stats_kernel(const float* __restrict__ x) {
    int ch = blockIdx.x;
    const float4* p4 = (const float4*)(x + (size_t)ch * V);
    float s = 0.f, s2 = 0.f;
    for (int i = threadIdx.x; i < V / 4; i += 256) {
        float4 v = p4[i];
        s += v.x + v.y + v.z + v.w;
        s2 += v.x * v.x + v.y * v.y + v.z * v.z + v.w * v.w;
    }
#pragma unroll
    for (int o = 16; o; o >>= 1) {
        s += __shfl_down_sync(0xffffffffu, s, o);
        s2 += __shfl_down_sync(0xffffffffu, s2, o);
    }
    __shared__ float a[8], b[8];
    int wp = threadIdx.x >> 5, ln = threadIdx.x & 31;
    if (ln == 0) { a[wp] = s; b[wp] = s2; }
    __syncthreads();
    if (threadIdx.x < 8) {
        s = a[threadIdx.x]; s2 = b[threadIdx.x];
#pragma unroll
        for (int o = 4; o; o >>= 1) {
            s += __shfl_down_sync(0xffu, s, o);
            s2 += __shfl_down_sync(0xffu, s2, o);
        }
        if (threadIdx.x == 0) {
            float m = s * (1.f / V);
            float var = s2 * (1.f / V) - m * m;
            g_stats[ch * 2] = m;
            g_stats[ch * 2 + 1] = rsqrtf(var + 1e-5f);
        }
    }
}

// ---------------- normalize + leaky relu in place ----------------
__global__ void norm_leaky_kernel(float* __restrict__ x) {
    int ch = blockIdx.y;
    int i = blockIdx.x * 256 + threadIdx.x;   // V/4 float4 per channel -> grid.x = 32
    float m = g_stats[ch * 2], r = g_stats[ch * 2 + 1];
    float4* p = (float4*)(x + (size_t)ch * V);
    float4 v = p[i];
    v.x = (v.x - m) * r; v.x = v.x >= 0.f ? v.x : 0.1f * v.x;
    v.y = (v.y - m) * r; v.y = v.y >= 0.f ? v.y : 0.1f * v.y;
    v.z = (v.z - m) * r; v.z = v.z >= 0.f ? v.z : 0.1f * v.z;
    v.w = (v.w - m) * r; v.w = v.w >= 0.f ? v.w : 0.1f * v.w;
    p[i] = v;
}

// ---------------- 3x3x3 conv, 219 in channels, tile 4x8x32 spatial x 8 co ----------------
__global__ void __launch_bounds__(256) conv3_kernel(const float* __restrict__ in,
                                                    const float* __restrict__ w,
                                                    const float* __restrict__ bias,
                                                    float* __restrict__ out, int CO) {
    __shared__ float sp[2040];  // 6*10*34 input patch for one ci
    __shared__ float sw[216];   // 8 co x 27 taps
    int tid = threadIdx.x;
    int z0 = (blockIdx.x >> 2) * 4;
    int y0 = (blockIdx.x & 3) * 8;
    int co0 = blockIdx.y * 8;
    int tz = tid >> 6, ty = (tid >> 3) & 7, tx = (tid & 7) << 2;

    int poff[8]; bool pval[8];
#pragma unroll
    for (int k = 0; k < 8; k++) {
        int i = k * 256 + tid;
        int pz = i / 340, r = i % 340, py = r / 34, px = r % 34;
        int gz = z0 + pz - 1, gy = y0 + py - 1, gx = px - 1;
        pval[k] = (i < 2040) && ((unsigned)gz < 32u) && ((unsigned)gy < 32u) && ((unsigned)gx < 32u);
        poff[k] = (gz << 10) + (gy << 5) + gx;
    }
    int wj = tid / 27, wt0 = tid % 27;
    bool wok = (tid < 216) && (co0 + wj < CO);
    size_t wbase = ((size_t)(co0 + wj) * CC) * 27 + wt0;

    float acc[8][4];
#pragma unroll
    for (int j = 0; j < 8; j++) { acc[j][0] = 0.f; acc[j][1] = 0.f; acc[j][2] = 0.f; acc[j][3] = 0.f; }

    for (int ci = 0; ci < CC; ci++) {
        __syncthreads();
        const float* inc = in + (size_t)ci * V;
#pragma unroll
        for (int k = 0; k < 8; k++) {
            int i = k * 256 + tid;
            if (i < 2040) sp[i] = pval[k] ? inc[poff[k]] : 0.f;
        }
        if (tid < 216) sw[tid] = wok ? w[wbase + (size_t)ci * 27] : 0.f;
        __syncthreads();
#pragma unroll
        for (int kz = 0; kz < 3; kz++) {
#pragma unroll
            for (int ky = 0; ky < 3; ky++) {
                int base = ((tz + kz) * 10 + (ty + ky)) * 34 + tx;
                float v[6];
#pragma unroll
                for (int q = 0; q < 6; q++) v[q] = sp[base + q];
#pragma unroll
                for (int kx = 0; kx < 3; kx++) {
                    int wt = (kz * 3 + ky) * 3 + kx;
#pragma unroll
                    for (int j = 0; j < 8; j++) {
                        float wv = sw[j * 27 + wt];
                        acc[j][0] += wv * v[kx];
                        acc[j][1] += wv * v[kx + 1];
                        acc[j][2] += wv * v[kx + 2];
                        acc[j][3] += wv * v[kx + 3];
                    }
                }
            }
        }
    }
    int z = z0 + tz, y = y0 + ty;
    size_t obase = (size_t)(z << 10) + (y << 5) + tx;
#pragma unroll
    for (int j = 0; j < 8; j++) {
        int co = co0 + j;
        if (co < CO) {
            float bb = bias[co];
            float4 o;
            o.x = acc[j][0] + bb; o.y = acc[j][1] + bb;
            o.z = acc[j][2] + bb; o.w = acc[j][3] + bb;
            *(float4*)(out + (size_t)co * V + obase) = o;
        }
    }
}

// ---------------- final 3-channel conv, fine-grained grid ----------------
__global__ void __launch_bounds__(256) conv_out_kernel(const float* __restrict__ in,
                                                       const float* __restrict__ w,
                                                       const float* __restrict__ bias,
                                                       float* __restrict__ out) {
    __shared__ float sp[816];  // 4*6*34
    __shared__ float sw[81];   // 3 co x 27
    int tid = threadIdx.x;
    int z0 = (blockIdx.x >> 3) * 2;
    int y0 = (blockIdx.x & 7) * 4;
    int tz = tid >> 7, ty = (tid >> 5) & 3, tx = tid & 31;

    int poff[4]; bool pval[4];
#pragma unroll
    for (int k = 0; k < 4; k++) {
        int i = k * 256 + tid;
        int pz = i / 204, r = i % 204, py = r / 34, px = r % 34;
        int gz = z0 + pz - 1, gy = y0 + py - 1, gx = px - 1;
        pval[k] = (i < 816) && ((unsigned)gz < 32u) && ((unsigned)gy < 32u) && ((unsigned)gx < 32u);
        poff[k] = (gz << 10) + (gy << 5) + gx;
    }

    float acc[3] = {0.f, 0.f, 0.f};
    for (int ci = 0; ci < CC; ci++) {
        __syncthreads();
#pragma unroll
        for (int k = 0; k < 4; k++) {
            int i = k * 256 + tid;
            if (i < 816) sp[i] = pval[k] ? in[(size_t)ci * V + poff[k]] : 0.f;
        }
        if (tid < 81) sw[tid] = w[((size_t)(tid / 27) * CC + ci) * 27 + tid % 27];
        __syncthreads();
#pragma unroll
        for (int kz = 0; kz < 3; kz++)
#pragma unroll
            for (int ky = 0; ky < 3; ky++) {
                int base = ((tz + kz) * 6 + (ty + ky)) * 34 + tx;
                float v0 = sp[base], v1 = sp[base + 1], v2 = sp[base + 2];
#pragma unroll
                for (int kx = 0; kx < 3; kx++) {
                    int wt = (kz * 3 + ky) * 3 + kx;
                    float vv = (kx == 0) ? v0 : ((kx == 1) ? v1 : v2);
                    acc[0] += sw[wt] * vv;
                    acc[1] += sw[27 + wt] * vv;
                    acc[2] += sw[54 + wt] * vv;
                }
            }
    }
    int p = ((z0 + tz) << 10) + ((y0 + ty) << 5) + tx;
#pragma unroll
    for (int co = 0; co < 3; co++) out[(size_t)co * V + p] = acc[co] + bias[co];
}

extern "C" void kernel_launch(void* const* d_in, const int* in_sizes, int n_in,
                              void* d_out, int out_size) {
    (void)in_sizes; (void)n_in; (void)out_size;
    const float* src   = (const float*)d_in[0];
    const float* tgt   = (const float*)d_in[1];
    const float* C     = (const float*)d_in[2];
    const float* up_w  = (const float*)d_in[3];
    const float* up_b  = (const float*)d_in[4];
    const float* c1_w  = (const float*)d_in[5];
    const float* c1_b  = (const float*)d_in[6];
    const float* c2_w  = (const float*)d_in[7];
    const float* c2_b  = (const float*)d_in[8];
    const float* out_w = (const float*)d_in[9];
    const float* out_b = (const float*)d_in[10];
    float* dout = (float*)d_out;

    float *gx = nullptr, *gy = nullptr;
    cudaGetSymbolAddress((void**)&gx, g_x);
    cudaGetSymbolAddress((void**)&gy, g_y);

    // Stage 1: build concat input
    copy_kernel<<<2048, 256>>>(tgt, src);
    upsample_kernel<<<dim3(128, 4), 256>>>(C, up_w, up_b);
    corr_kernel<<<128, 256>>>(tgt, src);

    // Instance norm + leaky on Cup (channels 155..218 of g_x)
    stats_kernel<<<64, 256>>>(gx + (size_t)155 * V);
    norm_leaky_kernel<<<dim3(32, 64), 256>>>(gx + (size_t)155 * V);

    // conv1 + IN + leaky
    conv3_kernel<<<dim3(32, 28), 256>>>(gx, c1_w, c1_b, gy, CC);
    stats_kernel<<<CC, 256>>>(gy);
    norm_leaky_kernel<<<dim3(32, CC), 256>>>(gy);

    // conv2 + IN + leaky  -> Cn lives in d_out[0 .. 219*V)
    conv3_kernel<<<dim3(32, 28), 256>>>(gy, c2_w, c2_b, dout, CC);
    stats_kernel<<<CC, 256>>>(dout);
    norm_leaky_kernel<<<dim3(32, CC), 256>>>(dout);

    // output conv -> d_out[219*V .. 222*V)
    conv_out_kernel<<<128, 256>>>(dout, out_w, out_b, dout + (size_t)CC * V);
}

// round 4
// speedup vs baseline: 1.5640x; 1.5640x over previous
#include <cuda_runtime.h>
#include <cstdint>

#define V 32768            // 32*32*32
#define CC 219             // real channels
#define CP 224             // padded channels (multiple of 32)

__device__ float g_x[CP * V];          // concat input [tgt(64), src(64), cost(27), Cup(64), pad(5)=0]
__device__ float g_y[CP * V];          // conv1 output (padded)
__device__ float g_wr[27 * 7 * 7168];  // pre-swizzled B: [(tap*7+cib)*7168 + co*32 + (ci32 ^ ((co&7)<<2))]
__device__ float g_stats[CC * 2];      // per-channel (mean, rstd)

__device__ __forceinline__ float rtf32(float x) {
    uint32_t u;
    asm("cvt.rna.tf32.f32 %0, %1;" : "=r"(u) : "f"(x));
    return __uint_as_float(u);
}

__device__ __forceinline__ void mma_tf32(float d[4], const uint32_t a[4], const uint32_t b[2]) {
    asm volatile(
        "mma.sync.aligned.m16n8k8.row.col.f32.tf32.tf32.f32 "
        "{%0,%1,%2,%3}, {%4,%5,%6,%7}, {%8,%9}, {%0,%1,%2,%3};"
        : "+f"(d[0]), "+f"(d[1]), "+f"(d[2]), "+f"(d[3])
        : "r"(a[0]), "r"(a[1]), "r"(a[2]), "r"(a[3]), "r"(b[0]), "r"(b[1]));
}

// ======================= small kernels =======================
__global__ void pad_zero_kernel() {
    int i = blockIdx.x * 256 + threadIdx.x;      // over 5*V
    g_x[(size_t)CC * V + i] = 0.f;
    g_y[(size_t)CC * V + i] = 0.f;
}

__global__ void copy_kernel(const float* __restrict__ tgt, const float* __restrict__ src) {
    int i = blockIdx.x * 256 + threadIdx.x;   // over 64*V/4 float4
    float4* dx = (float4*)g_x;
    dx[i] = ((const float4*)tgt)[i];
    dx[(64 * V) / 4 + i] = ((const float4*)src)[i];
}

// weight reorder + tf32 round + pre-swizzle
__global__ void reorder_w_kernel(const float* __restrict__ w) {
    int id = blockIdx.x * 256 + threadIdx.x;     // < 27*7*7168 = 1354752
    int blob = id / 7168, r = id % 7168;
    int tap = blob / 7, cib = blob % 7;
    int co = r >> 5, jj = r & 31;
    int j = jj ^ ((co & 7) << 2);
    int ci = cib * 32 + j;
    float v = 0.f;
    if (co < CC && ci < CC) v = w[((size_t)co * CC + ci) * 27 + tap];
    g_wr[id] = rtf32(v);
}

// ======================= correlation volume =======================
__global__ void __launch_bounds__(256) corr_kernel(const float* __restrict__ tgt,
                                                   const float* __restrict__ src) {
    __shared__ float sp[4 * 6 * 34];
    int tid = threadIdx.x;
    int z0 = (blockIdx.x >> 3) * 2;
    int y0 = (blockIdx.x & 7) * 4;
    int tz = tid >> 7, ty = (tid >> 5) & 3, tx = tid & 31;
    int z = z0 + tz, y = y0 + ty;
    int p = (z << 10) + (y << 5) + tx;

    int poff[4]; bool pval[4];
#pragma unroll
    for (int k = 0; k < 4; k++) {
        int i = k * 256 + tid;
        int pz = i / 204, r = i % 204, py = r / 34, px = r % 34;
        int gz = z0 + pz - 1, gy = y0 + py - 1, gx = px - 1;
        pval[k] = (i < 816) && ((unsigned)gz < 32u) && ((unsigned)gy < 32u) && ((unsigned)gx < 32u);
        poff[k] = (gz << 10) + (gy << 5) + gx;
    }
    float acc[27];
#pragma unroll
    for (int d = 0; d < 27; d++) acc[d] = 0.f;
    for (int c = 0; c < 64; c++) {
        __syncthreads();
#pragma unroll
        for (int k = 0; k < 4; k++) {
            int i = k * 256 + tid;
            if (i < 816) sp[i] = pval[k] ? src[c * V + poff[k]] : 0.f;
        }
        __syncthreads();
        float t = tgt[c * V + p];
#pragma unroll
        for (int dz = 0; dz < 3; dz++)
#pragma unroll
            for (int dy = 0; dy < 3; dy++) {
                int base = ((tz + dz) * 6 + (ty + dy)) * 34 + tx;
                acc[dz * 9 + dy * 3 + 0] += t * sp[base];
                acc[dz * 9 + dy * 3 + 1] += t * sp[base + 1];
                acc[dz * 9 + dy * 3 + 2] += t * sp[base + 2];
            }
    }
    const float inv = 1.f / 64.f;
#pragma unroll
    for (int d = 0; d < 27; d++) g_x[(size_t)(128 + d) * V + p] = acc[d] * inv;
}

// ======================= conv transpose upsample =======================
__global__ void __launch_bounds__(256) upsample_kernel(const float* __restrict__ Cin,
                                                       const float* __restrict__ w,
                                                       const float* __restrict__ bias) {
    __shared__ float swt[16 * 64];
    __shared__ float spatch[3 * 4 * 18];
    int tid = threadIdx.x;
    int z0 = (blockIdx.x >> 3) * 2;
    int y0 = (blockIdx.x & 7) * 4;
    int co0 = blockIdx.y * 16;
    int tz = tid >> 7, ty = (tid >> 5) & 3, tx = tid & 31;
    int oz = z0 + tz, oy = y0 + ty, ox = tx;
    int izb = (z0 >> 1) - 1, iyb = (y0 >> 1) - 1;

    int taps[8]; int nt = 0;
    for (int kz = (oz + 1) & 1; kz < 4; kz += 2) {
        int iz = (oz + 1 - kz) >> 1; if (iz < 0 || iz >= 16) continue;
        for (int ky = (oy + 1) & 1; ky < 4; ky += 2) {
            int iy = (oy + 1 - ky) >> 1; if (iy < 0 || iy >= 16) continue;
            for (int kx = (ox + 1) & 1; kx < 4; kx += 2) {
                int ix = (ox + 1 - kx) >> 1; if (ix < 0 || ix >= 16) continue;
                int pofs = ((iz - izb) * 4 + (iy - iyb)) * 18 + (ix + 1);
                int wofs = (kz << 4) + (ky << 2) + kx;
                taps[nt++] = pofs | (wofs << 16);
            }
        }
    }
    int pl_off = 0; bool pl_val = false;
    if (tid < 216) {
        int pz = tid / 72, r = tid % 72, py = r / 18, px = r % 18;
        int gz = izb + pz, gy = iyb + py, gx = px - 1;
        pl_val = ((unsigned)gz < 16u) && ((unsigned)gy < 16u) && ((unsigned)gx < 16u);
        pl_off = (gz << 8) + (gy << 4) + gx;
    }
    float acc[16];
#pragma unroll
    for (int j = 0; j < 16; j++) acc[j] = 0.f;
    for (int ci = 0; ci < 411; ci++) {
        __syncthreads();
        if (tid < 216) spatch[tid] = pl_val ? Cin[ci * 4096 + pl_off] : 0.f;
        const float* wc = w + ((size_t)ci * 64 + co0) * 64;
#pragma unroll
        for (int k = 0; k < 4; k++) swt[k * 256 + tid] = wc[k * 256 + tid];
        __syncthreads();
        for (int t = 0; t < nt; t++) {
            int tp = taps[t];
            float v = spatch[tp & 0xffff];
            int wofs = tp >> 16;
#pragma unroll
            for (int j = 0; j < 16; j++) acc[j] += v * swt[(j << 6) + wofs];
        }
    }
    int p = (oz << 10) + (oy << 5) + ox;
#pragma unroll
    for (int j = 0; j < 16; j++)
        g_x[(size_t)(155 + co0 + j) * V + p] = acc[j] + bias[co0 + j];
}

// ======================= instance norm =======================
__global__ void stats_kernel(const float* __restrict__ x) {
    int ch = blockIdx.x;
    const float4* p4 = (const float4*)(x + (size_t)ch * V);
    float s = 0.f, s2 = 0.f;
    for (int i = threadIdx.x; i < V / 4; i += 256) {
        float4 v = p4[i];
        s += v.x + v.y + v.z + v.w;
        s2 += v.x * v.x + v.y * v.y + v.z * v.z + v.w * v.w;
    }
#pragma unroll
    for (int o = 16; o; o >>= 1) {
        s += __shfl_down_sync(0xffffffffu, s, o);
        s2 += __shfl_down_sync(0xffffffffu, s2, o);
    }
    __shared__ float a[8], b[8];
    int wp = threadIdx.x >> 5, ln = threadIdx.x & 31;
    if (ln == 0) { a[wp] = s; b[wp] = s2; }
    __syncthreads();
    if (threadIdx.x < 8) {
        s = a[threadIdx.x]; s2 = b[threadIdx.x];
#pragma unroll
        for (int o = 4; o; o >>= 1) {
            s += __shfl_down_sync(0xffu, s, o);
            s2 += __shfl_down_sync(0xffu, s2, o);
        }
        if (threadIdx.x == 0) {
            float m = s * (1.f / V);
            float var = s2 * (1.f / V) - m * m;
            g_stats[ch * 2] = m;
            g_stats[ch * 2 + 1] = rsqrtf(var + 1e-5f);
        }
    }
}

__global__ void norm_leaky_kernel(float* __restrict__ x) {
    int ch = blockIdx.y;
    int i = blockIdx.x * 256 + threadIdx.x;
    float m = g_stats[ch * 2], r = g_stats[ch * 2 + 1];
    float4* p = (float4*)(x + (size_t)ch * V);
    float4 v = p[i];
    v.x = (v.x - m) * r; v.x = v.x >= 0.f ? v.x : 0.1f * v.x;
    v.y = (v.y - m) * r; v.y = v.y >= 0.f ? v.y : 0.1f * v.y;
    v.z = (v.z - m) * r; v.z = v.z >= 0.f ? v.z : 0.1f * v.z;
    v.w = (v.w - m) * r; v.w = v.w >= 0.f ? v.w : 0.1f * v.w;
    p[i] = v;
}

// ======================= tf32 HMMA implicit-GEMM conv3x3x3 =======================
// CTA: M=128 (z fixed, 4 y, 32 x) x N=64 co. 8 warps (4Mx2N), warp tile 32x32.
// K: 189 chunks of 32 (tap x 32ci). Double-buffered SMEM A(16KB)+B(8KB) per buf.
__global__ void __launch_bounds__(256) conv3_mma_kernel(const float* __restrict__ in,
                                                        const float* __restrict__ bias,
                                                        float* __restrict__ out) {
    __shared__ float sA[2][128 * 32];
    __shared__ float sB[2][64 * 32];

    int tid = threadIdx.x, wid = tid >> 5, lane = tid & 31;
    int z = blockIdx.x >> 3, y0 = (blockIdx.x & 7) << 2;
    int co0 = blockIdx.y << 6;

    int wm = wid >> 1, wn = wid & 1;
    int r4 = lane >> 2, c4 = lane & 3;

    // A-build constants: thread = (row m = tid&127, ci parity hi = tid>>7)
    int m = tid & 127;
    int hi = tid >> 7;
    int yl = m >> 5;
    int x = m & 31;
    int sw = (m & 7) << 2;

    float acc[2][4][4];
#pragma unroll
    for (int a = 0; a < 2; a++)
#pragma unroll
        for (int b = 0; b < 4; b++)
#pragma unroll
            for (int c = 0; c < 4; c++) acc[a][b][c] = 0.f;

    float areg[16];
    float4 breg[2];

#define BUILD_LDG(s) do { \
        int cib = (s) / 27, tap = (s) % 27; \
        int dz = tap / 9 - 1, dy = (tap / 3) % 3 - 1, dx = tap % 3 - 1; \
        int zz = z + dz, yy = y0 + yl + dy, xx = x + dx; \
        bool ok = ((unsigned)zz < 32u) && ((unsigned)yy < 32u) && ((unsigned)xx < 32u); \
        const float* p = in + (size_t)(cib * 32 + hi) * V + (zz << 10) + (yy << 5) + xx; \
        _Pragma("unroll") \
        for (int i = 0; i < 16; i++) areg[i] = ok ? __ldg(p + (size_t)(2 * i) * V) : 0.f; \
        const float4* s4 = (const float4*)(g_wr + (size_t)(tap * 7 + cib) * 7168 + co0 * 32); \
        breg[0] = s4[tid]; breg[1] = s4[256 + tid]; \
    } while (0)

#define BUILD_STS(buf) do { \
        float* arow = &sA[buf][m * 32]; \
        _Pragma("unroll") \
        for (int i = 0; i < 16; i++) arow[(2 * i + hi) ^ sw] = rtf32(areg[i]); \
        ((float4*)sB[buf])[tid] = breg[0]; \
        ((float4*)sB[buf])[256 + tid] = breg[1]; \
    } while (0)

#define COMPUTE(buf) do { \
        const float* A = sA[buf]; \
        const float* B = sB[buf]; \
        _Pragma("unroll") \
        for (int ks = 0; ks < 4; ks++) { \
            int k0 = ks << 3; \
            uint32_t af[2][4], bf[4][2]; \
            _Pragma("unroll") \
            for (int mt = 0; mt < 2; mt++) { \
                int mr = (wm << 5) + (mt << 4) + r4; \
                int sw8 = (mr & 7) << 2; \
                af[mt][0] = __float_as_uint(A[mr * 32 + ((k0 + c4) ^ sw8)]); \
                af[mt][1] = __float_as_uint(A[(mr + 8) * 32 + ((k0 + c4) ^ sw8)]); \
                af[mt][2] = __float_as_uint(A[mr * 32 + ((k0 + c4 + 4) ^ sw8)]); \
                af[mt][3] = __float_as_uint(A[(mr + 8) * 32 + ((k0 + c4 + 4) ^ sw8)]); \
            } \
            _Pragma("unroll") \
            for (int nt = 0; nt < 4; nt++) { \
                int co = (wn << 5) + (nt << 3) + r4; \
                int swb = (co & 7) << 2; \
                bf[nt][0] = __float_as_uint(B[co * 32 + ((k0 + c4) ^ swb)]); \
                bf[nt][1] = __float_as_uint(B[co * 32 + ((k0 + c4 + 4) ^ swb)]); \
            } \
            _Pragma("unroll") \
            for (int mt = 0; mt < 2; mt++) \
                _Pragma("unroll") \
                for (int nt = 0; nt < 4; nt++) \
                    mma_tf32(acc[mt][nt], af[mt], bf[nt]); \
        } \
    } while (0)

    BUILD_LDG(0);
    BUILD_STS(0);
    __syncthreads();

    for (int s = 0; s < 189; s++) {
        int buf = s & 1;
        if (s < 188) BUILD_LDG(s + 1);
        COMPUTE(buf);
        if (s < 188) BUILD_STS(buf ^ 1);
        __syncthreads();
    }

    // epilogue: scatter accumulators + bias
#pragma unroll
    for (int mt = 0; mt < 2; mt++) {
        int mr = (wm << 5) + (mt << 4) + r4;
        int pos1 = (z << 10) + ((y0 + (mr >> 5)) << 5) + (mr & 31);
        int mr2 = mr + 8;
        int pos2 = (z << 10) + ((y0 + (mr2 >> 5)) << 5) + (mr2 & 31);
#pragma unroll
        for (int nt = 0; nt < 4; nt++) {
            int c = co0 + (wn << 5) + (nt << 3) + (c4 << 1);
            if (c < CC) {
                float bb = bias[c];
                out[(size_t)c * V + pos1] = acc[mt][nt][0] + bb;
                out[(size_t)c * V + pos2] = acc[mt][nt][2] + bb;
            }
            if (c + 1 < CC) {
                float bb = bias[c + 1];
                out[(size_t)(c + 1) * V + pos1] = acc[mt][nt][1] + bb;
                out[(size_t)(c + 1) * V + pos2] = acc[mt][nt][3] + bb;
            }
        }
    }
}

// ======================= final 3-channel conv (fp32) =======================
__global__ void __launch_bounds__(256) conv_out_kernel(const float* __restrict__ in,
                                                       const float* __restrict__ w,
                                                       const float* __restrict__ bias,
                                                       float* __restrict__ out) {
    __shared__ float sp[816];
    __shared__ float sw[81];
    int tid = threadIdx.x;
    int z0 = (blockIdx.x >> 3) * 2;
    int y0 = (blockIdx.x & 7) * 4;
    int tz = tid >> 7, ty = (tid >> 5) & 3, tx = tid & 31;

    int poff[4]; bool pval[4];
#pragma unroll
    for (int k = 0; k < 4; k++) {
        int i = k * 256 + tid;
        int pz = i / 204, r = i % 204, py = r / 34, px = r % 34;
        int gz = z0 + pz - 1, gy = y0 + py - 1, gx = px - 1;
        pval[k] = (i < 816) && ((unsigned)gz < 32u) && ((unsigned)gy < 32u) && ((unsigned)gx < 32u);
        poff[k] = (gz << 10) + (gy << 5) + gx;
    }
    float acc[3] = {0.f, 0.f, 0.f};
    for (int ci = 0; ci < CC; ci++) {
        __syncthreads();
#pragma unroll
        for (int k = 0; k < 4; k++) {
            int i = k * 256 + tid;
            if (i < 816) sp[i] = pval[k] ? in[(size_t)ci * V + poff[k]] : 0.f;
        }
        if (tid < 81) sw[tid] = w[((size_t)(tid / 27) * CC + ci) * 27 + tid % 27];
        __syncthreads();
#pragma unroll
        for (int kz = 0; kz < 3; kz++)
#pragma unroll
            for (int ky = 0; ky < 3; ky++) {
                int base = ((tz + kz) * 6 + (ty + ky)) * 34 + tx;
                float v0 = sp[base], v1 = sp[base + 1], v2 = sp[base + 2];
#pragma unroll
                for (int kx = 0; kx < 3; kx++) {
                    int wt = (kz * 3 + ky) * 3 + kx;
                    float vv = (kx == 0) ? v0 : ((kx == 1) ? v1 : v2);
                    acc[0] += sw[wt] * vv;
                    acc[1] += sw[27 + wt] * vv;
                    acc[2] += sw[54 + wt] * vv;
                }
            }
    }
    int p = ((z0 + tz) << 10) + ((y0 + ty) << 5) + tx;
#pragma unroll
    for (int co = 0; co < 3; co++) out[(size_t)co * V + p] = acc[co] + bias[co];
}

// ======================= launch =======================
extern "C" void kernel_launch(void* const* d_in, const int* in_sizes, int n_in,
                              void* d_out, int out_size) {
    (void)in_sizes; (void)n_in; (void)out_size;
    const float* src   = (const float*)d_in[0];
    const float* tgt   = (const float*)d_in[1];
    const float* C     = (const float*)d_in[2];
    const float* up_w  = (const float*)d_in[3];
    const float* up_b  = (const float*)d_in[4];
    const float* c1_w  = (const float*)d_in[5];
    const float* c1_b  = (const float*)d_in[6];
    const float* c2_w  = (const float*)d_in[7];
    const float* c2_b  = (const float*)d_in[8];
    const float* out_w = (const float*)d_in[9];
    const float* out_b = (const float*)d_in[10];
    float* dout = (float*)d_out;

    float *gx = nullptr, *gy = nullptr;
    cudaGetSymbolAddress((void**)&gx, g_x);
    cudaGetSymbolAddress((void**)&gy, g_y);

    // Stage 1: build concat input (224 channels, pads zeroed)
    pad_zero_kernel<<<640, 256>>>();
    copy_kernel<<<2048, 256>>>(tgt, src);
    upsample_kernel<<<dim3(128, 4), 256>>>(C, up_w, up_b);
    corr_kernel<<<128, 256>>>(tgt, src);

    // IN + leaky on Cup (channels 155..218)
    stats_kernel<<<64, 256>>>(gx + (size_t)155 * V);
    norm_leaky_kernel<<<dim3(32, 64), 256>>>(gx + (size_t)155 * V);

    // conv1 (tf32 HMMA) + IN + leaky
    reorder_w_kernel<<<5292, 256>>>(c1_w);
    conv3_mma_kernel<<<dim3(256, 4), 256>>>(gx, c1_b, gy);
    stats_kernel<<<CC, 256>>>(gy);
    norm_leaky_kernel<<<dim3(32, CC), 256>>>(gy);

    // conv2 (tf32 HMMA) + IN + leaky  -> Cn in d_out[0 .. 219*V)
    reorder_w_kernel<<<5292, 256>>>(c2_w);
    conv3_mma_kernel<<<dim3(256, 4), 256>>>(gy, c2_b, dout);
    stats_kernel<<<CC, 256>>>(dout);
    norm_leaky_kernel<<<dim3(32, CC), 256>>>(dout);

    // output conv -> d_out[219*V .. 222*V)
    conv_out_kernel<<<128, 256>>>(dout, out_w, out_b, dout + (size_t)CC * V);
}

// round 5
// speedup vs baseline: 1.6779x; 1.0729x over previous
#include <cuda_runtime.h>
#include <cstdint>

#define V 32768            // 32*32*32
#define CC 219             // real channels
#define CP 224             // padded channels (multiple of 32)

__device__ float g_x[CP * V];          // concat input [tgt(64), src(64), cost(27), Cup(64), pad(5)=0]
__device__ float g_y[CP * V];          // conv1 output (padded)
__device__ float g_wr[27 * 7 * 7168];  // pre-swizzled B: [(tap*7+cib)*7168 + co*32 + (ci32 ^ ((co&7)<<2))]
__device__ float g_stats[CC * 2];      // per-channel (mean, rstd)

__device__ __forceinline__ float rtf32(float x) {
    uint32_t u;
    asm("cvt.rna.tf32.f32 %0, %1;" : "=r"(u) : "f"(x));
    return __uint_as_float(u);
}

__device__ __forceinline__ void mma_tf32(float d[4], const uint32_t a[4], const uint32_t b[2]) {
    asm volatile(
        "mma.sync.aligned.m16n8k8.row.col.f32.tf32.tf32.f32 "
        "{%0,%1,%2,%3}, {%4,%5,%6,%7}, {%8,%9}, {%0,%1,%2,%3};"
        : "+f"(d[0]), "+f"(d[1]), "+f"(d[2]), "+f"(d[3])
        : "r"(a[0]), "r"(a[1]), "r"(a[2]), "r"(a[3]), "r"(b[0]), "r"(b[1]));
}

// ======================= small kernels =======================
__global__ void pad_zero_kernel() {
    int i = blockIdx.x * 256 + threadIdx.x;      // over 5*V
    g_x[(size_t)CC * V + i] = 0.f;
    g_y[(size_t)CC * V + i] = 0.f;
}

__global__ void copy_kernel(const float* __restrict__ tgt, const float* __restrict__ src) {
    int i = blockIdx.x * 256 + threadIdx.x;   // over 64*V/4 float4
    float4* dx = (float4*)g_x;
    dx[i] = ((const float4*)tgt)[i];
    dx[(64 * V) / 4 + i] = ((const float4*)src)[i];
}

// weight reorder + tf32 round + pre-swizzle
__global__ void reorder_w_kernel(const float* __restrict__ w) {
    int id = blockIdx.x * 256 + threadIdx.x;     // < 27*7*7168 = 1354752
    int blob = id / 7168, r = id % 7168;
    int tap = blob / 7, cib = blob % 7;
    int co = r >> 5, jj = r & 31;
    int j = jj ^ ((co & 7) << 2);
    int ci = cib * 32 + j;
    float v = 0.f;
    if (co < CC && ci < CC) v = w[((size_t)co * CC + ci) * 27 + tap];
    g_wr[id] = rtf32(v);
}

// ======================= correlation volume =======================
__global__ void __launch_bounds__(256) corr_kernel(const float* __restrict__ tgt,
                                                   const float* __restrict__ src) {
    __shared__ float sp[4 * 6 * 34];
    int tid = threadIdx.x;
    int z0 = (blockIdx.x >> 3) * 2;
    int y0 = (blockIdx.x & 7) * 4;
    int tz = tid >> 7, ty = (tid >> 5) & 3, tx = tid & 31;
    int z = z0 + tz, y = y0 + ty;
    int p = (z << 10) + (y << 5) + tx;

    int poff[4]; bool pval[4];
#pragma unroll
    for (int k = 0; k < 4; k++) {
        int i = k * 256 + tid;
        int pz = i / 204, r = i % 204, py = r / 34, px = r % 34;
        int gz = z0 + pz - 1, gy = y0 + py - 1, gx = px - 1;
        pval[k] = (i < 816) && ((unsigned)gz < 32u) && ((unsigned)gy < 32u) && ((unsigned)gx < 32u);
        poff[k] = (gz << 10) + (gy << 5) + gx;
    }
    float acc[27];
#pragma unroll
    for (int d = 0; d < 27; d++) acc[d] = 0.f;
    for (int c = 0; c < 64; c++) {
        __syncthreads();
#pragma unroll
        for (int k = 0; k < 4; k++) {
            int i = k * 256 + tid;
            if (i < 816) sp[i] = pval[k] ? src[c * V + poff[k]] : 0.f;
        }
        __syncthreads();
        float t = tgt[c * V + p];
#pragma unroll
        for (int dz = 0; dz < 3; dz++)
#pragma unroll
            for (int dy = 0; dy < 3; dy++) {
                int base = ((tz + dz) * 6 + (ty + dy)) * 34 + tx;
                acc[dz * 9 + dy * 3 + 0] += t * sp[base];
                acc[dz * 9 + dy * 3 + 1] += t * sp[base + 1];
                acc[dz * 9 + dy * 3 + 2] += t * sp[base + 2];
            }
    }
    const float inv = 1.f / 64.f;
#pragma unroll
    for (int d = 0; d < 27; d++) g_x[(size_t)(128 + d) * V + p] = acc[d] * inv;
}

// ======================= conv transpose upsample =======================
__global__ void __launch_bounds__(256) upsample_kernel(const float* __restrict__ Cin,
                                                       const float* __restrict__ w,
                                                       const float* __restrict__ bias) {
    __shared__ float swt[16 * 64];
    __shared__ float spatch[3 * 4 * 18];
    int tid = threadIdx.x;
    int z0 = (blockIdx.x >> 3) * 2;
    int y0 = (blockIdx.x & 7) * 4;
    int co0 = blockIdx.y * 16;
    int tz = tid >> 7, ty = (tid >> 5) & 3, tx = tid & 31;
    int oz = z0 + tz, oy = y0 + ty, ox = tx;
    int izb = (z0 >> 1) - 1, iyb = (y0 >> 1) - 1;

    int taps[8]; int nt = 0;
    for (int kz = (oz + 1) & 1; kz < 4; kz += 2) {
        int iz = (oz + 1 - kz) >> 1; if (iz < 0 || iz >= 16) continue;
        for (int ky = (oy + 1) & 1; ky < 4; ky += 2) {
            int iy = (oy + 1 - ky) >> 1; if (iy < 0 || iy >= 16) continue;
            for (int kx = (ox + 1) & 1; kx < 4; kx += 2) {
                int ix = (ox + 1 - kx) >> 1; if (ix < 0 || ix >= 16) continue;
                int pofs = ((iz - izb) * 4 + (iy - iyb)) * 18 + (ix + 1);
                int wofs = (kz << 4) + (ky << 2) + kx;
                taps[nt++] = pofs | (wofs << 16);
            }
        }
    }
    int pl_off = 0; bool pl_val = false;
    if (tid < 216) {
        int pz = tid / 72, r = tid % 72, py = r / 18, px = r % 18;
        int gz = izb + pz, gy = iyb + py, gx = px - 1;
        pl_val = ((unsigned)gz < 16u) && ((unsigned)gy < 16u) && ((unsigned)gx < 16u);
        pl_off = (gz << 8) + (gy << 4) + gx;
    }
    float acc[16];
#pragma unroll
    for (int j = 0; j < 16; j++) acc[j] = 0.f;
    for (int ci = 0; ci < 411; ci++) {
        __syncthreads();
        if (tid < 216) spatch[tid] = pl_val ? Cin[ci * 4096 + pl_off] : 0.f;
        const float* wc = w + ((size_t)ci * 64 + co0) * 64;
#pragma unroll
        for (int k = 0; k < 4; k++) swt[k * 256 + tid] = wc[k * 256 + tid];
        __syncthreads();
        for (int t = 0; t < nt; t++) {
            int tp = taps[t];
            float v = spatch[tp & 0xffff];
            int wofs = tp >> 16;
#pragma unroll
            for (int j = 0; j < 16; j++) acc[j] += v * swt[(j << 6) + wofs];
        }
    }
    int p = (oz << 10) + (oy << 5) + ox;
#pragma unroll
    for (int j = 0; j < 16; j++)
        g_x[(size_t)(155 + co0 + j) * V + p] = acc[j] + bias[co0 + j];
}

// ======================= instance norm =======================
__global__ void stats_kernel(const float* __restrict__ x) {
    int ch = blockIdx.x;
    const float4* p4 = (const float4*)(x + (size_t)ch * V);
    float s = 0.f, s2 = 0.f;
    for (int i = threadIdx.x; i < V / 4; i += 256) {
        float4 v = p4[i];
        s += v.x + v.y + v.z + v.w;
        s2 += v.x * v.x + v.y * v.y + v.z * v.z + v.w * v.w;
    }
#pragma unroll
    for (int o = 16; o; o >>= 1) {
        s += __shfl_down_sync(0xffffffffu, s, o);
        s2 += __shfl_down_sync(0xffffffffu, s2, o);
    }
    __shared__ float a[8], b[8];
    int wp = threadIdx.x >> 5, ln = threadIdx.x & 31;
    if (ln == 0) { a[wp] = s; b[wp] = s2; }
    __syncthreads();
    if (threadIdx.x < 8) {
        s = a[threadIdx.x]; s2 = b[threadIdx.x];
#pragma unroll
        for (int o = 4; o; o >>= 1) {
            s += __shfl_down_sync(0xffu, s, o);
            s2 += __shfl_down_sync(0xffu, s2, o);
        }
        if (threadIdx.x == 0) {
            float m = s * (1.f / V);
            float var = s2 * (1.f / V) - m * m;
            g_stats[ch * 2] = m;
            g_stats[ch * 2 + 1] = rsqrtf(var + 1e-5f);
        }
    }
}

__global__ void norm_leaky_kernel(float* __restrict__ x) {
    int ch = blockIdx.y;
    int i = blockIdx.x * 256 + threadIdx.x;
    float m = g_stats[ch * 2], r = g_stats[ch * 2 + 1];
    float4* p = (float4*)(x + (size_t)ch * V);
    float4 v = p[i];
    v.x = (v.x - m) * r; v.x = v.x >= 0.f ? v.x : 0.1f * v.x;
    v.y = (v.y - m) * r; v.y = v.y >= 0.f ? v.y : 0.1f * v.y;
    v.z = (v.z - m) * r; v.z = v.z >= 0.f ? v.z : 0.1f * v.z;
    v.w = (v.w - m) * r; v.w = v.w >= 0.f ? v.w : 0.1f * v.w;
    p[i] = v;
}

// ======================= tf32 HMMA conv3x3x3 with persistent SMEM patch =======================
// CTA: M=256 (2z x 4y x 32x) x N=112 co (co-split 2). 512 threads = 16 warps (8 wm x 2 wn),
// warp tile 32M x 56N. Per ci-block(32): stage 4x6x34 halo patch once; 27 taps read fragments
// directly from it. B tiles (112x32) double-buffered from pre-swizzled g_wr.
// Dyn SMEM: patch 26112 f + 2 x 3584 f = 133120 B.
__global__ void __launch_bounds__(512) conv3_mma_kernel(const float* __restrict__ in,
                                                        const float* __restrict__ bias,
                                                        float* __restrict__ out) {
    extern __shared__ float smem[];
    float* P = smem;                 // patch: 816 voxels x 32 ci, swizzled
    float* B[2] = { smem + 26112, smem + 26112 + 3584 };

    int tid = threadIdx.x, wid = tid >> 5, lane = tid & 31;
    int zt = blockIdx.x >> 3, yt = blockIdx.x & 7;
    int z0 = zt * 2, y0 = yt * 4;
    int co0 = blockIdx.y * 112;

    int wm = wid >> 1, wn = wid & 1;
    int r4 = lane >> 2, c4 = lane & 3;
    int pzw = wm >> 2, yw = wm & 3;          // warp's (zl, yl)

    // patch-load constants: warp handles pairs p = wid + 16*j, j<48; pair -> (rowid, ci)
    // rowid = p>>5 in 0..23 -> (pz = rowid/6, py = rowid%6); lanes cover px.
    float acc[2][7][4];
#pragma unroll
    for (int a = 0; a < 2; a++)
#pragma unroll
        for (int b = 0; b < 7; b++)
#pragma unroll
            for (int c = 0; c < 4; c++) acc[a][b][c] = 0.f;

    float4 breg0, breg1;
    const bool bpred = (tid < 384);          // 896 float4 total per B tile

#define LDG_B(s) do { \
        int cib_ = (s) / 27, tap_ = (s) % 27; \
        const float4* s4 = (const float4*)(g_wr + (size_t)(tap_ * 7 + cib_) * 7168 + co0 * 32); \
        breg0 = s4[tid]; \
        if (bpred) breg1 = s4[512 + tid]; \
    } while (0)

#define STS_B(buf) do { \
        ((float4*)B[buf])[tid] = breg0; \
        if (bpred) ((float4*)B[buf])[512 + tid] = breg1; \
    } while (0)

    // preload B(0)
    LDG_B(0);
    STS_B(0);

    for (int cib = 0; cib < 7; cib++) {
        __syncthreads();   // previous patch fully consumed
        // ---- load patch for this ci-block ----
        {
            int cig0 = cib * 32;
#pragma unroll 4
            for (int j = 0; j < 48; j++) {
                int p = wid + j * 16;
                int ci = p & 31, rowid = p >> 5;
                int pz = rowid / 6, py = rowid - pz * 6;
                int gz = z0 + pz - 1, gy = y0 + py - 1;
                bool rowok = ((unsigned)gz < 32u) && ((unsigned)gy < 32u);
                const float* src = in + (size_t)(cig0 + ci) * V + (gz << 10) + (gy << 5);
#pragma unroll
                for (int q = 0; q < 2; q++) {
                    int px = lane + q * 32;
                    if (px < 34) {
                        int gx = px - 1;
                        float v = (rowok && (unsigned)gx < 32u) ? __ldg(src + gx) : 0.f;
                        int voxel = rowid * 34 + px;
                        P[voxel * 32 + (ci ^ ((voxel & 7) << 2))] = rtf32(v);
                    }
                }
            }
        }
        __syncthreads();   // patch visible

        for (int tap = 0; tap < 27; tap++) {
            int s = cib * 27 + tap;
            int buf = s & 1;
            if (s + 1 < 189) LDG_B(s + 1);

            int dz = tap / 9, rem = tap - dz * 9;
            int dy = rem / 3, dx = rem - dy * 3;
            int vb = ((pzw + dz) * 6 + (yw + dy)) * 34 + dx;
            const float* Bb = B[buf];

#pragma unroll
            for (int ks = 0; ks < 4; ks++) {
                int k0 = ks << 3;
                uint32_t af[2][4], bf[7][2];
#pragma unroll
                for (int mt = 0; mt < 2; mt++) {
                    int v1 = vb + (mt << 4) + r4;
                    int sw = (v1 & 7) << 2;
                    int b1 = v1 << 5;
                    int ka = (k0 + c4) ^ sw, kb = (k0 + c4 + 4) ^ sw;
                    af[mt][0] = __float_as_uint(P[b1 + ka]);
                    af[mt][1] = __float_as_uint(P[b1 + 256 + ka]);
                    af[mt][2] = __float_as_uint(P[b1 + kb]);
                    af[mt][3] = __float_as_uint(P[b1 + 256 + kb]);
                }
#pragma unroll
                for (int nt = 0; nt < 7; nt++) {
                    int col = (wn * 56) + (nt << 3) + r4;
                    int swb = (col & 7) << 2;
                    bf[nt][0] = __float_as_uint(Bb[(col << 5) + ((k0 + c4) ^ swb)]);
                    bf[nt][1] = __float_as_uint(Bb[(col << 5) + ((k0 + c4 + 4) ^ swb)]);
                }
#pragma unroll
                for (int mt = 0; mt < 2; mt++)
#pragma unroll
                    for (int nt = 0; nt < 7; nt++)
                        mma_tf32(acc[mt][nt], af[mt], bf[nt]);
            }
            if (s + 1 < 189) STS_B(buf ^ 1);
            __syncthreads();
        }
    }

    // ---- epilogue ----
    int zg = z0 + pzw, yg = y0 + yw;
#pragma unroll
    for (int mt = 0; mt < 2; mt++) {
        int x1 = (mt << 4) + r4;
        int pos = (zg << 10) + (yg << 5) + x1;
#pragma unroll
        for (int nt = 0; nt < 7; nt++) {
            int c = co0 + wn * 56 + (nt << 3) + (c4 << 1);
            if (c < CC) {
                float bb = bias[c];
                out[(size_t)c * V + pos] = acc[mt][nt][0] + bb;
                out[(size_t)c * V + pos + 8] = acc[mt][nt][2] + bb;
            }
            if (c + 1 < CC) {
                float bb = bias[c + 1];
                out[(size_t)(c + 1) * V + pos] = acc[mt][nt][1] + bb;
                out[(size_t)(c + 1) * V + pos + 8] = acc[mt][nt][3] + bb;
            }
        }
    }
}

// ======================= final 3-channel conv (fp32) =======================
__global__ void __launch_bounds__(256) conv_out_kernel(const float* __restrict__ in,
                                                       const float* __restrict__ w,
                                                       const float* __restrict__ bias,
                                                       float* __restrict__ out) {
    __shared__ float sp[816];
    __shared__ float sw[81];
    int tid = threadIdx.x;
    int z0 = (blockIdx.x >> 3) * 2;
    int y0 = (blockIdx.x & 7) * 4;
    int tz = tid >> 7, ty = (tid >> 5) & 3, tx = tid & 31;

    int poff[4]; bool pval[4];
#pragma unroll
    for (int k = 0; k < 4; k++) {
        int i = k * 256 + tid;
        int pz = i / 204, r = i % 204, py = r / 34, px = r % 34;
        int gz = z0 + pz - 1, gy = y0 + py - 1, gx = px - 1;
        pval[k] = (i < 816) && ((unsigned)gz < 32u) && ((unsigned)gy < 32u) && ((unsigned)gx < 32u);
        poff[k] = (gz << 10) + (gy << 5) + gx;
    }
    float acc[3] = {0.f, 0.f, 0.f};
    for (int ci = 0; ci < CC; ci++) {
        __syncthreads();
#pragma unroll
        for (int k = 0; k < 4; k++) {
            int i = k * 256 + tid;
            if (i < 816) sp[i] = pval[k] ? in[(size_t)ci * V + poff[k]] : 0.f;
        }
        if (tid < 81) sw[tid] = w[((size_t)(tid / 27) * CC + ci) * 27 + tid % 27];
        __syncthreads();
#pragma unroll
        for (int kz = 0; kz < 3; kz++)
#pragma unroll
            for (int ky = 0; ky < 3; ky++) {
                int base = ((tz + kz) * 6 + (ty + ky)) * 34 + tx;
                float v0 = sp[base], v1 = sp[base + 1], v2 = sp[base + 2];
#pragma unroll
                for (int kx = 0; kx < 3; kx++) {
                    int wt = (kz * 3 + ky) * 3 + kx;
                    float vv = (kx == 0) ? v0 : ((kx == 1) ? v1 : v2);
                    acc[0] += sw[wt] * vv;
                    acc[1] += sw[27 + wt] * vv;
                    acc[2] += sw[54 + wt] * vv;
                }
            }
    }
    int p = ((z0 + tz) << 10) + ((y0 + ty) << 5) + tx;
#pragma unroll
    for (int co = 0; co < 3; co++) out[(size_t)co * V + p] = acc[co] + bias[co];
}

// ======================= launch =======================
extern "C" void kernel_launch(void* const* d_in, const int* in_sizes, int n_in,
                              void* d_out, int out_size) {
    (void)in_sizes; (void)n_in; (void)out_size;
    const float* src   = (const float*)d_in[0];
    const float* tgt   = (const float*)d_in[1];
    const float* C     = (const float*)d_in[2];
    const float* up_w  = (const float*)d_in[3];
    const float* up_b  = (const float*)d_in[4];
    const float* c1_w  = (const float*)d_in[5];
    const float* c1_b  = (const float*)d_in[6];
    const float* c2_w  = (const float*)d_in[7];
    const float* c2_b  = (const float*)d_in[8];
    const float* out_w = (const float*)d_in[9];
    const float* out_b = (const float*)d_in[10];
    float* dout = (float*)d_out;

    float *gx = nullptr, *gy = nullptr;
    cudaGetSymbolAddress((void**)&gx, g_x);
    cudaGetSymbolAddress((void**)&gy, g_y);

    const int CONV_SMEM = 133120;   // 26112 + 2*3584 floats
    cudaFuncSetAttribute(conv3_mma_kernel, cudaFuncAttributeMaxDynamicSharedMemorySize, CONV_SMEM);

    // Stage 1: build concat input (224 channels, pads zeroed)
    pad_zero_kernel<<<640, 256>>>();
    copy_kernel<<<2048, 256>>>(tgt, src);
    upsample_kernel<<<dim3(128, 4), 256>>>(C, up_w, up_b);
    corr_kernel<<<128, 256>>>(tgt, src);

    // IN + leaky on Cup (channels 155..218)
    stats_kernel<<<64, 256>>>(gx + (size_t)155 * V);
    norm_leaky_kernel<<<dim3(32, 64), 256>>>(gx + (size_t)155 * V);

    // conv1 (tf32 HMMA, patch-staged) + IN + leaky
    reorder_w_kernel<<<5292, 256>>>(c1_w);
    conv3_mma_kernel<<<dim3(128, 2), 512, CONV_SMEM>>>(gx, c1_b, gy);
    stats_kernel<<<CC, 256>>>(gy);
    norm_leaky_kernel<<<dim3(32, CC), 256>>>(gy);

    // conv2 (tf32 HMMA, patch-staged) + IN + leaky  -> Cn in d_out[0 .. 219*V)
    reorder_w_kernel<<<5292, 256>>>(c2_w);
    conv3_mma_kernel<<<dim3(128, 2), 512, CONV_SMEM>>>(gy, c2_b, dout);
    stats_kernel<<<CC, 256>>>(dout);
    norm_leaky_kernel<<<dim3(32, CC), 256>>>(dout);

    // output conv -> d_out[219*V .. 222*V)
    conv_out_kernel<<<128, 256>>>(dout, out_w, out_b, dout + (size_t)CC * V);
}

// round 6
// speedup vs baseline: 2.0985x; 1.2506x over previous
#include <cuda_runtime.h>
#include <cuda_fp16.h>
#include <cstdint>

#define V 32768            // 32*32*32
#define CC 219             // real channels
#define CP 224             // padded channels (multiple of 32)

__device__ float g_x[CP * V];              // concat input [tgt(64), src(64), cost(27), Cup(64), pad(5)=0]
__device__ float g_y[CP * V];              // conv1 output (padded)
__device__ uint32_t g_wh[27 * 7 * 3584];   // half2-packed pre-swizzled B: [(tap*7+cib)][co*16 + (j ^ ((co&7)<<1))]
__device__ float g_stats[CC * 2];          // per-channel (mean, rstd)

__device__ __forceinline__ void mma_f16(float d[4], const uint32_t a[4], const uint32_t b[2]) {
    asm volatile(
        "mma.sync.aligned.m16n8k16.row.col.f32.f16.f16.f32 "
        "{%0,%1,%2,%3}, {%4,%5,%6,%7}, {%8,%9}, {%0,%1,%2,%3};"
        : "+f"(d[0]), "+f"(d[1]), "+f"(d[2]), "+f"(d[3])
        : "r"(a[0]), "r"(a[1]), "r"(a[2]), "r"(a[3]), "r"(b[0]), "r"(b[1]));
}

// ======================= small kernels =======================
__global__ void pad_zero_kernel() {
    int i = blockIdx.x * 256 + threadIdx.x;      // over 5*V
    g_x[(size_t)CC * V + i] = 0.f;
    g_y[(size_t)CC * V + i] = 0.f;
}

__global__ void copy_kernel(const float* __restrict__ tgt, const float* __restrict__ src) {
    int i = blockIdx.x * 256 + threadIdx.x;   // over 64*V/4 float4
    float4* dx = (float4*)g_x;
    dx[i] = ((const float4*)tgt)[i];
    dx[(64 * V) / 4 + i] = ((const float4*)src)[i];
}

// weight reorder: half2 pack + pre-swizzle. word (co, jj) at blob (tap,cib) holds ci pair (2j, 2j+1), j = jj ^ ((co&7)<<1)
__global__ void reorder_w_kernel(const float* __restrict__ w) {
    int id = blockIdx.x * 256 + threadIdx.x;     // < 27*7*3584 = 677376
    if (id >= 27 * 7 * 3584) return;
    int blob = id / 3584, r = id % 3584;
    int tap = blob / 7, cib = blob % 7;
    int co = r >> 4, jj = r & 15;
    int j = jj ^ ((co & 7) << 1);
    int ci0 = cib * 32 + 2 * j;
    float v0 = 0.f, v1 = 0.f;
    if (co < CC) {
        if (ci0 < CC)     v0 = w[((size_t)co * CC + ci0) * 27 + tap];
        if (ci0 + 1 < CC) v1 = w[((size_t)co * CC + ci0 + 1) * 27 + tap];
    }
    half2 h = __floats2half2_rn(v0, v1);
    g_wh[id] = *(uint32_t*)&h;
}

// ======================= correlation volume =======================
__global__ void __launch_bounds__(256) corr_kernel(const float* __restrict__ tgt,
                                                   const float* __restrict__ src) {
    __shared__ float sp[4 * 6 * 34];
    int tid = threadIdx.x;
    int z0 = (blockIdx.x >> 3) * 2;
    int y0 = (blockIdx.x & 7) * 4;
    int tz = tid >> 7, ty = (tid >> 5) & 3, tx = tid & 31;
    int z = z0 + tz, y = y0 + ty;
    int p = (z << 10) + (y << 5) + tx;

    int poff[4]; bool pval[4];
#pragma unroll
    for (int k = 0; k < 4; k++) {
        int i = k * 256 + tid;
        int pz = i / 204, r = i % 204, py = r / 34, px = r % 34;
        int gz = z0 + pz - 1, gy = y0 + py - 1, gx = px - 1;
        pval[k] = (i < 816) && ((unsigned)gz < 32u) && ((unsigned)gy < 32u) && ((unsigned)gx < 32u);
        poff[k] = (gz << 10) + (gy << 5) + gx;
    }
    float acc[27];
#pragma unroll
    for (int d = 0; d < 27; d++) acc[d] = 0.f;
    for (int c = 0; c < 64; c++) {
        __syncthreads();
#pragma unroll
        for (int k = 0; k < 4; k++) {
            int i = k * 256 + tid;
            if (i < 816) sp[i] = pval[k] ? src[c * V + poff[k]] : 0.f;
        }
        __syncthreads();
        float t = tgt[c * V + p];
#pragma unroll
        for (int dz = 0; dz < 3; dz++)
#pragma unroll
            for (int dy = 0; dy < 3; dy++) {
                int base = ((tz + dz) * 6 + (ty + dy)) * 34 + tx;
                acc[dz * 9 + dy * 3 + 0] += t * sp[base];
                acc[dz * 9 + dy * 3 + 1] += t * sp[base + 1];
                acc[dz * 9 + dy * 3 + 2] += t * sp[base + 2];
            }
    }
    const float inv = 1.f / 64.f;
#pragma unroll
    for (int d = 0; d < 27; d++) g_x[(size_t)(128 + d) * V + p] = acc[d] * inv;
}

// ======================= conv transpose upsample =======================
__global__ void __launch_bounds__(256) upsample_kernel(const float* __restrict__ Cin,
                                                       const float* __restrict__ w,
                                                       const float* __restrict__ bias) {
    __shared__ float swt[16 * 64];
    __shared__ float spatch[3 * 4 * 18];
    int tid = threadIdx.x;
    int z0 = (blockIdx.x >> 3) * 2;
    int y0 = (blockIdx.x & 7) * 4;
    int co0 = blockIdx.y * 16;
    int tz = tid >> 7, ty = (tid >> 5) & 3, tx = tid & 31;
    int oz = z0 + tz, oy = y0 + ty, ox = tx;
    int izb = (z0 >> 1) - 1, iyb = (y0 >> 1) - 1;

    int taps[8]; int nt = 0;
    for (int kz = (oz + 1) & 1; kz < 4; kz += 2) {
        int iz = (oz + 1 - kz) >> 1; if (iz < 0 || iz >= 16) continue;
        for (int ky = (oy + 1) & 1; ky < 4; ky += 2) {
            int iy = (oy + 1 - ky) >> 1; if (iy < 0 || iy >= 16) continue;
            for (int kx = (ox + 1) & 1; kx < 4; kx += 2) {
                int ix = (ox + 1 - kx) >> 1; if (ix < 0 || ix >= 16) continue;
                int pofs = ((iz - izb) * 4 + (iy - iyb)) * 18 + (ix + 1);
                int wofs = (kz << 4) + (ky << 2) + kx;
                taps[nt++] = pofs | (wofs << 16);
            }
        }
    }
    int pl_off = 0; bool pl_val = false;
    if (tid < 216) {
        int pz = tid / 72, r = tid % 72, py = r / 18, px = r % 18;
        int gz = izb + pz, gy = iyb + py, gx = px - 1;
        pl_val = ((unsigned)gz < 16u) && ((unsigned)gy < 16u) && ((unsigned)gx < 16u);
        pl_off = (gz << 8) + (gy << 4) + gx;
    }
    float acc[16];
#pragma unroll
    for (int j = 0; j < 16; j++) acc[j] = 0.f;
    for (int ci = 0; ci < 411; ci++) {
        __syncthreads();
        if (tid < 216) spatch[tid] = pl_val ? Cin[ci * 4096 + pl_off] : 0.f;
        const float* wc = w + ((size_t)ci * 64 + co0) * 64;
#pragma unroll
        for (int k = 0; k < 4; k++) swt[k * 256 + tid] = wc[k * 256 + tid];
        __syncthreads();
        for (int t = 0; t < nt; t++) {
            int tp = taps[t];
            float v = spatch[tp & 0xffff];
            int wofs = tp >> 16;
#pragma unroll
            for (int j = 0; j < 16; j++) acc[j] += v * swt[(j << 6) + wofs];
        }
    }
    int p = (oz << 10) + (oy << 5) + ox;
#pragma unroll
    for (int j = 0; j < 16; j++)
        g_x[(size_t)(155 + co0 + j) * V + p] = acc[j] + bias[co0 + j];
}

// ======================= instance norm =======================
__global__ void stats_kernel(const float* __restrict__ x) {
    int ch = blockIdx.x;
    const float4* p4 = (const float4*)(x + (size_t)ch * V);
    float s = 0.f, s2 = 0.f;
    for (int i = threadIdx.x; i < V / 4; i += 256) {
        float4 v = p4[i];
        s += v.x + v.y + v.z + v.w;
        s2 += v.x * v.x + v.y * v.y + v.z * v.z + v.w * v.w;
    }
#pragma unroll
    for (int o = 16; o; o >>= 1) {
        s += __shfl_down_sync(0xffffffffu, s, o);
        s2 += __shfl_down_sync(0xffffffffu, s2, o);
    }
    __shared__ float a[8], b[8];
    int wp = threadIdx.x >> 5, ln = threadIdx.x & 31;
    if (ln == 0) { a[wp] = s; b[wp] = s2; }
    __syncthreads();
    if (threadIdx.x < 8) {
        s = a[threadIdx.x]; s2 = b[threadIdx.x];
#pragma unroll
        for (int o = 4; o; o >>= 1) {
            s += __shfl_down_sync(0xffu, s, o);
            s2 += __shfl_down_sync(0xffu, s2, o);
        }
        if (threadIdx.x == 0) {
            float m = s * (1.f / V);
            float var = s2 * (1.f / V) - m * m;
            g_stats[ch * 2] = m;
            g_stats[ch * 2 + 1] = rsqrtf(var + 1e-5f);
        }
    }
}

__global__ void norm_leaky_kernel(float* __restrict__ x) {
    int ch = blockIdx.y;
    int i = blockIdx.x * 256 + threadIdx.x;
    float m = g_stats[ch * 2], r = g_stats[ch * 2 + 1];
    float4* p = (float4*)(x + (size_t)ch * V);
    float4 v = p[i];
    v.x = (v.x - m) * r; v.x = v.x >= 0.f ? v.x : 0.1f * v.x;
    v.y = (v.y - m) * r; v.y = v.y >= 0.f ? v.y : 0.1f * v.y;
    v.z = (v.z - m) * r; v.z = v.z >= 0.f ? v.z : 0.1f * v.z;
    v.w = (v.w - m) * r; v.w = v.w >= 0.f ? v.w : 0.1f * v.w;
    p[i] = v;
}

// ======================= fp16 HMMA conv3x3x3 with persistent SMEM patch =======================
// CTA: M=256 (2z x 4y x 32x) x N=112 co (co-split 2). 512 threads = 16 warps (8 wm x 2 wn),
// warp tile 32M x 56N. Patch (4x6x34 voxels x 32 ci, half2-packed words) staged once per ci-block;
// 27 taps read fragments directly. B (112 co x 16 half2 words) double-buffered from g_wh.
// Dyn SMEM words: patch 816*16 = 13056, B 2*1792 -> total (13056+3584)*4 = 66560 B.
__global__ void __launch_bounds__(512) conv3_mma_kernel(const float* __restrict__ in,
                                                        const float* __restrict__ bias,
                                                        float* __restrict__ out) {
    extern __shared__ uint32_t smem32[];
    uint32_t* P = smem32;                   // patch words, swizzled
    uint32_t* B[2] = { smem32 + 13056, smem32 + 13056 + 1792 };

    int tid = threadIdx.x, wid = tid >> 5, lane = tid & 31;
    int zt = blockIdx.x >> 3, yt = blockIdx.x & 7;
    int z0 = zt * 2, y0 = yt * 4;
    int co0 = blockIdx.y * 112;

    int wm = wid >> 1, wn = wid & 1;
    int r4 = lane >> 2, c4 = lane & 3;
    int pzw = wm >> 2, yw = wm & 3;          // warp's (zl, yl)

    float acc[2][7][4];
#pragma unroll
    for (int a = 0; a < 2; a++)
#pragma unroll
        for (int b = 0; b < 7; b++)
#pragma unroll
            for (int c = 0; c < 4; c++) acc[a][b][c] = 0.f;

    uint4 breg;
    const bool bpred = (tid < 448);          // 1792 words = 448 uint4 per B tile

#define LDG_B(s) do { \
        int cib_ = (s) / 27, tap_ = (s) % 27; \
        const uint4* s4 = (const uint4*)(g_wh + (size_t)(tap_ * 7 + cib_) * 3584 + co0 * 16); \
        if (bpred) breg = s4[tid]; \
    } while (0)

#define STS_B(buf) do { \
        if (bpred) ((uint4*)B[buf])[tid] = breg; \
    } while (0)

    LDG_B(0);
    STS_B(0);

    for (int cib = 0; cib < 7; cib++) {
        __syncthreads();   // previous patch fully consumed
        // ---- stage patch for this ci-block (half2-packed, word-swizzled) ----
        {
            int cig0 = cib * 32;
#pragma unroll 4
            for (int jj = 0; jj < 24; jj++) {
                int p = wid + jj * 16;       // 0..383
                int wword = p & 15;          // ci-pair word
                int rowid = p >> 4;          // 0..23 (4z x 6y)
                int pz = rowid / 6, py = rowid - pz * 6;
                int gz = z0 + pz - 1, gy = y0 + py - 1;
                bool rowok = ((unsigned)gz < 32u) && ((unsigned)gy < 32u);
                const float* s0 = in + (size_t)(cig0 + 2 * wword) * V + (gz << 10) + (gy << 5);
#pragma unroll
                for (int q = 0; q < 2; q++) {
                    int px = lane + q * 32;
                    if (px < 34) {
                        int gx = px - 1;
                        bool ok = rowok && ((unsigned)gx < 32u);
                        float v0 = ok ? __ldg(s0 + gx) : 0.f;
                        float v1 = ok ? __ldg(s0 + V + gx) : 0.f;
                        half2 h = __floats2half2_rn(v0, v1);
                        int voxel = rowid * 34 + px;
                        P[voxel * 16 + (wword ^ ((voxel & 7) << 1))] = *(uint32_t*)&h;
                    }
                }
            }
        }
        __syncthreads();   // patch visible

        for (int tap = 0; tap < 27; tap++) {
            int s = cib * 27 + tap;
            int buf = s & 1;
            if (s + 1 < 189) LDG_B(s + 1);

            int dz = tap / 9, rem = tap - dz * 9;
            int dy = rem / 3, dx = rem - dy * 3;
            int vb = ((pzw + dz) * 6 + (yw + dy)) * 34 + dx;
            const uint32_t* Bb = B[buf];

#pragma unroll
            for (int ks = 0; ks < 2; ks++) {
                int k0 = ks << 3;            // word base (8 words = 16 k)
                uint32_t af[2][4], bf[7][2];
#pragma unroll
                for (int mt = 0; mt < 2; mt++) {
                    int v1 = vb + (mt << 4) + r4;
                    int v2 = v1 + 8;
                    int w1 = (k0 + c4) ^ ((v1 & 7) << 1);
                    int w1b = (k0 + c4 + 4) ^ ((v1 & 7) << 1);
                    int w2 = (k0 + c4) ^ ((v2 & 7) << 1);
                    int w2b = (k0 + c4 + 4) ^ ((v2 & 7) << 1);
                    af[mt][0] = P[(v1 << 4) + w1];
                    af[mt][1] = P[(v2 << 4) + w2];
                    af[mt][2] = P[(v1 << 4) + w1b];
                    af[mt][3] = P[(v2 << 4) + w2b];
                }
#pragma unroll
                for (int nt = 0; nt < 7; nt++) {
                    int col = (wn * 56) + (nt << 3) + r4;
                    int swb = (col & 7) << 1;
                    bf[nt][0] = Bb[(col << 4) + ((k0 + c4) ^ swb)];
                    bf[nt][1] = Bb[(col << 4) + ((k0 + c4 + 4) ^ swb)];
                }
#pragma unroll
                for (int mt = 0; mt < 2; mt++)
#pragma unroll
                    for (int nt = 0; nt < 7; nt++)
                        mma_f16(acc[mt][nt], af[mt], bf[nt]);
            }
            if (s + 1 < 189) STS_B(buf ^ 1);
            __syncthreads();
        }
    }

    // ---- epilogue ----
    int zg = z0 + pzw, yg = y0 + yw;
#pragma unroll
    for (int mt = 0; mt < 2; mt++) {
        int x1 = (mt << 4) + r4;
        int pos = (zg << 10) + (yg << 5) + x1;
#pragma unroll
        for (int nt = 0; nt < 7; nt++) {
            int c = co0 + wn * 56 + (nt << 3) + (c4 << 1);
            if (c < CC) {
                float bb = bias[c];
                out[(size_t)c * V + pos] = acc[mt][nt][0] + bb;
                out[(size_t)c * V + pos + 8] = acc[mt][nt][2] + bb;
            }
            if (c + 1 < CC) {
                float bb = bias[c + 1];
                out[(size_t)(c + 1) * V + pos] = acc[mt][nt][1] + bb;
                out[(size_t)(c + 1) * V + pos + 8] = acc[mt][nt][3] + bb;
            }
        }
    }
}

// ======================= final 3-channel conv (fp32) =======================
__global__ void __launch_bounds__(256) conv_out_kernel(const float* __restrict__ in,
                                                       const float* __restrict__ w,
                                                       const float* __restrict__ bias,
                                                       float* __restrict__ out) {
    __shared__ float sp[816];
    __shared__ float sw[81];
    int tid = threadIdx.x;
    int z0 = (blockIdx.x >> 3) * 2;
    int y0 = (blockIdx.x & 7) * 4;
    int tz = tid >> 7, ty = (tid >> 5) & 3, tx = tid & 31;

    int poff[4]; bool pval[4];
#pragma unroll
    for (int k = 0; k < 4; k++) {
        int i = k * 256 + tid;
        int pz = i / 204, r = i % 204, py = r / 34, px = r % 34;
        int gz = z0 + pz - 1, gy = y0 + py - 1, gx = px - 1;
        pval[k] = (i < 816) && ((unsigned)gz < 32u) && ((unsigned)gy < 32u) && ((unsigned)gx < 32u);
        poff[k] = (gz << 10) + (gy << 5) + gx;
    }
    float acc[3] = {0.f, 0.f, 0.f};
    for (int ci = 0; ci < CC; ci++) {
        __syncthreads();
#pragma unroll
        for (int k = 0; k < 4; k++) {
            int i = k * 256 + tid;
            if (i < 816) sp[i] = pval[k] ? in[(size_t)ci * V + poff[k]] : 0.f;
        }
        if (tid < 81) sw[tid] = w[((size_t)(tid / 27) * CC + ci) * 27 + tid % 27];
        __syncthreads();
#pragma unroll
        for (int kz = 0; kz < 3; kz++)
#pragma unroll
            for (int ky = 0; ky < 3; ky++) {
                int base = ((tz + kz) * 6 + (ty + ky)) * 34 + tx;
                float v0 = sp[base], v1 = sp[base + 1], v2 = sp[base + 2];
#pragma unroll
                for (int kx = 0; kx < 3; kx++) {
                    int wt = (kz * 3 + ky) * 3 + kx;
                    float vv = (kx == 0) ? v0 : ((kx == 1) ? v1 : v2);
                    acc[0] += sw[wt] * vv;
                    acc[1] += sw[27 + wt] * vv;
                    acc[2] += sw[54 + wt] * vv;
                }
            }
    }
    int p = ((z0 + tz) << 10) + ((y0 + ty) << 5) + tx;
#pragma unroll
    for (int co = 0; co < 3; co++) out[(size_t)co * V + p] = acc[co] + bias[co];
}

// ======================= launch =======================
extern "C" void kernel_launch(void* const* d_in, const int* in_sizes, int n_in,
                              void* d_out, int out_size) {
    (void)in_sizes; (void)n_in; (void)out_size;
    const float* src   = (const float*)d_in[0];
    const float* tgt   = (const float*)d_in[1];
    const float* C     = (const float*)d_in[2];
    const float* up_w  = (const float*)d_in[3];
    const float* up_b  = (const float*)d_in[4];
    const float* c1_w  = (const float*)d_in[5];
    const float* c1_b  = (const float*)d_in[6];
    const float* c2_w  = (const float*)d_in[7];
    const float* c2_b  = (const float*)d_in[8];
    const float* out_w = (const float*)d_in[9];
    const float* out_b = (const float*)d_in[10];
    float* dout = (float*)d_out;

    float *gx = nullptr, *gy = nullptr;
    cudaGetSymbolAddress((void**)&gx, g_x);
    cudaGetSymbolAddress((void**)&gy, g_y);

    const int CONV_SMEM = 66560;   // (13056 + 2*1792) uint32 words
    cudaFuncSetAttribute(conv3_mma_kernel, cudaFuncAttributeMaxDynamicSharedMemorySize, CONV_SMEM);

    // Stage 1: build concat input (224 channels, pads zeroed)
    pad_zero_kernel<<<640, 256>>>();
    copy_kernel<<<2048, 256>>>(tgt, src);
    upsample_kernel<<<dim3(128, 4), 256>>>(C, up_w, up_b);
    corr_kernel<<<128, 256>>>(tgt, src);

    // IN + leaky on Cup (channels 155..218)
    stats_kernel<<<64, 256>>>(gx + (size_t)155 * V);
    norm_leaky_kernel<<<dim3(32, 64), 256>>>(gx + (size_t)155 * V);

    // conv1 (fp16 HMMA, patch-staged) + IN + leaky
    reorder_w_kernel<<<2646, 256>>>(c1_w);
    conv3_mma_kernel<<<dim3(128, 2), 512, CONV_SMEM>>>(gx, c1_b, gy);
    stats_kernel<<<CC, 256>>>(gy);
    norm_leaky_kernel<<<dim3(32, CC), 256>>>(gy);

    // conv2 (fp16 HMMA, patch-staged) + IN + leaky  -> Cn in d_out[0 .. 219*V)
    reorder_w_kernel<<<2646, 256>>>(c2_w);
    conv3_mma_kernel<<<dim3(128, 2), 512, CONV_SMEM>>>(gy, c2_b, dout);
    stats_kernel<<<CC, 256>>>(dout);
    norm_leaky_kernel<<<dim3(32, CC), 256>>>(dout);

    // output conv -> d_out[219*V .. 222*V)
    conv_out_kernel<<<128, 256>>>(dout, out_w, out_b, dout + (size_t)CC * V);
}

// round 7
// speedup vs baseline: 2.2334x; 1.0643x over previous
#include <cuda_runtime.h>
#include <cuda_fp16.h>
#include <cstdint>

#define V 32768            // 32*32*32
#define CC 219             // real channels
#define CP 224             // padded channels (multiple of 32)

__device__ float g_x[CP * V];              // concat input [tgt(64), src(64), cost(27), Cup(64), pad(5)=0]
__device__ float g_y[CP * V];              // conv1 output (padded)
__device__ uint32_t g_wh[27 * 7 * 3584];   // half2-packed pre-swizzled B (16B-granular swizzle)
__device__ float g_stats[CC * 2];          // per-channel (mean, rstd)

__device__ __forceinline__ uint32_t smem_u32(const void* p) {
    uint32_t a;
    asm("{ .reg .u64 t; cvta.to.shared.u64 t, %1; cvt.u32.u64 %0, t; }" : "=r"(a) : "l"(p));
    return a;
}

__device__ __forceinline__ void mma_f16(float d[4], const uint32_t a[4], const uint32_t b[2]) {
    asm volatile(
        "mma.sync.aligned.m16n8k16.row.col.f32.f16.f16.f32 "
        "{%0,%1,%2,%3}, {%4,%5,%6,%7}, {%8,%9}, {%0,%1,%2,%3};"
        : "+f"(d[0]), "+f"(d[1]), "+f"(d[2]), "+f"(d[3])
        : "r"(a[0]), "r"(a[1]), "r"(a[2]), "r"(a[3]), "r"(b[0]), "r"(b[1]));
}
__device__ __forceinline__ void ldsm_x4(uint32_t r[4], uint32_t addr) {
    asm volatile("ldmatrix.sync.aligned.m8n8.x4.shared.b16 {%0,%1,%2,%3}, [%4];"
                 : "=r"(r[0]), "=r"(r[1]), "=r"(r[2]), "=r"(r[3]) : "r"(addr));
}
__device__ __forceinline__ void ldsm_x2(uint32_t r[2], uint32_t addr) {
    asm volatile("ldmatrix.sync.aligned.m8n8.x2.shared.b16 {%0,%1}, [%2];"
                 : "=r"(r[0]), "=r"(r[1]) : "r"(addr));
}

// ======================= small kernels =======================
__global__ void pad_zero_kernel() {
    int i = blockIdx.x * 256 + threadIdx.x;      // over 5*V
    g_x[(size_t)CC * V + i] = 0.f;
    g_y[(size_t)CC * V + i] = 0.f;
}

__global__ void copy_kernel(const float* __restrict__ tgt, const float* __restrict__ src) {
    int i = blockIdx.x * 256 + threadIdx.x;   // over 64*V/4 float4
    float4* dx = (float4*)g_x;
    dx[i] = ((const float4*)tgt)[i];
    dx[(64 * V) / 4 + i] = ((const float4*)src)[i];
}

// weight reorder: half2 pack + 16B-granular swizzle.
// storage jj for co: logical word w = ((jj>>2) ^ ((co>>1)&3))<<2 | (jj&3); holds ci pair (2w, 2w+1)
__global__ void reorder_w_kernel(const float* __restrict__ w) {
    int id = blockIdx.x * 256 + threadIdx.x;     // < 27*7*3584 = 677376
    if (id >= 27 * 7 * 3584) return;
    int blob = id / 3584, r = id % 3584;
    int tap = blob / 7, cib = blob % 7;
    int co = r >> 4, jj = r & 15;
    int wlog = (((jj >> 2) ^ ((co >> 1) & 3)) << 2) | (jj & 3);
    int ci0 = cib * 32 + 2 * wlog;
    float v0 = 0.f, v1 = 0.f;
    if (co < CC) {
        if (ci0 < CC)     v0 = w[((size_t)co * CC + ci0) * 27 + tap];
        if (ci0 + 1 < CC) v1 = w[((size_t)co * CC + ci0 + 1) * 27 + tap];
    }
    half2 h = __floats2half2_rn(v0, v1);
    g_wh[id] = *(uint32_t*)&h;
}

// ======================= correlation volume =======================
__global__ void __launch_bounds__(256) corr_kernel(const float* __restrict__ tgt,
                                                   const float* __restrict__ src) {
    __shared__ float sp[4 * 6 * 34];
    int tid = threadIdx.x;
    int z0 = (blockIdx.x >> 3) * 2;
    int y0 = (blockIdx.x & 7) * 4;
    int tz = tid >> 7, ty = (tid >> 5) & 3, tx = tid & 31;
    int z = z0 + tz, y = y0 + ty;
    int p = (z << 10) + (y << 5) + tx;

    int poff[4]; bool pval[4];
#pragma unroll
    for (int k = 0; k < 4; k++) {
        int i = k * 256 + tid;
        int pz = i / 204, r = i % 204, py = r / 34, px = r % 34;
        int gz = z0 + pz - 1, gy = y0 + py - 1, gx = px - 1;
        pval[k] = (i < 816) && ((unsigned)gz < 32u) && ((unsigned)gy < 32u) && ((unsigned)gx < 32u);
        poff[k] = (gz << 10) + (gy << 5) + gx;
    }
    float acc[27];
#pragma unroll
    for (int d = 0; d < 27; d++) acc[d] = 0.f;
    for (int c = 0; c < 64; c++) {
        __syncthreads();
#pragma unroll
        for (int k = 0; k < 4; k++) {
            int i = k * 256 + tid;
            if (i < 816) sp[i] = pval[k] ? src[c * V + poff[k]] : 0.f;
        }
        __syncthreads();
        float t = tgt[c * V + p];
#pragma unroll
        for (int dz = 0; dz < 3; dz++)
#pragma unroll
            for (int dy = 0; dy < 3; dy++) {
                int base = ((tz + dz) * 6 + (ty + dy)) * 34 + tx;
                acc[dz * 9 + dy * 3 + 0] += t * sp[base];
                acc[dz * 9 + dy * 3 + 1] += t * sp[base + 1];
                acc[dz * 9 + dy * 3 + 2] += t * sp[base + 2];
            }
    }
    const float inv = 1.f / 64.f;
#pragma unroll
    for (int d = 0; d < 27; d++) g_x[(size_t)(128 + d) * V + p] = acc[d] * inv;
}

// ======================= conv transpose upsample =======================
__global__ void __launch_bounds__(256) upsample_kernel(const float* __restrict__ Cin,
                                                       const float* __restrict__ w,
                                                       const float* __restrict__ bias) {
    __shared__ float swt[16 * 64];
    __shared__ float spatch[3 * 4 * 18];
    int tid = threadIdx.x;
    int z0 = (blockIdx.x >> 3) * 2;
    int y0 = (blockIdx.x & 7) * 4;
    int co0 = blockIdx.y * 16;
    int tz = tid >> 7, ty = (tid >> 5) & 3, tx = tid & 31;
    int oz = z0 + tz, oy = y0 + ty, ox = tx;
    int izb = (z0 >> 1) - 1, iyb = (y0 >> 1) - 1;

    int taps[8]; int nt = 0;
    for (int kz = (oz + 1) & 1; kz < 4; kz += 2) {
        int iz = (oz + 1 - kz) >> 1; if (iz < 0 || iz >= 16) continue;
        for (int ky = (oy + 1) & 1; ky < 4; ky += 2) {
            int iy = (oy + 1 - ky) >> 1; if (iy < 0 || iy >= 16) continue;
            for (int kx = (ox + 1) & 1; kx < 4; kx += 2) {
                int ix = (ox + 1 - kx) >> 1; if (ix < 0 || ix >= 16) continue;
                int pofs = ((iz - izb) * 4 + (iy - iyb)) * 18 + (ix + 1);
                int wofs = (kz << 4) + (ky << 2) + kx;
                taps[nt++] = pofs | (wofs << 16);
            }
        }
    }
    int pl_off = 0; bool pl_val = false;
    if (tid < 216) {
        int pz = tid / 72, r = tid % 72, py = r / 18, px = r % 18;
        int gz = izb + pz, gy = iyb + py, gx = px - 1;
        pl_val = ((unsigned)gz < 16u) && ((unsigned)gy < 16u) && ((unsigned)gx < 16u);
        pl_off = (gz << 8) + (gy << 4) + gx;
    }
    float acc[16];
#pragma unroll
    for (int j = 0; j < 16; j++) acc[j] = 0.f;
    for (int ci = 0; ci < 411; ci++) {
        __syncthreads();
        if (tid < 216) spatch[tid] = pl_val ? Cin[ci * 4096 + pl_off] : 0.f;
        const float* wc = w + ((size_t)ci * 64 + co0) * 64;
#pragma unroll
        for (int k = 0; k < 4; k++) swt[k * 256 + tid] = wc[k * 256 + tid];
        __syncthreads();
        for (int t = 0; t < nt; t++) {
            int tp = taps[t];
            float v = spatch[tp & 0xffff];
            int wofs = tp >> 16;
#pragma unroll
            for (int j = 0; j < 16; j++) acc[j] += v * swt[(j << 6) + wofs];
        }
    }
    int p = (oz << 10) + (oy << 5) + ox;
#pragma unroll
    for (int j = 0; j < 16; j++)
        g_x[(size_t)(155 + co0 + j) * V + p] = acc[j] + bias[co0 + j];
}

// ======================= instance norm =======================
__global__ void stats_kernel(const float* __restrict__ x) {
    int ch = blockIdx.x;
    const float4* p4 = (const float4*)(x + (size_t)ch * V);
    float s = 0.f, s2 = 0.f;
    for (int i = threadIdx.x; i < V / 4; i += 256) {
        float4 v = p4[i];
        s += v.x + v.y + v.z + v.w;
        s2 += v.x * v.x + v.y * v.y + v.z * v.z + v.w * v.w;
    }
#pragma unroll
    for (int o = 16; o; o >>= 1) {
        s += __shfl_down_sync(0xffffffffu, s, o);
        s2 += __shfl_down_sync(0xffffffffu, s2, o);
    }
    __shared__ float a[8], b[8];
    int wp = threadIdx.x >> 5, ln = threadIdx.x & 31;
    if (ln == 0) { a[wp] = s; b[wp] = s2; }
    __syncthreads();
    if (threadIdx.x < 8) {
        s = a[threadIdx.x]; s2 = b[threadIdx.x];
#pragma unroll
        for (int o = 4; o; o >>= 1) {
            s += __shfl_down_sync(0xffu, s, o);
            s2 += __shfl_down_sync(0xffu, s2, o);
        }
        if (threadIdx.x == 0) {
            float m = s * (1.f / V);
            float var = s2 * (1.f / V) - m * m;
            g_stats[ch * 2] = m;
            g_stats[ch * 2 + 1] = rsqrtf(var + 1e-5f);
        }
    }
}

__global__ void norm_leaky_kernel(float* __restrict__ x) {
    int ch = blockIdx.y;
    int i = blockIdx.x * 256 + threadIdx.x;
    float m = g_stats[ch * 2], r = g_stats[ch * 2 + 1];
    float4* p = (float4*)(x + (size_t)ch * V);
    float4 v = p[i];
    v.x = (v.x - m) * r; v.x = v.x >= 0.f ? v.x : 0.1f * v.x;
    v.y = (v.y - m) * r; v.y = v.y >= 0.f ? v.y : 0.1f * v.y;
    v.z = (v.z - m) * r; v.z = v.z >= 0.f ? v.z : 0.1f * v.z;
    v.w = (v.w - m) * r; v.w = v.w >= 0.f ? v.w : 0.1f * v.w;
    p[i] = v;
}

// ======================= fp16 HMMA conv3x3x3, ldmatrix fragment feed =======================
// CTA: M=256 (2z x 4y x 32x) x N=112 co. 512 threads = 16 warps (8 wm x 2 wn), warp tile 32x56.
// Patch: 816 voxel-rows x 16 half2 words, 16B-seg swizzle seg' = seg ^ ((row>>1)&3).
// B: 112 co-rows x 16 words, same swizzle (pre-applied in g_wh). Double-buffered.
__global__ void __launch_bounds__(512) conv3_mma_kernel(const float* __restrict__ in,
                                                        const float* __restrict__ bias,
                                                        float* __restrict__ out) {
    extern __shared__ uint32_t smem32[];
    uint32_t* P = smem32;                   // 13056 words
    uint32_t sbase = smem_u32(smem32);
    const uint32_t BBASE = 13056u * 4u;     // byte offset of B buffers
    uint32_t* Bw[2] = { smem32 + 13056, smem32 + 13056 + 1792 };

    int tid = threadIdx.x, wid = tid >> 5, lane = tid & 31;
    int zt = blockIdx.x >> 3, yt = blockIdx.x & 7;
    int z0 = zt * 2, y0 = yt * 4;
    int co0 = blockIdx.y * 112;

    int wm = wid >> 1, wn = wid & 1;
    int r4 = lane >> 2, c4 = lane & 3;
    int pzw = wm >> 2, yw = wm & 3;          // warp's (zl, yl)

    // ldmatrix lane constants
    int sub = lane >> 3, l7 = lane & 7;
    int a_lro = ((sub & 1) << 3) + l7;       // A row offset within 16-row block
    int a_sh = sub >> 1;                     // A k-seg half
    int b_segbit = sub & 1;                  // B k-seg half
    int b_ntoff = sub >> 1;                  // B nt offset within pair
    // B per-lane byte offsets (buffer-relative) and swizzle masks
    uint32_t bco[4]; int bsw[4];
#pragma unroll
    for (int t = 0; t < 3; t++) {
        int co = wn * 56 + (2 * t + b_ntoff) * 8 + l7;
        bco[t] = (uint32_t)(co << 6);
        bsw[t] = (co >> 1) & 3;
    }
    {
        int co = wn * 56 + 48 + l7;          // x2 tail (nt=6)
        bco[3] = (uint32_t)(co << 6);
        bsw[3] = (co >> 1) & 3;
    }

    float acc[2][7][4];
#pragma unroll
    for (int a = 0; a < 2; a++)
#pragma unroll
        for (int b = 0; b < 7; b++)
#pragma unroll
            for (int c = 0; c < 4; c++) acc[a][b][c] = 0.f;

    uint4 breg;
    const bool bpred = (tid < 448);          // 1792 words = 448 uint4 per B tile

#define LDG_B(s) do { \
        int cib_ = (s) / 27, tap_ = (s) % 27; \
        const uint4* s4 = (const uint4*)(g_wh + (size_t)(tap_ * 7 + cib_) * 3584 + co0 * 16); \
        if (bpred) breg = s4[tid]; \
    } while (0)

#define STS_B(buf) do { \
        if (bpred) ((uint4*)Bw[buf])[tid] = breg; \
    } while (0)

    LDG_B(0);
    STS_B(0);

    for (int cib = 0; cib < 7; cib++) {
        __syncthreads();   // previous patch fully consumed
        // ---- stage patch (half2-packed, 16B-seg swizzle) ----
        {
            int cig0 = cib * 32;
#pragma unroll 4
            for (int jj = 0; jj < 24; jj++) {
                int p = wid + jj * 16;       // 0..383
                int wword = p & 15;          // logical ci-pair word
                int rowid = p >> 4;          // 0..23 (4z x 6y)
                int pz = rowid / 6, py = rowid - pz * 6;
                int gz = z0 + pz - 1, gy = y0 + py - 1;
                bool rowok = ((unsigned)gz < 32u) && ((unsigned)gy < 32u);
                const float* s0 = in + (size_t)(cig0 + 2 * wword) * V + (gz << 10) + (gy << 5);
#pragma unroll
                for (int q = 0; q < 2; q++) {
                    int px = lane + q * 32;
                    if (px < 34) {
                        int gx = px - 1;
                        bool ok = rowok && ((unsigned)gx < 32u);
                        float v0 = ok ? __ldg(s0 + gx) : 0.f;
                        float v1 = ok ? __ldg(s0 + V + gx) : 0.f;
                        half2 h = __floats2half2_rn(v0, v1);
                        int voxel = rowid * 34 + px;
                        int st = (((wword >> 2) ^ ((voxel >> 1) & 3)) << 2) | (wword & 3);
                        P[voxel * 16 + st] = *(uint32_t*)&h;
                    }
                }
            }
        }
        __syncthreads();   // patch visible

        for (int tap = 0; tap < 27; tap++) {
            int s = cib * 27 + tap;
            int buf = s & 1;
            if (s + 1 < 189) LDG_B(s + 1);

            int dz = tap / 9, rem = tap - dz * 9;
            int dy = rem / 3, dx = rem - dy * 3;
            int vb = ((pzw + dz) * 6 + (yw + dy)) * 34 + dx;
            uint32_t Bbb = sbase + BBASE + (uint32_t)buf * 7168u;

#pragma unroll
            for (int ks = 0; ks < 2; ks++) {
                uint32_t af[2][4];
#pragma unroll
                for (int mt = 0; mt < 2; mt++) {
                    int v = vb + a_lro + (mt << 4);
                    uint32_t ad = sbase + (uint32_t)(v << 6)
                                + (uint32_t)((((ks << 1) + a_sh) ^ ((v >> 1) & 3)) << 4);
                    ldsm_x4(af[mt], ad);
                }
                uint32_t bf[7][2];
#pragma unroll
                for (int t = 0; t < 3; t++) {
                    uint32_t r[4];
                    uint32_t ad = Bbb + bco[t] + (uint32_t)((((ks << 1) + b_segbit) ^ bsw[t]) << 4);
                    ldsm_x4(r, ad);
                    bf[2 * t][0] = r[0]; bf[2 * t][1] = r[1];
                    bf[2 * t + 1][0] = r[2]; bf[2 * t + 1][1] = r[3];
                }
                {
                    uint32_t r2[2];
                    uint32_t ad = Bbb + bco[3] + (uint32_t)((((ks << 1) + b_segbit) ^ bsw[3]) << 4);
                    ldsm_x2(r2, ad);
                    bf[6][0] = r2[0]; bf[6][1] = r2[1];
                }
#pragma unroll
                for (int mt = 0; mt < 2; mt++)
#pragma unroll
                    for (int nt = 0; nt < 7; nt++)
                        mma_f16(acc[mt][nt], af[mt], bf[nt]);
            }
            if (s + 1 < 189) STS_B(buf ^ 1);
            __syncthreads();
        }
    }

    // ---- epilogue ----
    int zg = z0 + pzw, yg = y0 + yw;
#pragma unroll
    for (int mt = 0; mt < 2; mt++) {
        int x1 = (mt << 4) + r4;
        int pos = (zg << 10) + (yg << 5) + x1;
#pragma unroll
        for (int nt = 0; nt < 7; nt++) {
            int c = co0 + wn * 56 + (nt << 3) + (c4 << 1);
            if (c < CC) {
                float bb = bias[c];
                out[(size_t)c * V + pos] = acc[mt][nt][0] + bb;
                out[(size_t)c * V + pos + 8] = acc[mt][nt][2] + bb;
            }
            if (c + 1 < CC) {
                float bb = bias[c + 1];
                out[(size_t)(c + 1) * V + pos] = acc[mt][nt][1] + bb;
                out[(size_t)(c + 1) * V + pos + 8] = acc[mt][nt][3] + bb;
            }
        }
    }
}

// ======================= final 3-channel conv (fp32) =======================
__global__ void __launch_bounds__(256) conv_out_kernel(const float* __restrict__ in,
                                                       const float* __restrict__ w,
                                                       const float* __restrict__ bias,
                                                       float* __restrict__ out) {
    __shared__ float sp[816];
    __shared__ float sw[81];
    int tid = threadIdx.x;
    int z0 = (blockIdx.x >> 3) * 2;
    int y0 = (blockIdx.x & 7) * 4;
    int tz = tid >> 7, ty = (tid >> 5) & 3, tx = tid & 31;

    int poff[4]; bool pval[4];
#pragma unroll
    for (int k = 0; k < 4; k++) {
        int i = k * 256 + tid;
        int pz = i / 204, r = i % 204, py = r / 34, px = r % 34;
        int gz = z0 + pz - 1, gy = y0 + py - 1, gx = px - 1;
        pval[k] = (i < 816) && ((unsigned)gz < 32u) && ((unsigned)gy < 32u) && ((unsigned)gx < 32u);
        poff[k] = (gz << 10) + (gy << 5) + gx;
    }
    float acc[3] = {0.f, 0.f, 0.f};
    for (int ci = 0; ci < CC; ci++) {
        __syncthreads();
#pragma unroll
        for (int k = 0; k < 4; k++) {
            int i = k * 256 + tid;
            if (i < 816) sp[i] = pval[k] ? in[(size_t)ci * V + poff[k]] : 0.f;
        }
        if (tid < 81) sw[tid] = w[((size_t)(tid / 27) * CC + ci) * 27 + tid % 27];
        __syncthreads();
#pragma unroll
        for (int kz = 0; kz < 3; kz++)
#pragma unroll
            for (int ky = 0; ky < 3; ky++) {
                int base = ((tz + kz) * 6 + (ty + ky)) * 34 + tx;
                float v0 = sp[base], v1 = sp[base + 1], v2 = sp[base + 2];
#pragma unroll
                for (int kx = 0; kx < 3; kx++) {
                    int wt = (kz * 3 + ky) * 3 + kx;
                    float vv = (kx == 0) ? v0 : ((kx == 1) ? v1 : v2);
                    acc[0] += sw[wt] * vv;
                    acc[1] += sw[27 + wt] * vv;
                    acc[2] += sw[54 + wt] * vv;
                }
            }
    }
    int p = ((z0 + tz) << 10) + ((y0 + ty) << 5) + tx;
#pragma unroll
    for (int co = 0; co < 3; co++) out[(size_t)co * V + p] = acc[co] + bias[co];
}

// ======================= launch =======================
extern "C" void kernel_launch(void* const* d_in, const int* in_sizes, int n_in,
                              void* d_out, int out_size) {
    (void)in_sizes; (void)n_in; (void)out_size;
    const float* src   = (const float*)d_in[0];
    const float* tgt   = (const float*)d_in[1];
    const float* C     = (const float*)d_in[2];
    const float* up_w  = (const float*)d_in[3];
    const float* up_b  = (const float*)d_in[4];
    const float* c1_w  = (const float*)d_in[5];
    const float* c1_b  = (const float*)d_in[6];
    const float* c2_w  = (const float*)d_in[7];
    const float* c2_b  = (const float*)d_in[8];
    const float* out_w = (const float*)d_in[9];
    const float* out_b = (const float*)d_in[10];
    float* dout = (float*)d_out;

    float *gx = nullptr, *gy = nullptr;
    cudaGetSymbolAddress((void**)&gx, g_x);
    cudaGetSymbolAddress((void**)&gy, g_y);

    const int CONV_SMEM = 66560;   // (13056 + 2*1792) uint32 words
    cudaFuncSetAttribute(conv3_mma_kernel, cudaFuncAttributeMaxDynamicSharedMemorySize, CONV_SMEM);

    // Stage 1: build concat input (224 channels, pads zeroed)
    pad_zero_kernel<<<640, 256>>>();
    copy_kernel<<<2048, 256>>>(tgt, src);
    upsample_kernel<<<dim3(128, 4), 256>>>(C, up_w, up_b);
    corr_kernel<<<128, 256>>>(tgt, src);

    // IN + leaky on Cup (channels 155..218)
    stats_kernel<<<64, 256>>>(gx + (size_t)155 * V);
    norm_leaky_kernel<<<dim3(32, 64), 256>>>(gx + (size_t)155 * V);

    // conv1 (fp16 HMMA + ldmatrix) + IN + leaky
    reorder_w_kernel<<<2646, 256>>>(c1_w);
    conv3_mma_kernel<<<dim3(128, 2), 512, CONV_SMEM>>>(gx, c1_b, gy);
    stats_kernel<<<CC, 256>>>(gy);
    norm_leaky_kernel<<<dim3(32, CC), 256>>>(gy);

    // conv2 (fp16 HMMA + ldmatrix) + IN + leaky  -> Cn in d_out[0 .. 219*V)
    reorder_w_kernel<<<2646, 256>>>(c2_w);
    conv3_mma_kernel<<<dim3(128, 2), 512, CONV_SMEM>>>(gy, c2_b, dout);
    stats_kernel<<<CC, 256>>>(dout);
    norm_leaky_kernel<<<dim3(32, CC), 256>>>(dout);

    // output conv -> d_out[219*V .. 222*V)
    conv_out_kernel<<<128, 256>>>(dout, out_w, out_b, dout + (size_t)CC * V);
}

// round 8
// speedup vs baseline: 2.3980x; 1.0737x over previous
#include <cuda_runtime.h>
#include <cuda_fp16.h>
#include <cstdint>

#define V 32768            // 32*32*32
#define CC 219             // real channels
#define CP 224             // padded channels (multiple of 32)

__device__ float g_x[CP * V];              // concat input [tgt(64), src(64), cost(27), Cup(64), pad(5)=0]
__device__ float g_y[CP * V];              // conv1 output (padded)
__device__ uint32_t g_wh[27 * 7 * 3584];   // half2-packed pre-swizzled B (16B-granular swizzle)
__device__ float g_stats[CC * 2];          // per-channel (mean, rstd)

__device__ __forceinline__ uint32_t smem_u32(const void* p) {
    uint32_t a;
    asm("{ .reg .u64 t; cvta.to.shared.u64 t, %1; cvt.u32.u64 %0, t; }" : "=r"(a) : "l"(p));
    return a;
}
__device__ __forceinline__ void cp_async16(uint32_t dst, const void* src) {
    asm volatile("cp.async.cg.shared.global [%0], [%1], 16;" :: "r"(dst), "l"(src));
}
#define CP_COMMIT() asm volatile("cp.async.commit_group;" ::: "memory")
#define CP_WAIT1()  asm volatile("cp.async.wait_group 1;" ::: "memory")

__device__ __forceinline__ void mma_f16(float d[4], const uint32_t a[4], const uint32_t b[2]) {
    asm volatile(
        "mma.sync.aligned.m16n8k16.row.col.f32.f16.f16.f32 "
        "{%0,%1,%2,%3}, {%4,%5,%6,%7}, {%8,%9}, {%0,%1,%2,%3};"
        : "+f"(d[0]), "+f"(d[1]), "+f"(d[2]), "+f"(d[3])
        : "r"(a[0]), "r"(a[1]), "r"(a[2]), "r"(a[3]), "r"(b[0]), "r"(b[1]));
}
__device__ __forceinline__ void ldsm_x4(uint32_t r[4], uint32_t addr) {
    asm volatile("ldmatrix.sync.aligned.m8n8.x4.shared.b16 {%0,%1,%2,%3}, [%4];"
                 : "=r"(r[0]), "=r"(r[1]), "=r"(r[2]), "=r"(r[3]) : "r"(addr));
}
__device__ __forceinline__ void ldsm_x2(uint32_t r[2], uint32_t addr) {
    asm volatile("ldmatrix.sync.aligned.m8n8.x2.shared.b16 {%0,%1}, [%2];"
                 : "=r"(r[0]), "=r"(r[1]) : "r"(addr));
}

// ======================= small kernels =======================
__global__ void pad_zero_kernel() {
    int i = blockIdx.x * 256 + threadIdx.x;      // over 5*V
    g_x[(size_t)CC * V + i] = 0.f;
    g_y[(size_t)CC * V + i] = 0.f;
}

__global__ void copy_kernel(const float* __restrict__ tgt, const float* __restrict__ src) {
    int i = blockIdx.x * 256 + threadIdx.x;   // over 64*V/4 float4
    float4* dx = (float4*)g_x;
    dx[i] = ((const float4*)tgt)[i];
    dx[(64 * V) / 4 + i] = ((const float4*)src)[i];
}

// weight reorder: half2 pack + 16B-granular swizzle.
// storage jj for co: logical word w = ((jj>>2) ^ ((co>>1)&3))<<2 | (jj&3); holds ci pair (2w, 2w+1)
__global__ void reorder_w_kernel(const float* __restrict__ w) {
    int id = blockIdx.x * 256 + threadIdx.x;     // < 27*7*3584 = 677376
    if (id >= 27 * 7 * 3584) return;
    int blob = id / 3584, r = id % 3584;
    int tap = blob / 7, cib = blob % 7;
    int co = r >> 4, jj = r & 15;
    int wlog = (((jj >> 2) ^ ((co >> 1) & 3)) << 2) | (jj & 3);
    int ci0 = cib * 32 + 2 * wlog;
    float v0 = 0.f, v1 = 0.f;
    if (co < CC) {
        if (ci0 < CC)     v0 = w[((size_t)co * CC + ci0) * 27 + tap];
        if (ci0 + 1 < CC) v1 = w[((size_t)co * CC + ci0 + 1) * 27 + tap];
    }
    half2 h = __floats2half2_rn(v0, v1);
    g_wh[id] = *(uint32_t*)&h;
}

// ======================= correlation volume =======================
__global__ void __launch_bounds__(256) corr_kernel(const float* __restrict__ tgt,
                                                   const float* __restrict__ src) {
    __shared__ float sp[4 * 6 * 34];
    int tid = threadIdx.x;
    int z0 = (blockIdx.x >> 3) * 2;
    int y0 = (blockIdx.x & 7) * 4;
    int tz = tid >> 7, ty = (tid >> 5) & 3, tx = tid & 31;
    int z = z0 + tz, y = y0 + ty;
    int p = (z << 10) + (y << 5) + tx;

    int poff[4]; bool pval[4];
#pragma unroll
    for (int k = 0; k < 4; k++) {
        int i = k * 256 + tid;
        int pz = i / 204, r = i % 204, py = r / 34, px = r % 34;
        int gz = z0 + pz - 1, gy = y0 + py - 1, gx = px - 1;
        pval[k] = (i < 816) && ((unsigned)gz < 32u) && ((unsigned)gy < 32u) && ((unsigned)gx < 32u);
        poff[k] = (gz << 10) + (gy << 5) + gx;
    }
    float acc[27];
#pragma unroll
    for (int d = 0; d < 27; d++) acc[d] = 0.f;
    for (int c = 0; c < 64; c++) {
        __syncthreads();
#pragma unroll
        for (int k = 0; k < 4; k++) {
            int i = k * 256 + tid;
            if (i < 816) sp[i] = pval[k] ? src[c * V + poff[k]] : 0.f;
        }
        __syncthreads();
        float t = tgt[c * V + p];
#pragma unroll
        for (int dz = 0; dz < 3; dz++)
#pragma unroll
            for (int dy = 0; dy < 3; dy++) {
                int base = ((tz + dz) * 6 + (ty + dy)) * 34 + tx;
                acc[dz * 9 + dy * 3 + 0] += t * sp[base];
                acc[dz * 9 + dy * 3 + 1] += t * sp[base + 1];
                acc[dz * 9 + dy * 3 + 2] += t * sp[base + 2];
            }
    }
    const float inv = 1.f / 64.f;
#pragma unroll
    for (int d = 0; d < 27; d++) g_x[(size_t)(128 + d) * V + p] = acc[d] * inv;
}

// ======================= conv transpose upsample =======================
__global__ void __launch_bounds__(256) upsample_kernel(const float* __restrict__ Cin,
                                                       const float* __restrict__ w,
                                                       const float* __restrict__ bias) {
    __shared__ float swt[16 * 64];
    __shared__ float spatch[3 * 4 * 18];
    int tid = threadIdx.x;
    int z0 = (blockIdx.x >> 3) * 2;
    int y0 = (blockIdx.x & 7) * 4;
    int co0 = blockIdx.y * 16;
    int tz = tid >> 7, ty = (tid >> 5) & 3, tx = tid & 31;
    int oz = z0 + tz, oy = y0 + ty, ox = tx;
    int izb = (z0 >> 1) - 1, iyb = (y0 >> 1) - 1;

    int taps[8]; int nt = 0;
    for (int kz = (oz + 1) & 1; kz < 4; kz += 2) {
        int iz = (oz + 1 - kz) >> 1; if (iz < 0 || iz >= 16) continue;
        for (int ky = (oy + 1) & 1; ky < 4; ky += 2) {
            int iy = (oy + 1 - ky) >> 1; if (iy < 0 || iy >= 16) continue;
            for (int kx = (ox + 1) & 1; kx < 4; kx += 2) {
                int ix = (ox + 1 - kx) >> 1; if (ix < 0 || ix >= 16) continue;
                int pofs = ((iz - izb) * 4 + (iy - iyb)) * 18 + (ix + 1);
                int wofs = (kz << 4) + (ky << 2) + kx;
                taps[nt++] = pofs | (wofs << 16);
            }
        }
    }
    int pl_off = 0; bool pl_val = false;
    if (tid < 216) {
        int pz = tid / 72, r = tid % 72, py = r / 18, px = r % 18;
        int gz = izb + pz, gy = iyb + py, gx = px - 1;
        pl_val = ((unsigned)gz < 16u) && ((unsigned)gy < 16u) && ((unsigned)gx < 16u);
        pl_off = (gz << 8) + (gy << 4) + gx;
    }
    float acc[16];
#pragma unroll
    for (int j = 0; j < 16; j++) acc[j] = 0.f;
    for (int ci = 0; ci < 411; ci++) {
        __syncthreads();
        if (tid < 216) spatch[tid] = pl_val ? Cin[ci * 4096 + pl_off] : 0.f;
        const float* wc = w + ((size_t)ci * 64 + co0) * 64;
#pragma unroll
        for (int k = 0; k < 4; k++) swt[k * 256 + tid] = wc[k * 256 + tid];
        __syncthreads();
        for (int t = 0; t < nt; t++) {
            int tp = taps[t];
            float v = spatch[tp & 0xffff];
            int wofs = tp >> 16;
#pragma unroll
            for (int j = 0; j < 16; j++) acc[j] += v * swt[(j << 6) + wofs];
        }
    }
    int p = (oz << 10) + (oy << 5) + ox;
#pragma unroll
    for (int j = 0; j < 16; j++)
        g_x[(size_t)(155 + co0 + j) * V + p] = acc[j] + bias[co0 + j];
}

// ======================= instance norm =======================
__global__ void stats_kernel(const float* __restrict__ x) {
    int ch = blockIdx.x;
    const float4* p4 = (const float4*)(x + (size_t)ch * V);
    float s = 0.f, s2 = 0.f;
    for (int i = threadIdx.x; i < V / 4; i += 256) {
        float4 v = p4[i];
        s += v.x + v.y + v.z + v.w;
        s2 += v.x * v.x + v.y * v.y + v.z * v.z + v.w * v.w;
    }
#pragma unroll
    for (int o = 16; o; o >>= 1) {
        s += __shfl_down_sync(0xffffffffu, s, o);
        s2 += __shfl_down_sync(0xffffffffu, s2, o);
    }
    __shared__ float a[8], b[8];
    int wp = threadIdx.x >> 5, ln = threadIdx.x & 31;
    if (ln == 0) { a[wp] = s; b[wp] = s2; }
    __syncthreads();
    if (threadIdx.x < 8) {
        s = a[threadIdx.x]; s2 = b[threadIdx.x];
#pragma unroll
        for (int o = 4; o; o >>= 1) {
            s += __shfl_down_sync(0xffu, s, o);
            s2 += __shfl_down_sync(0xffu, s2, o);
        }
        if (threadIdx.x == 0) {
            float m = s * (1.f / V);
            float var = s2 * (1.f / V) - m * m;
            g_stats[ch * 2] = m;
            g_stats[ch * 2 + 1] = rsqrtf(var + 1e-5f);
        }
    }
}

__global__ void norm_leaky_kernel(float* __restrict__ x) {
    int ch = blockIdx.y;
    int i = blockIdx.x * 256 + threadIdx.x;
    float m = g_stats[ch * 2], r = g_stats[ch * 2 + 1];
    float4* p = (float4*)(x + (size_t)ch * V);
    float4 v = p[i];
    v.x = (v.x - m) * r; v.x = v.x >= 0.f ? v.x : 0.1f * v.x;
    v.y = (v.y - m) * r; v.y = v.y >= 0.f ? v.y : 0.1f * v.y;
    v.z = (v.z - m) * r; v.z = v.z >= 0.f ? v.z : 0.1f * v.z;
    v.w = (v.w - m) * r; v.w = v.w >= 0.f ? v.w : 0.1f * v.w;
    p[i] = v;
}

// ======================= fp16 HMMA conv3x3x3: patch-resident + cp.async 9-tap B groups ========
// CTA: M=256 (2z x 4y x 32x) x N=112 co. 512 threads = 16 warps (8 wm x 2 wn), warp tile 32x56.
// Patch: 816 voxel-rows x 16 half2 words, 16B-seg swizzle. B: 2 group buffers x 9 taps x 1792 words,
// filled by cp.async (2-deep group pipeline). Linear schedule s=0..20: cib=s/3, dz-group=s%3.
// Dyn SMEM: (13056 + 32256) words = 181248 B.
__global__ void __launch_bounds__(512) conv3_mma_kernel(const float* __restrict__ in,
                                                        const float* __restrict__ bias,
                                                        float* __restrict__ out) {
    extern __shared__ uint32_t smem32[];
    uint32_t* P = smem32;                    // 13056 words
    uint32_t sbase = smem_u32(smem32);
    const uint32_t BBYTE = 13056u * 4u;      // byte offset of B buffers (2 x 64512 B)

    int tid = threadIdx.x, wid = tid >> 5, lane = tid & 31;
    int zt = blockIdx.x >> 3, yt = blockIdx.x & 7;
    int z0 = zt * 2, y0 = yt * 4;
    int co0 = blockIdx.y * 112;

    int wm = wid >> 1, wn = wid & 1;
    int r4 = lane >> 2, c4 = lane & 3;
    int pzw = wm >> 2, yw = wm & 3;          // warp's (zl, yl)

    // ldmatrix lane constants
    int sub = lane >> 3, l7 = lane & 7;
    int a_lro = ((sub & 1) << 3) + l7;
    int a_sh = sub >> 1;
    int b_segbit = sub & 1;
    int b_ntoff = sub >> 1;
    uint32_t bco[4]; int bsw[4];
#pragma unroll
    for (int t = 0; t < 3; t++) {
        int co = wn * 56 + (2 * t + b_ntoff) * 8 + l7;
        bco[t] = (uint32_t)(co << 6);
        bsw[t] = (co >> 1) & 3;
    }
    {
        int co = wn * 56 + 48 + l7;
        bco[3] = (uint32_t)(co << 6);
        bsw[3] = (co >> 1) & 3;
    }

    float acc[2][7][4];
#pragma unroll
    for (int a = 0; a < 2; a++)
#pragma unroll
        for (int b = 0; b < 7; b++)
#pragma unroll
            for (int c = 0; c < 4; c++) acc[a][b][c] = 0.f;

    // ---- cp.async group prefetch: 9 taps x 1792 words = 4032 x 16B ----
#define PREFETCH_GRP(s_, buf_) do { \
        int cib_ = (s_) / 3, grp_ = (s_) % 3; \
        uint32_t dbase = sbase + BBYTE + (uint32_t)(buf_) * 64512u; \
        _Pragma("unroll") \
        for (int it = 0; it < 8; it++) { \
            int i = tid + it * 512; \
            if (i < 4032) { \
                int tl = i / 448, rem = i - tl * 448; \
                const uint32_t* src = g_wh + (size_t)((grp_ * 9 + tl) * 7 + cib_) * 3584 + co0 * 16 + rem * 4; \
                cp_async16(dbase + (uint32_t)(tl * 7168 + rem * 16), src); \
            } \
        } \
        CP_COMMIT(); \
    } while (0)

    PREFETCH_GRP(0, 0);
    PREFETCH_GRP(1, 1);

    for (int s = 0; s < 21; s++) {
        int cib = s / 3, grp = s - cib * 3;
        int buf = s & 1;

        if (grp == 0) {
            // ---- stage patch for this ci-block (previous patch consumed: post-compute sync) ----
            int cig0 = cib * 32;
#pragma unroll 4
            for (int jj = 0; jj < 24; jj++) {
                int p = wid + jj * 16;
                int wword = p & 15;
                int rowid = p >> 4;
                int pz = rowid / 6, py = rowid - pz * 6;
                int gz = z0 + pz - 1, gy = y0 + py - 1;
                bool rowok = ((unsigned)gz < 32u) && ((unsigned)gy < 32u);
                const float* s0 = in + (size_t)(cig0 + 2 * wword) * V + (gz << 10) + (gy << 5);
#pragma unroll
                for (int q = 0; q < 2; q++) {
                    int px = lane + q * 32;
                    if (px < 34) {
                        int gx = px - 1;
                        bool ok = rowok && ((unsigned)gx < 32u);
                        float v0 = ok ? __ldg(s0 + gx) : 0.f;
                        float v1 = ok ? __ldg(s0 + V + gx) : 0.f;
                        half2 h = __floats2half2_rn(v0, v1);
                        int voxel = rowid * 34 + px;
                        int st = (((wword >> 2) ^ ((voxel >> 1) & 3)) << 2) | (wword & 3);
                        P[voxel * 16 + st] = *(uint32_t*)&h;
                    }
                }
            }
        }

        CP_WAIT1();
        __syncthreads();      // B(buf) ready + patch visible

        // ---- compute 9 taps (dz = grp) ----
#pragma unroll
        for (int t = 0; t < 9; t++) {
            int dy = t / 3, dx = t - dy * 3;
            int vb = ((pzw + grp) * 6 + (yw + dy)) * 34 + dx;
            uint32_t Bbb = sbase + BBYTE + (uint32_t)buf * 64512u + (uint32_t)t * 7168u;

#pragma unroll
            for (int ks = 0; ks < 2; ks++) {
                uint32_t af[2][4];
#pragma unroll
                for (int mt = 0; mt < 2; mt++) {
                    int v = vb + a_lro + (mt << 4);
                    uint32_t ad = sbase + (uint32_t)(v << 6)
                                + (uint32_t)((((ks << 1) + a_sh) ^ ((v >> 1) & 3)) << 4);
                    ldsm_x4(af[mt], ad);
                }
                uint32_t bf[7][2];
#pragma unroll
                for (int t2 = 0; t2 < 3; t2++) {
                    uint32_t r[4];
                    uint32_t ad = Bbb + bco[t2] + (uint32_t)((((ks << 1) + b_segbit) ^ bsw[t2]) << 4);
                    ldsm_x4(r, ad);
                    bf[2 * t2][0] = r[0]; bf[2 * t2][1] = r[1];
                    bf[2 * t2 + 1][0] = r[2]; bf[2 * t2 + 1][1] = r[3];
                }
                {
                    uint32_t r2[2];
                    uint32_t ad = Bbb + bco[3] + (uint32_t)((((ks << 1) + b_segbit) ^ bsw[3]) << 4);
                    ldsm_x2(r2, ad);
                    bf[6][0] = r2[0]; bf[6][1] = r2[1];
                }
#pragma unroll
                for (int mt = 0; mt < 2; mt++)
#pragma unroll
                    for (int nt = 0; nt < 7; nt++)
                        mma_f16(acc[mt][nt], af[mt], bf[nt]);
            }
        }

        __syncthreads();      // all warps done reading B(buf) (+ patch, if last grp of cib)
        if (s + 2 < 21) PREFETCH_GRP(s + 2, buf);
    }

    // ---- epilogue ----
    int zg = z0 + pzw, yg = y0 + yw;
#pragma unroll
    for (int mt = 0; mt < 2; mt++) {
        int x1 = (mt << 4) + r4;
        int pos = (zg << 10) + (yg << 5) + x1;
#pragma unroll
        for (int nt = 0; nt < 7; nt++) {
            int c = co0 + wn * 56 + (nt << 3) + (c4 << 1);
            if (c < CC) {
                float bb = bias[c];
                out[(size_t)c * V + pos] = acc[mt][nt][0] + bb;
                out[(size_t)c * V + pos + 8] = acc[mt][nt][2] + bb;
            }
            if (c + 1 < CC) {
                float bb = bias[c + 1];
                out[(size_t)(c + 1) * V + pos] = acc[mt][nt][1] + bb;
                out[(size_t)(c + 1) * V + pos + 8] = acc[mt][nt][3] + bb;
            }
        }
    }
}

// ======================= final 3-channel conv (fp32) =======================
__global__ void __launch_bounds__(256) conv_out_kernel(const float* __restrict__ in,
                                                       const float* __restrict__ w,
                                                       const float* __restrict__ bias,
                                                       float* __restrict__ out) {
    __shared__ float sp[816];
    __shared__ float sw[81];
    int tid = threadIdx.x;
    int z0 = (blockIdx.x >> 3) * 2;
    int y0 = (blockIdx.x & 7) * 4;
    int tz = tid >> 7, ty = (tid >> 5) & 3, tx = tid & 31;

    int poff[4]; bool pval[4];
#pragma unroll
    for (int k = 0; k < 4; k++) {
        int i = k * 256 + tid;
        int pz = i / 204, r = i % 204, py = r / 34, px = r % 34;
        int gz = z0 + pz - 1, gy = y0 + py - 1, gx = px - 1;
        pval[k] = (i < 816) && ((unsigned)gz < 32u) && ((unsigned)gy < 32u) && ((unsigned)gx < 32u);
        poff[k] = (gz << 10) + (gy << 5) + gx;
    }
    float acc[3] = {0.f, 0.f, 0.f};
    for (int ci = 0; ci < CC; ci++) {
        __syncthreads();
#pragma unroll
        for (int k = 0; k < 4; k++) {
            int i = k * 256 + tid;
            if (i < 816) sp[i] = pval[k] ? in[(size_t)ci * V + poff[k]] : 0.f;
        }
        if (tid < 81) sw[tid] = w[((size_t)(tid / 27) * CC + ci) * 27 + tid % 27];
        __syncthreads();
#pragma unroll
        for (int kz = 0; kz < 3; kz++)
#pragma unroll
            for (int ky = 0; ky < 3; ky++) {
                int base = ((tz + kz) * 6 + (ty + ky)) * 34 + tx;
                float v0 = sp[base], v1 = sp[base + 1], v2 = sp[base + 2];
#pragma unroll
                for (int kx = 0; kx < 3; kx++) {
                    int wt = (kz * 3 + ky) * 3 + kx;
                    float vv = (kx == 0) ? v0 : ((kx == 1) ? v1 : v2);
                    acc[0] += sw[wt] * vv;
                    acc[1] += sw[27 + wt] * vv;
                    acc[2] += sw[54 + wt] * vv;
                }
            }
    }
    int p = ((z0 + tz) << 10) + ((y0 + ty) << 5) + tx;
#pragma unroll
    for (int co = 0; co < 3; co++) out[(size_t)co * V + p] = acc[co] + bias[co];
}

// ======================= launch =======================
extern "C" void kernel_launch(void* const* d_in, const int* in_sizes, int n_in,
                              void* d_out, int out_size) {
    (void)in_sizes; (void)n_in; (void)out_size;
    const float* src   = (const float*)d_in[0];
    const float* tgt   = (const float*)d_in[1];
    const float* C     = (const float*)d_in[2];
    const float* up_w  = (const float*)d_in[3];
    const float* up_b  = (const float*)d_in[4];
    const float* c1_w  = (const float*)d_in[5];
    const float* c1_b  = (const float*)d_in[6];
    const float* c2_w  = (const float*)d_in[7];
    const float* c2_b  = (const float*)d_in[8];
    const float* out_w = (const float*)d_in[9];
    const float* out_b = (const float*)d_in[10];
    float* dout = (float*)d_out;

    float *gx = nullptr, *gy = nullptr;
    cudaGetSymbolAddress((void**)&gx, g_x);
    cudaGetSymbolAddress((void**)&gy, g_y);

    const int CONV_SMEM = 181248;   // (13056 + 2*16128) uint32 words
    cudaFuncSetAttribute(conv3_mma_kernel, cudaFuncAttributeMaxDynamicSharedMemorySize, CONV_SMEM);

    // Stage 1: build concat input (224 channels, pads zeroed)
    pad_zero_kernel<<<640, 256>>>();
    copy_kernel<<<2048, 256>>>(tgt, src);
    upsample_kernel<<<dim3(128, 4), 256>>>(C, up_w, up_b);
    corr_kernel<<<128, 256>>>(tgt, src);

    // IN + leaky on Cup (channels 155..218)
    stats_kernel<<<64, 256>>>(gx + (size_t)155 * V);
    norm_leaky_kernel<<<dim3(32, 64), 256>>>(gx + (size_t)155 * V);

    // conv1 (fp16 HMMA + cp.async groups) + IN + leaky
    reorder_w_kernel<<<2646, 256>>>(c1_w);
    conv3_mma_kernel<<<dim3(128, 2), 512, CONV_SMEM>>>(gx, c1_b, gy);
    stats_kernel<<<CC, 256>>>(gy);
    norm_leaky_kernel<<<dim3(32, CC), 256>>>(gy);

    // conv2 (fp16 HMMA + cp.async groups) + IN + leaky  -> Cn in d_out[0 .. 219*V)
    reorder_w_kernel<<<2646, 256>>>(c2_w);
    conv3_mma_kernel<<<dim3(128, 2), 512, CONV_SMEM>>>(gy, c2_b, dout);
    stats_kernel<<<CC, 256>>>(dout);
    norm_leaky_kernel<<<dim3(32, CC), 256>>>(dout);

    // output conv -> d_out[219*V .. 222*V)
    conv_out_kernel<<<128, 256>>>(dout, out_w, out_b, dout + (size_t)CC * V);
}

// round 9
// speedup vs baseline: 2.4895x; 1.0382x over previous
#include <cuda_runtime.h>
#include <cuda_fp16.h>
#include <cstdint>

#define V 32768            // 32*32*32
#define CC 219             // real channels
#define CP 224             // padded channels (multiple of 32)

__device__ float g_x[CP * V];              // concat input [tgt(64), src(64), cost(27), Cup(64), pad(5)=0]
__device__ float g_y[CP * V];              // conv1 output (padded)
__device__ uint32_t g_wh[27 * 7 * 3584];   // half2-packed pre-swizzled B (16B-granular swizzle)
__device__ float g_stats[CC * 2];          // per-channel (mean, rstd)

__device__ __forceinline__ uint32_t smem_u32(const void* p) {
    uint32_t a;
    asm("{ .reg .u64 t; cvta.to.shared.u64 t, %1; cvt.u32.u64 %0, t; }" : "=r"(a) : "l"(p));
    return a;
}
__device__ __forceinline__ void cp_async16(uint32_t dst, const void* src) {
    asm volatile("cp.async.cg.shared.global [%0], [%1], 16;" :: "r"(dst), "l"(src));
}
#define CP_COMMIT() asm volatile("cp.async.commit_group;" ::: "memory")
#define CP_WAIT1()  asm volatile("cp.async.wait_group 1;" ::: "memory")

__device__ __forceinline__ void mma_f16(float d[4], const uint32_t a[4], const uint32_t b[2]) {
    asm volatile(
        "mma.sync.aligned.m16n8k16.row.col.f32.f16.f16.f32 "
        "{%0,%1,%2,%3}, {%4,%5,%6,%7}, {%8,%9}, {%0,%1,%2,%3};"
        : "+f"(d[0]), "+f"(d[1]), "+f"(d[2]), "+f"(d[3])
        : "r"(a[0]), "r"(a[1]), "r"(a[2]), "r"(a[3]), "r"(b[0]), "r"(b[1]));
}
__device__ __forceinline__ void ldsm_x4(uint32_t r[4], uint32_t addr) {
    asm volatile("ldmatrix.sync.aligned.m8n8.x4.shared.b16 {%0,%1,%2,%3}, [%4];"
                 : "=r"(r[0]), "=r"(r[1]), "=r"(r[2]), "=r"(r[3]) : "r"(addr));
}
__device__ __forceinline__ void ldsm_x2(uint32_t r[2], uint32_t addr) {
    asm volatile("ldmatrix.sync.aligned.m8n8.x2.shared.b16 {%0,%1}, [%2];"
                 : "=r"(r[0]), "=r"(r[1]) : "r"(addr));
}

// ======================= small kernels =======================
__global__ void pad_zero_kernel() {
    int i = blockIdx.x * 256 + threadIdx.x;      // over 5*V
    g_x[(size_t)CC * V + i] = 0.f;
    g_y[(size_t)CC * V + i] = 0.f;
}

__global__ void copy_kernel(const float* __restrict__ tgt, const float* __restrict__ src) {
    int i = blockIdx.x * 256 + threadIdx.x;   // over 64*V/4 float4
    float4* dx = (float4*)g_x;
    dx[i] = ((const float4*)tgt)[i];
    dx[(64 * V) / 4 + i] = ((const float4*)src)[i];
}

// weight reorder: half2 pack + 16B-granular swizzle.
__global__ void reorder_w_kernel(const float* __restrict__ w) {
    int id = blockIdx.x * 256 + threadIdx.x;     // < 27*7*3584 = 677376
    if (id >= 27 * 7 * 3584) return;
    int blob = id / 3584, r = id % 3584;
    int tap = blob / 7, cib = blob % 7;
    int co = r >> 4, jj = r & 15;
    int wlog = (((jj >> 2) ^ ((co >> 1) & 3)) << 2) | (jj & 3);
    int ci0 = cib * 32 + 2 * wlog;
    float v0 = 0.f, v1 = 0.f;
    if (co < CC) {
        if (ci0 < CC)     v0 = w[((size_t)co * CC + ci0) * 27 + tap];
        if (ci0 + 1 < CC) v1 = w[((size_t)co * CC + ci0 + 1) * 27 + tap];
    }
    half2 h = __floats2half2_rn(v0, v1);
    g_wh[id] = *(uint32_t*)&h;
}

// ======================= correlation volume =======================
__global__ void __launch_bounds__(256) corr_kernel(const float* __restrict__ tgt,
                                                   const float* __restrict__ src) {
    __shared__ float sp[4 * 6 * 34];
    int tid = threadIdx.x;
    int z0 = (blockIdx.x >> 3) * 2;
    int y0 = (blockIdx.x & 7) * 4;
    int tz = tid >> 7, ty = (tid >> 5) & 3, tx = tid & 31;
    int z = z0 + tz, y = y0 + ty;
    int p = (z << 10) + (y << 5) + tx;

    int poff[4]; bool pval[4];
#pragma unroll
    for (int k = 0; k < 4; k++) {
        int i = k * 256 + tid;
        int pz = i / 204, r = i % 204, py = r / 34, px = r % 34;
        int gz = z0 + pz - 1, gy = y0 + py - 1, gx = px - 1;
        pval[k] = (i < 816) && ((unsigned)gz < 32u) && ((unsigned)gy < 32u) && ((unsigned)gx < 32u);
        poff[k] = (gz << 10) + (gy << 5) + gx;
    }
    float acc[27];
#pragma unroll
    for (int d = 0; d < 27; d++) acc[d] = 0.f;
    for (int c = 0; c < 64; c++) {
        __syncthreads();
#pragma unroll
        for (int k = 0; k < 4; k++) {
            int i = k * 256 + tid;
            if (i < 816) sp[i] = pval[k] ? src[c * V + poff[k]] : 0.f;
        }
        __syncthreads();
        float t = tgt[c * V + p];
#pragma unroll
        for (int dz = 0; dz < 3; dz++)
#pragma unroll
            for (int dy = 0; dy < 3; dy++) {
                int base = ((tz + dz) * 6 + (ty + dy)) * 34 + tx;
                acc[dz * 9 + dy * 3 + 0] += t * sp[base];
                acc[dz * 9 + dy * 3 + 1] += t * sp[base + 1];
                acc[dz * 9 + dy * 3 + 2] += t * sp[base + 2];
            }
    }
    const float inv = 1.f / 64.f;
#pragma unroll
    for (int d = 0; d < 27; d++) g_x[(size_t)(128 + d) * V + p] = acc[d] * inv;
}

// ======================= conv transpose upsample =======================
__global__ void __launch_bounds__(256) upsample_kernel(const float* __restrict__ Cin,
                                                       const float* __restrict__ w,
                                                       const float* __restrict__ bias) {
    __shared__ float swt[16 * 64];
    __shared__ float spatch[3 * 4 * 18];
    int tid = threadIdx.x;
    int z0 = (blockIdx.x >> 3) * 2;
    int y0 = (blockIdx.x & 7) * 4;
    int co0 = blockIdx.y * 16;
    int tz = tid >> 7, ty = (tid >> 5) & 3, tx = tid & 31;
    int oz = z0 + tz, oy = y0 + ty, ox = tx;
    int izb = (z0 >> 1) - 1, iyb = (y0 >> 1) - 1;

    int taps[8]; int nt = 0;
    for (int kz = (oz + 1) & 1; kz < 4; kz += 2) {
        int iz = (oz + 1 - kz) >> 1; if (iz < 0 || iz >= 16) continue;
        for (int ky = (oy + 1) & 1; ky < 4; ky += 2) {
            int iy = (oy + 1 - ky) >> 1; if (iy < 0 || iy >= 16) continue;
            for (int kx = (ox + 1) & 1; kx < 4; kx += 2) {
                int ix = (ox + 1 - kx) >> 1; if (ix < 0 || ix >= 16) continue;
                int pofs = ((iz - izb) * 4 + (iy - iyb)) * 18 + (ix + 1);
                int wofs = (kz << 4) + (ky << 2) + kx;
                taps[nt++] = pofs | (wofs << 16);
            }
        }
    }
    int pl_off = 0; bool pl_val = false;
    if (tid < 216) {
        int pz = tid / 72, r = tid % 72, py = r / 18, px = r % 18;
        int gz = izb + pz, gy = iyb + py, gx = px - 1;
        pl_val = ((unsigned)gz < 16u) && ((unsigned)gy < 16u) && ((unsigned)gx < 16u);
        pl_off = (gz << 8) + (gy << 4) + gx;
    }
    float acc[16];
#pragma unroll
    for (int j = 0; j < 16; j++) acc[j] = 0.f;
    for (int ci = 0; ci < 411; ci++) {
        __syncthreads();
        if (tid < 216) spatch[tid] = pl_val ? Cin[ci * 4096 + pl_off] : 0.f;
        const float* wc = w + ((size_t)ci * 64 + co0) * 64;
#pragma unroll
        for (int k = 0; k < 4; k++) swt[k * 256 + tid] = wc[k * 256 + tid];
        __syncthreads();
        for (int t = 0; t < nt; t++) {
            int tp = taps[t];
            float v = spatch[tp & 0xffff];
            int wofs = tp >> 16;
#pragma unroll
            for (int j = 0; j < 16; j++) acc[j] += v * swt[(j << 6) + wofs];
        }
    }
    int p = (oz << 10) + (oy << 5) + ox;
#pragma unroll
    for (int j = 0; j < 16; j++)
        g_x[(size_t)(155 + co0 + j) * V + p] = acc[j] + bias[co0 + j];
}

// ======================= instance norm =======================
__global__ void stats_kernel(const float* __restrict__ x) {
    int ch = blockIdx.x;
    const float4* p4 = (const float4*)(x + (size_t)ch * V);
    float s = 0.f, s2 = 0.f;
    for (int i = threadIdx.x; i < V / 4; i += 256) {
        float4 v = p4[i];
        s += v.x + v.y + v.z + v.w;
        s2 += v.x * v.x + v.y * v.y + v.z * v.z + v.w * v.w;
    }
#pragma unroll
    for (int o = 16; o; o >>= 1) {
        s += __shfl_down_sync(0xffffffffu, s, o);
        s2 += __shfl_down_sync(0xffffffffu, s2, o);
    }
    __shared__ float a[8], b[8];
    int wp = threadIdx.x >> 5, ln = threadIdx.x & 31;
    if (ln == 0) { a[wp] = s; b[wp] = s2; }
    __syncthreads();
    if (threadIdx.x < 8) {
        s = a[threadIdx.x]; s2 = b[threadIdx.x];
#pragma unroll
        for (int o = 4; o; o >>= 1) {
            s += __shfl_down_sync(0xffu, s, o);
            s2 += __shfl_down_sync(0xffu, s2, o);
        }
        if (threadIdx.x == 0) {
            float m = s * (1.f / V);
            float var = s2 * (1.f / V) - m * m;
            g_stats[ch * 2] = m;
            g_stats[ch * 2 + 1] = rsqrtf(var + 1e-5f);
        }
    }
}

__global__ void norm_leaky_kernel(float* __restrict__ x) {
    int ch = blockIdx.y;
    int i = blockIdx.x * 256 + threadIdx.x;
    float m = g_stats[ch * 2], r = g_stats[ch * 2 + 1];
    float4* p = (float4*)(x + (size_t)ch * V);
    float4 v = p[i];
    v.x = (v.x - m) * r; v.x = v.x >= 0.f ? v.x : 0.1f * v.x;
    v.y = (v.y - m) * r; v.y = v.y >= 0.f ? v.y : 0.1f * v.y;
    v.z = (v.z - m) * r; v.z = v.z >= 0.f ? v.z : 0.1f * v.z;
    v.w = (v.w - m) * r; v.w = v.w >= 0.f ? v.w : 0.1f * v.w;
    p[i] = v;
}

// ======================= fp16 HMMA conv3x3x3: 2 CTAs/SM, cp.async 3-tap B groups ========
// CTA: M=128 (1z x 4y x 32x) x N=112 co. 256 threads = 8 warps (4 wm=y x 2 wn), warp tile 32x56.
// Patch: 3z x 6y x 34x voxels x 32 ci (612 rows x 16 half2 words), 16B-seg swizzle.
// B: 2 buffers x 3 taps x 1792 words via cp.async. 63 steps: cib=s/9, grp=s%9 (taps 3grp..3grp+2).
// Dyn SMEM: (9792 + 2*5376) words = 82176 B -> 2 CTAs/SM.
__global__ void __launch_bounds__(256, 2) conv3_mma_kernel(const float* __restrict__ in,
                                                           const float* __restrict__ bias,
                                                           float* __restrict__ out) {
    extern __shared__ uint32_t smem32[];
    uint32_t* P = smem32;                    // 9792 words
    uint32_t sbase = smem_u32(smem32);
    const uint32_t BBYTE = 9792u * 4u;       // byte offset of B buffers (2 x 21504 B)

    int tid = threadIdx.x, wid = tid >> 5, lane = tid & 31;
    int z = blockIdx.x >> 3, yt = blockIdx.x & 7;
    int y0 = yt * 4;
    int co0 = blockIdx.y * 112;

    int wm = wid >> 1, wn = wid & 1;         // wm = local y row
    int r4 = lane >> 2, c4 = lane & 3;

    // ldmatrix lane constants
    int sub = lane >> 3, l7 = lane & 7;
    int a_lro = ((sub & 1) << 3) + l7;
    int a_sh = sub >> 1;
    int b_segbit = sub & 1;
    int b_ntoff = sub >> 1;
    uint32_t bco[4]; int bsw[4];
#pragma unroll
    for (int t = 0; t < 3; t++) {
        int co = wn * 56 + (2 * t + b_ntoff) * 8 + l7;
        bco[t] = (uint32_t)(co << 6);
        bsw[t] = (co >> 1) & 3;
    }
    {
        int co = wn * 56 + 48 + l7;
        bco[3] = (uint32_t)(co << 6);
        bsw[3] = (co >> 1) & 3;
    }

    float acc[2][7][4];
#pragma unroll
    for (int a = 0; a < 2; a++)
#pragma unroll
        for (int b = 0; b < 7; b++)
#pragma unroll
            for (int c = 0; c < 4; c++) acc[a][b][c] = 0.f;

    // ---- cp.async group prefetch: 3 taps x 1792 words = 1344 x 16B ----
#define PREFETCH_GRP(s_, buf_) do { \
        int cib_ = (s_) / 9, grp_ = (s_) % 9; \
        uint32_t dbase = sbase + BBYTE + (uint32_t)(buf_) * 21504u; \
        _Pragma("unroll") \
        for (int it = 0; it < 6; it++) { \
            int i = tid + it * 256; \
            if (i < 1344) { \
                int tl = i / 448, rem = i - tl * 448; \
                const uint32_t* src = g_wh + (size_t)((grp_ * 3 + tl) * 7 + cib_) * 3584 + co0 * 16 + rem * 4; \
                cp_async16(dbase + (uint32_t)(tl * 7168 + rem * 16), src); \
            } \
        } \
        CP_COMMIT(); \
    } while (0)

    PREFETCH_GRP(0, 0);
    PREFETCH_GRP(1, 1);

    for (int s = 0; s < 63; s++) {
        int cib = s / 9, grp = s - cib * 9;
        int buf = s & 1;

        if (grp == 0) {
            // ---- stage patch for this ci-block (3z x 6y x 34x) ----
            int cig0 = cib * 32;
#pragma unroll 4
            for (int jj = 0; jj < 36; jj++) {
                int p = wid + jj * 8;        // 0..287
                int wword = p & 15;
                int rowid = p >> 4;          // 0..17 (3z x 6y)
                int pz = rowid / 6, py = rowid - pz * 6;
                int gz = z + pz - 1, gy = y0 + py - 1;
                bool rowok = ((unsigned)gz < 32u) && ((unsigned)gy < 32u);
                const float* s0 = in + (size_t)(cig0 + 2 * wword) * V + (gz << 10) + (gy << 5);
#pragma unroll
                for (int q = 0; q < 2; q++) {
                    int px = lane + q * 32;
                    if (px < 34) {
                        int gx = px - 1;
                        bool ok = rowok && ((unsigned)gx < 32u);
                        float v0 = ok ? __ldg(s0 + gx) : 0.f;
                        float v1 = ok ? __ldg(s0 + V + gx) : 0.f;
                        half2 h = __floats2half2_rn(v0, v1);
                        int voxel = rowid * 34 + px;
                        int st = (((wword >> 2) ^ ((voxel >> 1) & 3)) << 2) | (wword & 3);
                        P[voxel * 16 + st] = *(uint32_t*)&h;
                    }
                }
            }
        }

        CP_WAIT1();
        __syncthreads();      // B(buf) ready + patch visible

        // ---- compute 3 taps ----
#pragma unroll
        for (int t = 0; t < 3; t++) {
            int tap = grp * 3 + t;
            int dz = tap / 9, rem = tap - dz * 9;
            int dy = rem / 3, dx = rem - dy * 3;
            int vb = (dz * 6 + wm + dy) * 34 + dx;
            uint32_t Bbb = sbase + BBYTE + (uint32_t)buf * 21504u + (uint32_t)t * 7168u;

#pragma unroll
            for (int ks = 0; ks < 2; ks++) {
                uint32_t af[2][4];
#pragma unroll
                for (int mt = 0; mt < 2; mt++) {
                    int v = vb + a_lro + (mt << 4);
                    uint32_t ad = sbase + (uint32_t)(v << 6)
                                + (uint32_t)((((ks << 1) + a_sh) ^ ((v >> 1) & 3)) << 4);
                    ldsm_x4(af[mt], ad);
                }
                uint32_t bf[7][2];
#pragma unroll
                for (int t2 = 0; t2 < 3; t2++) {
                    uint32_t r[4];
                    uint32_t ad = Bbb + bco[t2] + (uint32_t)((((ks << 1) + b_segbit) ^ bsw[t2]) << 4);
                    ldsm_x4(r, ad);
                    bf[2 * t2][0] = r[0]; bf[2 * t2][1] = r[1];
                    bf[2 * t2 + 1][0] = r[2]; bf[2 * t2 + 1][1] = r[3];
                }
                {
                    uint32_t r2[2];
                    uint32_t ad = Bbb + bco[3] + (uint32_t)((((ks << 1) + b_segbit) ^ bsw[3]) << 4);
                    ldsm_x2(r2, ad);
                    bf[6][0] = r2[0]; bf[6][1] = r2[1];
                }
#pragma unroll
                for (int mt = 0; mt < 2; mt++)
#pragma unroll
                    for (int nt = 0; nt < 7; nt++)
                        mma_f16(acc[mt][nt], af[mt], bf[nt]);
            }
        }

        __syncthreads();      // all warps done reading B(buf) (+ patch if next step re-stages)
        if (s + 2 < 63) PREFETCH_GRP(s + 2, buf);
    }

    // ---- epilogue ----
    int yg = y0 + wm;
#pragma unroll
    for (int mt = 0; mt < 2; mt++) {
        int x1 = (mt << 4) + r4;
        int pos = (z << 10) + (yg << 5) + x1;
#pragma unroll
        for (int nt = 0; nt < 7; nt++) {
            int c = co0 + wn * 56 + (nt << 3) + (c4 << 1);
            if (c < CC) {
                float bb = bias[c];
                out[(size_t)c * V + pos] = acc[mt][nt][0] + bb;
                out[(size_t)c * V + pos + 8] = acc[mt][nt][2] + bb;
            }
            if (c + 1 < CC) {
                float bb = bias[c + 1];
                out[(size_t)(c + 1) * V + pos] = acc[mt][nt][1] + bb;
                out[(size_t)(c + 1) * V + pos + 8] = acc[mt][nt][3] + bb;
            }
        }
    }
}

// ======================= final 3-channel conv (fp32) =======================
__global__ void __launch_bounds__(256) conv_out_kernel(const float* __restrict__ in,
                                                       const float* __restrict__ w,
                                                       const float* __restrict__ bias,
                                                       float* __restrict__ out) {
    __shared__ float sp[816];
    __shared__ float sw[81];
    int tid = threadIdx.x;
    int z0 = (blockIdx.x >> 3) * 2;
    int y0 = (blockIdx.x & 7) * 4;
    int tz = tid >> 7, ty = (tid >> 5) & 3, tx = tid & 31;

    int poff[4]; bool pval[4];
#pragma unroll
    for (int k = 0; k < 4; k++) {
        int i = k * 256 + tid;
        int pz = i / 204, r = i % 204, py = r / 34, px = r % 34;
        int gz = z0 + pz - 1, gy = y0 + py - 1, gx = px - 1;
        pval[k] = (i < 816) && ((unsigned)gz < 32u) && ((unsigned)gy < 32u) && ((unsigned)gx < 32u);
        poff[k] = (gz << 10) + (gy << 5) + gx;
    }
    float acc[3] = {0.f, 0.f, 0.f};
    for (int ci = 0; ci < CC; ci++) {
        __syncthreads();
#pragma unroll
        for (int k = 0; k < 4; k++) {
            int i = k * 256 + tid;
            if (i < 816) sp[i] = pval[k] ? in[(size_t)ci * V + poff[k]] : 0.f;
        }
        if (tid < 81) sw[tid] = w[((size_t)(tid / 27) * CC + ci) * 27 + tid % 27];
        __syncthreads();
#pragma unroll
        for (int kz = 0; kz < 3; kz++)
#pragma unroll
            for (int ky = 0; ky < 3; ky++) {
                int base = ((tz + kz) * 6 + (ty + ky)) * 34 + tx;
                float v0 = sp[base], v1 = sp[base + 1], v2 = sp[base + 2];
#pragma unroll
                for (int kx = 0; kx < 3; kx++) {
                    int wt = (kz * 3 + ky) * 3 + kx;
                    float vv = (kx == 0) ? v0 : ((kx == 1) ? v1 : v2);
                    acc[0] += sw[wt] * vv;
                    acc[1] += sw[27 + wt] * vv;
                    acc[2] += sw[54 + wt] * vv;
                }
            }
    }
    int p = ((z0 + tz) << 10) + ((y0 + ty) << 5) + tx;
#pragma unroll
    for (int co = 0; co < 3; co++) out[(size_t)co * V + p] = acc[co] + bias[co];
}

// ======================= launch =======================
extern "C" void kernel_launch(void* const* d_in, const int* in_sizes, int n_in,
                              void* d_out, int out_size) {
    (void)in_sizes; (void)n_in; (void)out_size;
    const float* src   = (const float*)d_in[0];
    const float* tgt   = (const float*)d_in[1];
    const float* C     = (const float*)d_in[2];
    const float* up_w  = (const float*)d_in[3];
    const float* up_b  = (const float*)d_in[4];
    const float* c1_w  = (const float*)d_in[5];
    const float* c1_b  = (const float*)d_in[6];
    const float* c2_w  = (const float*)d_in[7];
    const float* c2_b  = (const float*)d_in[8];
    const float* out_w = (const float*)d_in[9];
    const float* out_b = (const float*)d_in[10];
    float* dout = (float*)d_out;

    float *gx = nullptr, *gy = nullptr;
    cudaGetSymbolAddress((void**)&gx, g_x);
    cudaGetSymbolAddress((void**)&gy, g_y);

    const int CONV_SMEM = 82176;   // (9792 + 2*5376) uint32 words
    cudaFuncSetAttribute(conv3_mma_kernel, cudaFuncAttributeMaxDynamicSharedMemorySize, CONV_SMEM);

    // Stage 1: build concat input (224 channels, pads zeroed)
    pad_zero_kernel<<<640, 256>>>();
    copy_kernel<<<2048, 256>>>(tgt, src);
    upsample_kernel<<<dim3(128, 4), 256>>>(C, up_w, up_b);
    corr_kernel<<<128, 256>>>(tgt, src);

    // IN + leaky on Cup (channels 155..218)
    stats_kernel<<<64, 256>>>(gx + (size_t)155 * V);
    norm_leaky_kernel<<<dim3(32, 64), 256>>>(gx + (size_t)155 * V);

    // conv1 (fp16 HMMA, 2 CTAs/SM) + IN + leaky
    reorder_w_kernel<<<2646, 256>>>(c1_w);
    conv3_mma_kernel<<<dim3(256, 2), 256, CONV_SMEM>>>(gx, c1_b, gy);
    stats_kernel<<<CC, 256>>>(gy);
    norm_leaky_kernel<<<dim3(32, CC), 256>>>(gy);

    // conv2 (fp16 HMMA, 2 CTAs/SM) + IN + leaky  -> Cn in d_out[0 .. 219*V)
    reorder_w_kernel<<<2646, 256>>>(c2_w);
    conv3_mma_kernel<<<dim3(256, 2), 256, CONV_SMEM>>>(gy, c2_b, dout);
    stats_kernel<<<CC, 256>>>(dout);
    norm_leaky_kernel<<<dim3(32, CC), 256>>>(dout);

    // output conv -> d_out[219*V .. 222*V)
    conv_out_kernel<<<128, 256>>>(dout, out_w, out_b, dout + (size_t)CC * V);
}

// round 12
// speedup vs baseline: 2.6035x; 1.0458x over previous
#include <cuda_runtime.h>
#include <cuda_fp16.h>
#include <cstdint>

#define V 32768            // 32*32*32
#define CC 219             // real channels
#define CP 224             // padded channels (multiple of 32)

__device__ float g_x[CP * V];              // concat input [tgt(64), src(64), cost(27), Cup(64), pad(5)=0]
__device__ float g_y[CP * V];              // conv1 output (padded)
__device__ uint32_t g_wh[27 * 7 * 3584];   // half2-packed pre-swizzled B (16B-granular swizzle)
__device__ float g_stats[CC * 2];          // per-channel (mean, rstd)

__device__ __forceinline__ uint32_t smem_u32(const void* p) {
    uint32_t a;
    asm("{ .reg .u64 t; cvta.to.shared.u64 t, %1; cvt.u32.u64 %0, t; }" : "=r"(a) : "l"(p));
    return a;
}
__device__ __forceinline__ void cp_async16(uint32_t dst, const void* src) {
    asm volatile("cp.async.cg.shared.global [%0], [%1], 16;" :: "r"(dst), "l"(src));
}
#define CP_COMMIT() asm volatile("cp.async.commit_group;" ::: "memory")
#define CP_WAIT1()  asm volatile("cp.async.wait_group 1;" ::: "memory")

__device__ __forceinline__ void mma_f16(float d[4], const uint32_t a[4], const uint32_t b[2]) {
    asm volatile(
        "mma.sync.aligned.m16n8k16.row.col.f32.f16.f16.f32 "
        "{%0,%1,%2,%3}, {%4,%5,%6,%7}, {%8,%9}, {%0,%1,%2,%3};"
        : "+f"(d[0]), "+f"(d[1]), "+f"(d[2]), "+f"(d[3])
        : "r"(a[0]), "r"(a[1]), "r"(a[2]), "r"(a[3]), "r"(b[0]), "r"(b[1]));
}
__device__ __forceinline__ void ldsm_x4(uint32_t r[4], uint32_t addr) {
    asm volatile("ldmatrix.sync.aligned.m8n8.x4.shared.b16 {%0,%1,%2,%3}, [%4];"
                 : "=r"(r[0]), "=r"(r[1]), "=r"(r[2]), "=r"(r[3]) : "r"(addr));
}
__device__ __forceinline__ void ldsm_x2(uint32_t r[2], uint32_t addr) {
    asm volatile("ldmatrix.sync.aligned.m8n8.x2.shared.b16 {%0,%1}, [%2];"
                 : "=r"(r[0]), "=r"(r[1]) : "r"(addr));
}

// ======================= small kernels =======================
__global__ void pad_zero_kernel() {
    int i = blockIdx.x * 256 + threadIdx.x;      // over 5*V
    g_x[(size_t)CC * V + i] = 0.f;
    g_y[(size_t)CC * V + i] = 0.f;
}

__global__ void copy_kernel(const float* __restrict__ tgt, const float* __restrict__ src) {
    int i = blockIdx.x * 256 + threadIdx.x;   // over 64*V/4 float4
    float4* dx = (float4*)g_x;
    dx[i] = ((const float4*)tgt)[i];
    dx[(64 * V) / 4 + i] = ((const float4*)src)[i];
}

// weight reorder: half2 pack + 16B-granular swizzle.
__global__ void reorder_w_kernel(const float* __restrict__ w) {
    int id = blockIdx.x * 256 + threadIdx.x;     // < 27*7*3584 = 677376
    if (id >= 27 * 7 * 3584) return;
    int blob = id / 3584, r = id % 3584;
    int tap = blob / 7, cib = blob % 7;
    int co = r >> 4, jj = r & 15;
    int wlog = (((jj >> 2) ^ ((co >> 1) & 3)) << 2) | (jj & 3);
    int ci0 = cib * 32 + 2 * wlog;
    float v0 = 0.f, v1 = 0.f;
    if (co < CC) {
        if (ci0 < CC)     v0 = w[((size_t)co * CC + ci0) * 27 + tap];
        if (ci0 + 1 < CC) v1 = w[((size_t)co * CC + ci0 + 1) * 27 + tap];
    }
    half2 h = __floats2half2_rn(v0, v1);
    g_wh[id] = *(uint32_t*)&h;
}

// ======================= correlation volume (2 channels / iteration) =======================
__global__ void __launch_bounds__(256) corr_kernel(const float* __restrict__ tgt,
                                                   const float* __restrict__ src) {
    __shared__ float sp[1632];   // 2 x (4*6*34) patches
    int tid = threadIdx.x;
    int z0 = (blockIdx.x >> 3) * 2;
    int y0 = (blockIdx.x & 7) * 4;
    int tz = tid >> 7, ty = (tid >> 5) & 3, tx = tid & 31;
    int z = z0 + tz, y = y0 + ty;
    int p = (z << 10) + (y << 5) + tx;

    int poff[7]; bool pval[7]; int phalf[7];
#pragma unroll
    for (int k = 0; k < 7; k++) {
        int i = k * 256 + tid;
        int half = i / 816;
        int j = i - half * 816;
        int pz = j / 204, r = j % 204, py = r / 34, px = r % 34;
        int gz = z0 + pz - 1, gy = y0 + py - 1, gx = px - 1;
        pval[k] = (i < 1632) && ((unsigned)gz < 32u) && ((unsigned)gy < 32u) && ((unsigned)gx < 32u);
        poff[k] = (gz << 10) + (gy << 5) + gx;
        phalf[k] = half;
    }

    float acc[27];
#pragma unroll
    for (int d = 0; d < 27; d++) acc[d] = 0.f;

    for (int c = 0; c < 32; c++) {       // 32 iterations x 2 channels
        __syncthreads();
#pragma unroll
        for (int k = 0; k < 7; k++) {
            int i = k * 256 + tid;
            if (i < 1632) sp[i] = pval[k] ? src[(size_t)(2 * c + phalf[k]) * V + poff[k]] : 0.f;
        }
        __syncthreads();
        float t0 = tgt[(size_t)(2 * c) * V + p];
        float t1 = tgt[(size_t)(2 * c + 1) * V + p];
#pragma unroll
        for (int dz = 0; dz < 3; dz++)
#pragma unroll
            for (int dy = 0; dy < 3; dy++) {
                int base = ((tz + dz) * 6 + (ty + dy)) * 34 + tx;
#pragma unroll
                for (int q = 0; q < 3; q++)
                    acc[dz * 9 + dy * 3 + q] += t0 * sp[base + q] + t1 * sp[816 + base + q];
            }
    }
    const float inv = 1.f / 64.f;
#pragma unroll
    for (int d = 0; d < 27; d++) g_x[(size_t)(128 + d) * V + p] = acc[d] * inv;
}

// ======================= conv transpose upsample (fp32, proven) =======================
__global__ void __launch_bounds__(256) upsample_kernel(const float* __restrict__ Cin,
                                                       const float* __restrict__ w,
                                                       const float* __restrict__ bias) {
    __shared__ float swt[16 * 64];
    __shared__ float spatch[3 * 4 * 18];
    int tid = threadIdx.x;
    int z0 = (blockIdx.x >> 3) * 2;
    int y0 = (blockIdx.x & 7) * 4;
    int co0 = blockIdx.y * 16;
    int tz = tid >> 7, ty = (tid >> 5) & 3, tx = tid & 31;
    int oz = z0 + tz, oy = y0 + ty, ox = tx;
    int izb = (z0 >> 1) - 1, iyb = (y0 >> 1) - 1;

    int taps[8]; int nt = 0;
    for (int kz = (oz + 1) & 1; kz < 4; kz += 2) {
        int iz = (oz + 1 - kz) >> 1; if (iz < 0 || iz >= 16) continue;
        for (int ky = (oy + 1) & 1; ky < 4; ky += 2) {
            int iy = (oy + 1 - ky) >> 1; if (iy < 0 || iy >= 16) continue;
            for (int kx = (ox + 1) & 1; kx < 4; kx += 2) {
                int ix = (ox + 1 - kx) >> 1; if (ix < 0 || ix >= 16) continue;
                int pofs = ((iz - izb) * 4 + (iy - iyb)) * 18 + (ix + 1);
                int wofs = (kz << 4) + (ky << 2) + kx;
                taps[nt++] = pofs | (wofs << 16);
            }
        }
    }
    int pl_off = 0; bool pl_val = false;
    if (tid < 216) {
        int pz = tid / 72, r = tid % 72, py = r / 18, px = r % 18;
        int gz = izb + pz, gy = iyb + py, gx = px - 1;
        pl_val = ((unsigned)gz < 16u) && ((unsigned)gy < 16u) && ((unsigned)gx < 16u);
        pl_off = (gz << 8) + (gy << 4) + gx;
    }
    float acc[16];
#pragma unroll
    for (int j = 0; j < 16; j++) acc[j] = 0.f;
    for (int ci = 0; ci < 411; ci++) {
        __syncthreads();
        if (tid < 216) spatch[tid] = pl_val ? Cin[ci * 4096 + pl_off] : 0.f;
        const float* wc = w + ((size_t)ci * 64 + co0) * 64;
#pragma unroll
        for (int k = 0; k < 4; k++) swt[k * 256 + tid] = wc[k * 256 + tid];
        __syncthreads();
        for (int t = 0; t < nt; t++) {
            int tp = taps[t];
            float v = spatch[tp & 0xffff];
            int wofs = tp >> 16;
#pragma unroll
            for (int j = 0; j < 16; j++) acc[j] += v * swt[(j << 6) + wofs];
        }
    }
    int p = (oz << 10) + (oy << 5) + ox;
#pragma unroll
    for (int j = 0; j < 16; j++)
        g_x[(size_t)(155 + co0 + j) * V + p] = acc[j] + bias[co0 + j];
}

// ======================= instance norm =======================
__global__ void stats_kernel(const float* __restrict__ x) {
    int ch = blockIdx.x;
    const float4* p4 = (const float4*)(x + (size_t)ch * V);
    float s = 0.f, s2 = 0.f;
    for (int i = threadIdx.x; i < V / 4; i += 256) {
        float4 v = p4[i];
        s += v.x + v.y + v.z + v.w;
        s2 += v.x * v.x + v.y * v.y + v.z * v.z + v.w * v.w;
    }
#pragma unroll
    for (int o = 16; o; o >>= 1) {
        s += __shfl_down_sync(0xffffffffu, s, o);
        s2 += __shfl_down_sync(0xffffffffu, s2, o);
    }
    __shared__ float a[8], b[8];
    int wp = threadIdx.x >> 5, ln = threadIdx.x & 31;
    if (ln == 0) { a[wp] = s; b[wp] = s2; }
    __syncthreads();
    if (threadIdx.x < 8) {
        s = a[threadIdx.x]; s2 = b[threadIdx.x];
#pragma unroll
        for (int o = 4; o; o >>= 1) {
            s += __shfl_down_sync(0xffu, s, o);
            s2 += __shfl_down_sync(0xffu, s2, o);
        }
        if (threadIdx.x == 0) {
            float m = s * (1.f / V);
            float var = s2 * (1.f / V) - m * m;
            g_stats[ch * 2] = m;
            g_stats[ch * 2 + 1] = rsqrtf(var + 1e-5f);
        }
    }
}

__global__ void norm_leaky_kernel(float* __restrict__ x) {
    int ch = blockIdx.y;
    int i = blockIdx.x * 256 + threadIdx.x;
    float m = g_stats[ch * 2], r = g_stats[ch * 2 + 1];
    float4* p = (float4*)(x + (size_t)ch * V);
    float4 v = p[i];
    v.x = (v.x - m) * r; v.x = v.x >= 0.f ? v.x : 0.1f * v.x;
    v.y = (v.y - m) * r; v.y = v.y >= 0.f ? v.y : 0.1f * v.y;
    v.z = (v.z - m) * r; v.z = v.z >= 0.f ? v.z : 0.1f * v.z;
    v.w = (v.w - m) * r; v.w = v.w >= 0.f ? v.w : 0.1f * v.w;
    p[i] = v;
}

// ======================= fp16 HMMA conv3x3x3: 2 CTAs/SM, cp.async 3-tap B groups ========
__global__ void __launch_bounds__(256, 2) conv3_mma_kernel(const float* __restrict__ in,
                                                           const float* __restrict__ bias,
                                                           float* __restrict__ out) {
    extern __shared__ uint32_t smem32[];
    uint32_t* P = smem32;                    // 9792 words
    uint32_t sbase = smem_u32(smem32);
    const uint32_t BBYTE = 9792u * 4u;       // byte offset of B buffers (2 x 21504 B)

    int tid = threadIdx.x, wid = tid >> 5, lane = tid & 31;
    int z = blockIdx.x >> 3, yt = blockIdx.x & 7;
    int y0 = yt * 4;
    int co0 = blockIdx.y * 112;

    int wm = wid >> 1, wn = wid & 1;         // wm = local y row
    int r4 = lane >> 2, c4 = lane & 3;

    int sub = lane >> 3, l7 = lane & 7;
    int a_lro = ((sub & 1) << 3) + l7;
    int a_sh = sub >> 1;
    int b_segbit = sub & 1;
    int b_ntoff = sub >> 1;
    uint32_t bco[4]; int bsw[4];
#pragma unroll
    for (int t = 0; t < 3; t++) {
        int co = wn * 56 + (2 * t + b_ntoff) * 8 + l7;
        bco[t] = (uint32_t)(co << 6);
        bsw[t] = (co >> 1) & 3;
    }
    {
        int co = wn * 56 + 48 + l7;
        bco[3] = (uint32_t)(co << 6);
        bsw[3] = (co >> 1) & 3;
    }

    float acc[2][7][4];
#pragma unroll
    for (int a = 0; a < 2; a++)
#pragma unroll
        for (int b = 0; b < 7; b++)
#pragma unroll
            for (int c = 0; c < 4; c++) acc[a][b][c] = 0.f;

#define PREFETCH_GRP(s_, buf_) do { \
        int cib_ = (s_) / 9, grp_ = (s_) % 9; \
        uint32_t dbase = sbase + BBYTE + (uint32_t)(buf_) * 21504u; \
        _Pragma("unroll") \
        for (int it = 0; it < 6; it++) { \
            int i = tid + it * 256; \
            if (i < 1344) { \
                int tl = i / 448, rem = i - tl * 448; \
                const uint32_t* src = g_wh + (size_t)((grp_ * 3 + tl) * 7 + cib_) * 3584 + co0 * 16 + rem * 4; \
                cp_async16(dbase + (uint32_t)(tl * 7168 + rem * 16), src); \
            } \
        } \
        CP_COMMIT(); \
    } while (0)

    PREFETCH_GRP(0, 0);
    PREFETCH_GRP(1, 1);

    for (int s = 0; s < 63; s++) {
        int cib = s / 9, grp = s - cib * 9;
        int buf = s & 1;

        if (grp == 0) {
            int cig0 = cib * 32;
#pragma unroll 4
            for (int jj = 0; jj < 36; jj++) {
                int p = wid + jj * 8;        // 0..287
                int wword = p & 15;
                int rowid = p >> 4;          // 0..17 (3z x 6y)
                int pz = rowid / 6, py = rowid - pz * 6;
                int gz = z + pz - 1, gy = y0 + py - 1;
                bool rowok = ((unsigned)gz < 32u) && ((unsigned)gy < 32u);
                const float* s0 = in + (size_t)(cig0 + 2 * wword) * V + (gz << 10) + (gy << 5);
#pragma unroll
                for (int q = 0; q < 2; q++) {
                    int px = lane + q * 32;
                    if (px < 34) {
                        int gx = px - 1;
                        bool ok = rowok && ((unsigned)gx < 32u);
                        float v0 = ok ? __ldg(s0 + gx) : 0.f;
                        float v1 = ok ? __ldg(s0 + V + gx) : 0.f;
                        half2 h = __floats2half2_rn(v0, v1);
                        int voxel = rowid * 34 + px;
                        int st = (((wword >> 2) ^ ((voxel >> 1) & 3)) << 2) | (wword & 3);
                        P[voxel * 16 + st] = *(uint32_t*)&h;
                    }
                }
            }
        }

        CP_WAIT1();
        __syncthreads();      // B(buf) ready + patch visible

#pragma unroll
        for (int t = 0; t < 3; t++) {
            int tap = grp * 3 + t;
            int dz = tap / 9, rem = tap - dz * 9;
            int dy = rem / 3, dx = rem - dy * 3;
            int vb = (dz * 6 + wm + dy) * 34 + dx;
            uint32_t Bbb = sbase + BBYTE + (uint32_t)buf * 21504u + (uint32_t)t * 7168u;

#pragma unroll
            for (int ks = 0; ks < 2; ks++) {
                uint32_t af[2][4];
#pragma unroll
                for (int mt = 0; mt < 2; mt++) {
                    int v = vb + a_lro + (mt << 4);
                    uint32_t ad = sbase + (uint32_t)(v << 6)
                                + (uint32_t)((((ks << 1) + a_sh) ^ ((v >> 1) & 3)) << 4);
                    ldsm_x4(af[mt], ad);
                }
                uint32_t bf[7][2];
#pragma unroll
                for (int t2 = 0; t2 < 3; t2++) {
                    uint32_t r[4];
                    uint32_t ad = Bbb + bco[t2] + (uint32_t)((((ks << 1) + b_segbit) ^ bsw[t2]) << 4);
                    ldsm_x4(r, ad);
                    bf[2 * t2][0] = r[0]; bf[2 * t2][1] = r[1];
                    bf[2 * t2 + 1][0] = r[2]; bf[2 * t2 + 1][1] = r[3];
                }
                {
                    uint32_t r2[2];
                    uint32_t ad = Bbb + bco[3] + (uint32_t)((((ks << 1) + b_segbit) ^ bsw[3]) << 4);
                    ldsm_x2(r2, ad);
                    bf[6][0] = r2[0]; bf[6][1] = r2[1];
                }
#pragma unroll
                for (int mt = 0; mt < 2; mt++)
#pragma unroll
                    for (int nt = 0; nt < 7; nt++)
                        mma_f16(acc[mt][nt], af[mt], bf[nt]);
            }
        }

        __syncthreads();
        if (s + 2 < 63) PREFETCH_GRP(s + 2, buf);
    }

    // ---- epilogue ----
    int yg = y0 + wm;
#pragma unroll
    for (int mt = 0; mt < 2; mt++) {
        int x1 = (mt << 4) + r4;
        int pos = (z << 10) + (yg << 5) + x1;
#pragma unroll
        for (int nt = 0; nt < 7; nt++) {
            int c = co0 + wn * 56 + (nt << 3) + (c4 << 1);
            if (c < CC) {
                float bb = bias[c];
                out[(size_t)c * V + pos] = acc[mt][nt][0] + bb;
                out[(size_t)c * V + pos + 8] = acc[mt][nt][2] + bb;
            }
            if (c + 1 < CC) {
                float bb = bias[c + 1];
                out[(size_t)(c + 1) * V + pos] = acc[mt][nt][1] + bb;
                out[(size_t)(c + 1) * V + pos + 8] = acc[mt][nt][3] + bb;
            }
        }
    }
}

// ======================= final 3-channel conv (fp32, 2 channels / iteration) =======================
__global__ void __launch_bounds__(256) conv_out_kernel(const float* __restrict__ in,
                                                       const float* __restrict__ w,
                                                       const float* __restrict__ bias,
                                                       float* __restrict__ out) {
    __shared__ float sp[1632];   // 2 x (4*6*34)
    __shared__ float sw[162];    // 2 x (3 co x 27)
    int tid = threadIdx.x;
    int z0 = (blockIdx.x >> 3) * 2;
    int y0 = (blockIdx.x & 7) * 4;
    int tz = tid >> 7, ty = (tid >> 5) & 3, tx = tid & 31;

    int poff[7]; bool pval[7]; int phalf[7];
#pragma unroll
    for (int k = 0; k < 7; k++) {
        int i = k * 256 + tid;
        int half = i / 816;
        int j = i - half * 816;
        int pz = j / 204, r = j % 204, py = r / 34, px = r % 34;
        int gz = z0 + pz - 1, gy = y0 + py - 1, gx = px - 1;
        pval[k] = (i < 1632) && ((unsigned)gz < 32u) && ((unsigned)gy < 32u) && ((unsigned)gx < 32u);
        poff[k] = (gz << 10) + (gy << 5) + gx;
        phalf[k] = half;
    }

    float acc[3] = {0.f, 0.f, 0.f};
    for (int c = 0; c < 110; c++) {            // pairs (2c, 2c+1), ci=219 padded to 0
        __syncthreads();
#pragma unroll
        for (int k = 0; k < 7; k++) {
            int i = k * 256 + tid;
            if (i < 1632) {
                int ch = 2 * c + phalf[k];
                sp[i] = (pval[k] && ch < CC) ? in[(size_t)ch * V + poff[k]] : 0.f;
            }
        }
        if (tid < 162) {
            int half = tid / 81;
            int t = tid - half * 81;
            int ch = 2 * c + half;
            sw[tid] = (ch < CC) ? w[((size_t)(t / 27) * CC + ch) * 27 + (t % 27)] : 0.f;
        }
        __syncthreads();
#pragma unroll
        for (int kz = 0; kz < 3; kz++)
#pragma unroll
            for (int ky = 0; ky < 3; ky++) {
                int base = ((tz + kz) * 6 + (ty + ky)) * 34 + tx;
#pragma unroll
                for (int kx = 0; kx < 3; kx++) {
                    int wt = (kz * 3 + ky) * 3 + kx;
                    float ve = sp[base + kx];
                    float vo = sp[816 + base + kx];
#pragma unroll
                    for (int co = 0; co < 3; co++)
                        acc[co] += sw[co * 27 + wt] * ve + sw[81 + co * 27 + wt] * vo;
                }
            }
    }
    int p = ((z0 + tz) << 10) + ((y0 + ty) << 5) + tx;
#pragma unroll
    for (int co = 0; co < 3; co++) out[(size_t)co * V + p] = acc[co] + bias[co];
}

// ======================= launch =======================
extern "C" void kernel_launch(void* const* d_in, const int* in_sizes, int n_in,
                              void* d_out, int out_size) {
    (void)in_sizes; (void)n_in; (void)out_size;
    const float* src   = (const float*)d_in[0];
    const float* tgt   = (const float*)d_in[1];
    const float* C     = (const float*)d_in[2];
    const float* up_w  = (const float*)d_in[3];
    const float* up_b  = (const float*)d_in[4];
    const float* c1_w  = (const float*)d_in[5];
    const float* c1_b  = (const float*)d_in[6];
    const float* c2_w  = (const float*)d_in[7];
    const float* c2_b  = (const float*)d_in[8];
    const float* out_w = (const float*)d_in[9];
    const float* out_b = (const float*)d_in[10];
    float* dout = (float*)d_out;

    float *gx = nullptr, *gy = nullptr;
    cudaGetSymbolAddress((void**)&gx, g_x);
    cudaGetSymbolAddress((void**)&gy, g_y);

    const int CONV_SMEM = 82176;   // (9792 + 2*5376) uint32 words
    cudaFuncSetAttribute(conv3_mma_kernel, cudaFuncAttributeMaxDynamicSharedMemorySize, CONV_SMEM);

    // Stage 1: build concat input (224 channels, pads zeroed)
    pad_zero_kernel<<<640, 256>>>();
    copy_kernel<<<2048, 256>>>(tgt, src);
    upsample_kernel<<<dim3(128, 4), 256>>>(C, up_w, up_b);
    corr_kernel<<<128, 256>>>(tgt, src);

    // IN + leaky on Cup (channels 155..218)
    stats_kernel<<<64, 256>>>(gx + (size_t)155 * V);
    norm_leaky_kernel<<<dim3(32, 64), 256>>>(gx + (size_t)155 * V);

    // conv1 (fp16 HMMA, 2 CTAs/SM) + IN + leaky
    reorder_w_kernel<<<2646, 256>>>(c1_w);
    conv3_mma_kernel<<<dim3(256, 2), 256, CONV_SMEM>>>(gx, c1_b, gy);
    stats_kernel<<<CC, 256>>>(gy);
    norm_leaky_kernel<<<dim3(32, CC), 256>>>(gy);

    // conv2 (fp16 HMMA, 2 CTAs/SM) + IN + leaky  -> Cn in d_out[0 .. 219*V)
    reorder_w_kernel<<<2646, 256>>>(c2_w);
    conv3_mma_kernel<<<dim3(256, 2), 256, CONV_SMEM>>>(gy, c2_b, dout);
    stats_kernel<<<CC, 256>>>(dout);
    norm_leaky_kernel<<<dim3(32, CC), 256>>>(dout);

    // output conv -> d_out[219*V .. 222*V)
    conv_out_kernel<<<128, 256>>>(dout, out_w, out_b, dout + (size_t)CC * V);
}

// round 13
// speedup vs baseline: 5.2887x; 2.0314x over previous
#include <cuda_runtime.h>
#include <cuda_fp16.h>
#include <cstdint>

#define V 32768            // 32*32*32
#define CC 219             // real channels
#define CP 224             // padded channels (multiple of 32)

__device__ float g_x[CP * V];              // concat input [tgt(64), src(64), cost(27), Cup(64), pad(5)=0]
__device__ float g_y[CP * V];              // conv1 output (padded)
__device__ uint32_t g_wh[27 * 7 * 3584];   // conv weights half2-packed, 16B-seg swizzle
__device__ uint32_t g_wu[8 * 13 * 8 * 1024]; // upsample weights per parity: [p][cib][tap][co64][16w]
__device__ float g_stats[CC * 2];          // per-channel (mean, rstd)

__device__ __forceinline__ uint32_t smem_u32(const void* p) {
    uint32_t a;
    asm("{ .reg .u64 t; cvta.to.shared.u64 t, %1; cvt.u32.u64 %0, t; }" : "=r"(a) : "l"(p));
    return a;
}
__device__ __forceinline__ void cp_async16(uint32_t dst, const void* src) {
    asm volatile("cp.async.cg.shared.global [%0], [%1], 16;" :: "r"(dst), "l"(src));
}
#define CP_COMMIT() asm volatile("cp.async.commit_group;" ::: "memory")
#define CP_WAIT1()  asm volatile("cp.async.wait_group 1;" ::: "memory")

__device__ __forceinline__ void mma_f16(float d[4], const uint32_t a[4], const uint32_t b[2]) {
    asm volatile(
        "mma.sync.aligned.m16n8k16.row.col.f32.f16.f16.f32 "
        "{%0,%1,%2,%3}, {%4,%5,%6,%7}, {%8,%9}, {%0,%1,%2,%3};"
        : "+f"(d[0]), "+f"(d[1]), "+f"(d[2]), "+f"(d[3])
        : "r"(a[0]), "r"(a[1]), "r"(a[2]), "r"(a[3]), "r"(b[0]), "r"(b[1]));
}
__device__ __forceinline__ void ldsm_x4(uint32_t r[4], uint32_t addr) {
    asm volatile("ldmatrix.sync.aligned.m8n8.x4.shared.b16 {%0,%1,%2,%3}, [%4];"
                 : "=r"(r[0]), "=r"(r[1]), "=r"(r[2]), "=r"(r[3]) : "r"(addr));
}
__device__ __forceinline__ void ldsm_x2(uint32_t r[2], uint32_t addr) {
    asm volatile("ldmatrix.sync.aligned.m8n8.x2.shared.b16 {%0,%1}, [%2];"
                 : "=r"(r[0]), "=r"(r[1]) : "r"(addr));
}

// ======================= small kernels =======================
__global__ void pad_zero_kernel() {
    int i = blockIdx.x * 256 + threadIdx.x;      // over 5*V
    g_x[(size_t)CC * V + i] = 0.f;
    g_y[(size_t)CC * V + i] = 0.f;
}

__global__ void copy_kernel(const float* __restrict__ tgt, const float* __restrict__ src) {
    int i = blockIdx.x * 256 + threadIdx.x;   // over 64*V/4 float4
    float4* dx = (float4*)g_x;
    dx[i] = ((const float4*)tgt)[i];
    dx[(64 * V) / 4 + i] = ((const float4*)src)[i];
}

// conv weight reorder: half2 pack + 16B-granular swizzle.
__global__ void reorder_w_kernel(const float* __restrict__ w) {
    int id = blockIdx.x * 256 + threadIdx.x;     // < 27*7*3584 = 677376
    if (id >= 27 * 7 * 3584) return;
    int blob = id / 3584, r = id % 3584;
    int tap = blob / 7, cib = blob % 7;
    int co = r >> 4, jj = r & 15;
    int wlog = (((jj >> 2) ^ ((co >> 1) & 3)) << 2) | (jj & 3);
    int ci0 = cib * 32 + 2 * wlog;
    float v0 = 0.f, v1 = 0.f;
    if (co < CC) {
        if (ci0 < CC)     v0 = w[((size_t)co * CC + ci0) * 27 + tap];
        if (ci0 + 1 < CC) v1 = w[((size_t)co * CC + ci0 + 1) * 27 + tap];
    }
    half2 h = __floats2half2_rn(v0, v1);
    g_wh[id] = *(uint32_t*)&h;
}

// upsample weight reorder: per parity class p, tap t -> (kz,ky,kx) of the 4x4x4 kernel.
// id = (((p*13 + cib)*8 + tap)*64 + co)*16 + jj
__global__ void reorder_wu_kernel(const float* __restrict__ w) {
    int id = blockIdx.x * 256 + threadIdx.x;     // < 851968
    if (id >= 8 * 13 * 8 * 1024) return;
    int jj = id & 15;
    int t = id >> 4;
    int co = t & 63; t >>= 6;
    int tap = t & 7; t >>= 3;
    int cib = t % 13;
    int p = t / 13;
    int pz = p >> 2, py = (p >> 1) & 1, px = p & 1;
    int tz = tap >> 2, ty = (tap >> 1) & 1, tx = tap & 1;
    int kz = (1 - pz) + 2 * tz;
    int ky = (1 - py) + 2 * ty;
    int kx = (1 - px) + 2 * tx;
    int wlog = (((jj >> 2) ^ ((co >> 1) & 3)) << 2) | (jj & 3);
    int ci0 = cib * 32 + 2 * wlog;
    float v0 = 0.f, v1 = 0.f;
    if (ci0 < 411)     v0 = w[((size_t)ci0 * 64 + co) * 64 + kz * 16 + ky * 4 + kx];
    if (ci0 + 1 < 411) v1 = w[((size_t)(ci0 + 1) * 64 + co) * 64 + kz * 16 + ky * 4 + kx];
    half2 h = __floats2half2_rn(v0, v1);
    g_wu[id] = *(uint32_t*)&h;
}

// ======================= correlation volume (2 channels / iteration) =======================
__global__ void __launch_bounds__(256) corr_kernel(const float* __restrict__ tgt,
                                                   const float* __restrict__ src) {
    __shared__ float sp[1632];   // 2 x (4*6*34) patches
    int tid = threadIdx.x;
    int z0 = (blockIdx.x >> 3) * 2;
    int y0 = (blockIdx.x & 7) * 4;
    int tz = tid >> 7, ty = (tid >> 5) & 3, tx = tid & 31;
    int z = z0 + tz, y = y0 + ty;
    int p = (z << 10) + (y << 5) + tx;

    int poff[7]; bool pval[7]; int phalf[7];
#pragma unroll
    for (int k = 0; k < 7; k++) {
        int i = k * 256 + tid;
        int half = i / 816;
        int j = i - half * 816;
        int pz = j / 204, r = j % 204, py = r / 34, px = r % 34;
        int gz = z0 + pz - 1, gy = y0 + py - 1, gx = px - 1;
        pval[k] = (i < 1632) && ((unsigned)gz < 32u) && ((unsigned)gy < 32u) && ((unsigned)gx < 32u);
        poff[k] = (gz << 10) + (gy << 5) + gx;
        phalf[k] = half;
    }

    float acc[27];
#pragma unroll
    for (int d = 0; d < 27; d++) acc[d] = 0.f;

    for (int c = 0; c < 32; c++) {       // 32 iterations x 2 channels
        __syncthreads();
#pragma unroll
        for (int k = 0; k < 7; k++) {
            int i = k * 256 + tid;
            if (i < 1632) sp[i] = pval[k] ? src[(size_t)(2 * c + phalf[k]) * V + poff[k]] : 0.f;
        }
        __syncthreads();
        float t0 = tgt[(size_t)(2 * c) * V + p];
        float t1 = tgt[(size_t)(2 * c + 1) * V + p];
#pragma unroll
        for (int dz = 0; dz < 3; dz++)
#pragma unroll
            for (int dy = 0; dy < 3; dy++) {
                int base = ((tz + dz) * 6 + (ty + dy)) * 34 + tx;
#pragma unroll
                for (int q = 0; q < 3; q++)
                    acc[dz * 9 + dy * 3 + q] += t0 * sp[base + q] + t1 * sp[816 + base + q];
            }
    }
    const float inv = 1.f / 64.f;
#pragma unroll
    for (int d = 0; d < 27; d++) g_x[(size_t)(128 + d) * V + p] = acc[d] * inv;
}

// ======================= upsample as fp16 implicit GEMM =======================
// Per CTA: parity class p (of 8), a-slice, half the (b,c) plane: M=128 (8b x 16c), N=64 co.
// K: 13 ci-blocks x 8 taps. Patch: 2iz x 9iy x 17ix voxel-rows x 32 ci (306 rows x 16 words).
// B: 2 buffers x 8 taps x 1024 words via cp.async. Dyn SMEM = 19584 + 65536 = 85120 B.
// Writes RAW Cup (no bias; IN cancels bias exactly) to g_x channels 155..218.
__global__ void __launch_bounds__(256, 2) upsample_mma_kernel(const float* __restrict__ Cin) {
    extern __shared__ uint32_t smem32[];
    uint32_t* P = smem32;                    // 4896 words
    uint32_t sbase = smem_u32(smem32);
    const uint32_t PBYTE = 19584u;

    int tid = threadIdx.x, wid = tid >> 5, lane = tid & 31;
    int a = blockIdx.x >> 1, b0 = (blockIdx.x & 1) * 8;
    int par = blockIdx.y;
    int pz = par >> 2, py = (par >> 1) & 1, px = par & 1;

    int wm = wid >> 1, wn = wid & 1;
    int r4 = lane >> 2, c4 = lane & 3;
    int sub = lane >> 3, l7 = lane & 7;
    int a_lro = ((sub & 1) << 3) + l7;
    int a_sh = sub >> 1;
    int b_segbit = sub & 1;
    int b_ntoff = sub >> 1;
    uint32_t bco[2]; int bsw[2];
#pragma unroll
    for (int t2 = 0; t2 < 2; t2++) {
        int co = wn * 32 + (2 * t2 + b_ntoff) * 8 + l7;
        bco[t2] = (uint32_t)(co << 6);
        bsw[t2] = (co >> 1) & 3;
    }

    float acc[2][4][4];
#pragma unroll
    for (int i = 0; i < 2; i++)
#pragma unroll
        for (int j = 0; j < 4; j++)
#pragma unroll
            for (int k = 0; k < 4; k++) acc[i][j][k] = 0.f;

#define PREFETCH_U(s_, buf_) do { \
        int cib_ = (s_); \
        uint32_t dbase = sbase + PBYTE + (uint32_t)(buf_) * 32768u; \
        _Pragma("unroll") \
        for (int it = 0; it < 8; it++) { \
            int i = tid + it * 256; \
            int tl = i >> 8, rem = i & 255; \
            const uint32_t* src = g_wu + ((size_t)((par * 13 + cib_) * 8 + tl) << 10) + rem * 4; \
            cp_async16(dbase + (uint32_t)((tl << 12) + (rem << 4)), src); \
        } \
        CP_COMMIT(); \
    } while (0)

    PREFETCH_U(0, 0);
    PREFETCH_U(1, 1);

    for (int s = 0; s < 13; s++) {
        int buf = s & 1;
        // ---- stage patch for ci-block s ----
        {
            int cig0 = s * 32;
#pragma unroll 4
            for (int jj = 0; jj < 36; jj++) {
                int pp = wid + jj * 8;           // 0..287
                int wword = pp & 15;
                int rowslot = pp >> 4;           // 0..17
                int slot = rowslot / 9, ry = rowslot - slot * 9;
                int iz = a + pz - 1 + slot;
                int iy = b0 + py - 1 + ry;
                bool rowok = ((unsigned)iz < 16u) && ((unsigned)iy < 16u);
                int c0 = cig0 + 2 * wword;
                const float* s0 = Cin + (size_t)c0 * 4096 + (iz << 8) + (iy << 4);
                if (lane < 17) {
                    int ix = px - 1 + lane;
                    bool ok = rowok && ((unsigned)ix < 16u);
                    float v0 = (ok && c0 < 411) ? __ldg(s0 + ix) : 0.f;
                    float v1 = (ok && c0 + 1 < 411) ? __ldg(s0 + 4096 + ix) : 0.f;
                    half2 h = __floats2half2_rn(v0, v1);
                    int row = slot * 153 + ry * 17 + lane;
                    int st = (((wword >> 2) ^ ((row >> 1) & 3)) << 2) | (wword & 3);
                    P[row * 16 + st] = *(uint32_t*)&h;
                }
            }
        }
        CP_WAIT1();
        __syncthreads();

#pragma unroll
        for (int tap = 0; tap < 8; tap++) {
            int tz = tap >> 2, ty = (tap >> 1) & 1, tx = tap & 1;
            int vb0 = (1 - tz) * 153 + (2 * wm + 1 - ty) * 17 + (1 - tx);
            uint32_t Bbb = sbase + PBYTE + (uint32_t)buf * 32768u + (uint32_t)tap * 4096u;

#pragma unroll
            for (int ks = 0; ks < 2; ks++) {
                uint32_t af[2][4];
#pragma unroll
                for (int mt = 0; mt < 2; mt++) {
                    int v = vb0 + mt * 17 + a_lro;
                    uint32_t ad = sbase + (uint32_t)(v << 6)
                                + (uint32_t)((((ks << 1) + a_sh) ^ ((v >> 1) & 3)) << 4);
                    ldsm_x4(af[mt], ad);
                }
                uint32_t bf[4][2];
#pragma unroll
                for (int t2 = 0; t2 < 2; t2++) {
                    uint32_t r[4];
                    uint32_t ad = Bbb + bco[t2] + (uint32_t)((((ks << 1) + b_segbit) ^ bsw[t2]) << 4);
                    ldsm_x4(r, ad);
                    bf[2 * t2][0] = r[0]; bf[2 * t2][1] = r[1];
                    bf[2 * t2 + 1][0] = r[2]; bf[2 * t2 + 1][1] = r[3];
                }
#pragma unroll
                for (int mt = 0; mt < 2; mt++)
#pragma unroll
                    for (int nt = 0; nt < 4; nt++)
                        mma_f16(acc[mt][nt], af[mt], bf[nt]);
            }
        }
        __syncthreads();
        if (s + 2 < 13) PREFETCH_U(s + 2, buf);
    }

    // ---- epilogue: scatter raw Cup to g_x channels 155.. ----
    int oz = 2 * a + pz;
#pragma unroll
    for (int mt = 0; mt < 2; mt++) {
        int bl = 2 * wm + mt;
        int oy = 2 * (b0 + bl) + py;
        int base = (oz << 10) + (oy << 5) + px;
#pragma unroll
        for (int nt = 0; nt < 4; nt++) {
            int co = wn * 32 + (nt << 3) + (c4 << 1);
            size_t ch0 = (size_t)(155 + co) * V;
            size_t ch1 = (size_t)(156 + co) * V;
            int o1 = base + 2 * r4, o2 = base + 2 * (r4 + 8);
            g_x[ch0 + o1] = acc[mt][nt][0];
            g_x[ch0 + o2] = acc[mt][nt][2];
            g_x[ch1 + o1] = acc[mt][nt][1];
            g_x[ch1 + o2] = acc[mt][nt][3];
        }
    }
}

// ======================= instance norm =======================
__global__ void stats_kernel(const float* __restrict__ x) {
    int ch = blockIdx.x;
    const float4* p4 = (const float4*)(x + (size_t)ch * V);
    float s = 0.f, s2 = 0.f;
    for (int i = threadIdx.x; i < V / 4; i += 256) {
        float4 v = p4[i];
        s += v.x + v.y + v.z + v.w;
        s2 += v.x * v.x + v.y * v.y + v.z * v.z + v.w * v.w;
    }
#pragma unroll
    for (int o = 16; o; o >>= 1) {
        s += __shfl_down_sync(0xffffffffu, s, o);
        s2 += __shfl_down_sync(0xffffffffu, s2, o);
    }
    __shared__ float a[8], b[8];
    int wp = threadIdx.x >> 5, ln = threadIdx.x & 31;
    if (ln == 0) { a[wp] = s; b[wp] = s2; }
    __syncthreads();
    if (threadIdx.x < 8) {
        s = a[threadIdx.x]; s2 = b[threadIdx.x];
#pragma unroll
        for (int o = 4; o; o >>= 1) {
            s += __shfl_down_sync(0xffu, s, o);
            s2 += __shfl_down_sync(0xffu, s2, o);
        }
        if (threadIdx.x == 0) {
            float m = s * (1.f / V);
            float var = s2 * (1.f / V) - m * m;
            g_stats[ch * 2] = m;
            g_stats[ch * 2 + 1] = rsqrtf(var + 1e-5f);
        }
    }
}

__global__ void norm_leaky_kernel(float* __restrict__ x) {
    int ch = blockIdx.y;
    int i = blockIdx.x * 256 + threadIdx.x;
    float m = g_stats[ch * 2], r = g_stats[ch * 2 + 1];
    float4* p = (float4*)(x + (size_t)ch * V);
    float4 v = p[i];
    v.x = (v.x - m) * r; v.x = v.x >= 0.f ? v.x : 0.1f * v.x;
    v.y = (v.y - m) * r; v.y = v.y >= 0.f ? v.y : 0.1f * v.y;
    v.z = (v.z - m) * r; v.z = v.z >= 0.f ? v.z : 0.1f * v.z;
    v.w = (v.w - m) * r; v.w = v.w >= 0.f ? v.w : 0.1f * v.w;
    p[i] = v;
}

// ======================= fp16 HMMA conv3x3x3: 2 CTAs/SM, cp.async 3-tap B groups ========
__global__ void __launch_bounds__(256, 2) conv3_mma_kernel(const float* __restrict__ in,
                                                           const float* __restrict__ bias,
                                                           float* __restrict__ out) {
    extern __shared__ uint32_t smem32[];
    uint32_t* P = smem32;                    // 9792 words
    uint32_t sbase = smem_u32(smem32);
    const uint32_t BBYTE = 9792u * 4u;       // byte offset of B buffers (2 x 21504 B)

    int tid = threadIdx.x, wid = tid >> 5, lane = tid & 31;
    int z = blockIdx.x >> 3, yt = blockIdx.x & 7;
    int y0 = yt * 4;
    int co0 = blockIdx.y * 112;

    int wm = wid >> 1, wn = wid & 1;         // wm = local y row
    int r4 = lane >> 2, c4 = lane & 3;

    int sub = lane >> 3, l7 = lane & 7;
    int a_lro = ((sub & 1) << 3) + l7;
    int a_sh = sub >> 1;
    int b_segbit = sub & 1;
    int b_ntoff = sub >> 1;
    uint32_t bco[4]; int bsw[4];
#pragma unroll
    for (int t = 0; t < 3; t++) {
        int co = wn * 56 + (2 * t + b_ntoff) * 8 + l7;
        bco[t] = (uint32_t)(co << 6);
        bsw[t] = (co >> 1) & 3;
    }
    {
        int co = wn * 56 + 48 + l7;
        bco[3] = (uint32_t)(co << 6);
        bsw[3] = (co >> 1) & 3;
    }

    float acc[2][7][4];
#pragma unroll
    for (int a = 0; a < 2; a++)
#pragma unroll
        for (int b = 0; b < 7; b++)
#pragma unroll
            for (int c = 0; c < 4; c++) acc[a][b][c] = 0.f;

#define PREFETCH_GRP(s_, buf_) do { \
        int cib_ = (s_) / 9, grp_ = (s_) % 9; \
        uint32_t dbase = sbase + BBYTE + (uint32_t)(buf_) * 21504u; \
        _Pragma("unroll") \
        for (int it = 0; it < 6; it++) { \
            int i = tid + it * 256; \
            if (i < 1344) { \
                int tl = i / 448, rem = i - tl * 448; \
                const uint32_t* src = g_wh + (size_t)((grp_ * 3 + tl) * 7 + cib_) * 3584 + co0 * 16 + rem * 4; \
                cp_async16(dbase + (uint32_t)(tl * 7168 + rem * 16), src); \
            } \
        } \
        CP_COMMIT(); \
    } while (0)

    PREFETCH_GRP(0, 0);
    PREFETCH_GRP(1, 1);

    for (int s = 0; s < 63; s++) {
        int cib = s / 9, grp = s - cib * 9;
        int buf = s & 1;

        if (grp == 0) {
            int cig0 = cib * 32;
#pragma unroll 4
            for (int jj = 0; jj < 36; jj++) {
                int p = wid + jj * 8;        // 0..287
                int wword = p & 15;
                int rowid = p >> 4;          // 0..17 (3z x 6y)
                int pz = rowid / 6, py = rowid - pz * 6;
                int gz = z + pz - 1, gy = y0 + py - 1;
                bool rowok = ((unsigned)gz < 32u) && ((unsigned)gy < 32u);
                const float* s0 = in + (size_t)(cig0 + 2 * wword) * V + (gz << 10) + (gy << 5);
#pragma unroll
                for (int q = 0; q < 2; q++) {
                    int px = lane + q * 32;
                    if (px < 34) {
                        int gx = px - 1;
                        bool ok = rowok && ((unsigned)gx < 32u);
                        float v0 = ok ? __ldg(s0 + gx) : 0.f;
                        float v1 = ok ? __ldg(s0 + V + gx) : 0.f;
                        half2 h = __floats2half2_rn(v0, v1);
                        int voxel = rowid * 34 + px;
                        int st = (((wword >> 2) ^ ((voxel >> 1) & 3)) << 2) | (wword & 3);
                        P[voxel * 16 + st] = *(uint32_t*)&h;
                    }
                }
            }
        }

        CP_WAIT1();
        __syncthreads();      // B(buf) ready + patch visible

#pragma unroll
        for (int t = 0; t < 3; t++) {
            int tap = grp * 3 + t;
            int dz = tap / 9, rem = tap - dz * 9;
            int dy = rem / 3, dx = rem - dy * 3;
            int vb = (dz * 6 + wm + dy) * 34 + dx;
            uint32_t Bbb = sbase + BBYTE + (uint32_t)buf * 21504u + (uint32_t)t * 7168u;

#pragma unroll
            for (int ks = 0; ks < 2; ks++) {
                uint32_t af[2][4];
#pragma unroll
                for (int mt = 0; mt < 2; mt++) {
                    int v = vb + a_lro + (mt << 4);
                    uint32_t ad = sbase + (uint32_t)(v << 6)
                                + (uint32_t)((((ks << 1) + a_sh) ^ ((v >> 1) & 3)) << 4);
                    ldsm_x4(af[mt], ad);
                }
                uint32_t bf[7][2];
#pragma unroll
                for (int t2 = 0; t2 < 3; t2++) {
                    uint32_t r[4];
                    uint32_t ad = Bbb + bco[t2] + (uint32_t)((((ks << 1) + b_segbit) ^ bsw[t2]) << 4);
                    ldsm_x4(r, ad);
                    bf[2 * t2][0] = r[0]; bf[2 * t2][1] = r[1];
                    bf[2 * t2 + 1][0] = r[2]; bf[2 * t2 + 1][1] = r[3];
                }
                {
                    uint32_t r2[2];
                    uint32_t ad = Bbb + bco[3] + (uint32_t)((((ks << 1) + b_segbit) ^ bsw[3]) << 4);
                    ldsm_x2(r2, ad);
                    bf[6][0] = r2[0]; bf[6][1] = r2[1];
                }
#pragma unroll
                for (int mt = 0; mt < 2; mt++)
#pragma unroll
                    for (int nt = 0; nt < 7; nt++)
                        mma_f16(acc[mt][nt], af[mt], bf[nt]);
            }
        }

        __syncthreads();
        if (s + 2 < 63) PREFETCH_GRP(s + 2, buf);
    }

    // ---- epilogue ----
    int yg = y0 + wm;
#pragma unroll
    for (int mt = 0; mt < 2; mt++) {
        int x1 = (mt << 4) + r4;
        int pos = (z << 10) + (yg << 5) + x1;
#pragma unroll
        for (int nt = 0; nt < 7; nt++) {
            int c = co0 + wn * 56 + (nt << 3) + (c4 << 1);
            if (c < CC) {
                float bb = bias[c];
                out[(size_t)c * V + pos] = acc[mt][nt][0] + bb;
                out[(size_t)c * V + pos + 8] = acc[mt][nt][2] + bb;
            }
            if (c + 1 < CC) {
                float bb = bias[c + 1];
                out[(size_t)(c + 1) * V + pos] = acc[mt][nt][1] + bb;
                out[(size_t)(c + 1) * V + pos + 8] = acc[mt][nt][3] + bb;
            }
        }
    }
}

// ======================= final 3-channel conv (fp32, 2 channels / iteration) =======================
__global__ void __launch_bounds__(256) conv_out_kernel(const float* __restrict__ in,
                                                       const float* __restrict__ w,
                                                       const float* __restrict__ bias,
                                                       float* __restrict__ out) {
    __shared__ float sp[1632];   // 2 x (4*6*34)
    __shared__ float sw[162];    // 2 x (3 co x 27)
    int tid = threadIdx.x;
    int z0 = (blockIdx.x >> 3) * 2;
    int y0 = (blockIdx.x & 7) * 4;
    int tz = tid >> 7, ty = (tid >> 5) & 3, tx = tid & 31;

    int poff[7]; bool pval[7]; int phalf[7];
#pragma unroll
    for (int k = 0; k < 7; k++) {
        int i = k * 256 + tid;
        int half = i / 816;
        int j = i - half * 816;
        int pz = j / 204, r = j % 204, py = r / 34, px = r % 34;
        int gz = z0 + pz - 1, gy = y0 + py - 1, gx = px - 1;
        pval[k] = (i < 1632) && ((unsigned)gz < 32u) && ((unsigned)gy < 32u) && ((unsigned)gx < 32u);
        poff[k] = (gz << 10) + (gy << 5) + gx;
        phalf[k] = half;
    }

    float acc[3] = {0.f, 0.f, 0.f};
    for (int c = 0; c < 110; c++) {            // pairs (2c, 2c+1), ci=219 padded to 0
        __syncthreads();
#pragma unroll
        for (int k = 0; k < 7; k++) {
            int i = k * 256 + tid;
            if (i < 1632) {
                int ch = 2 * c + phalf[k];
                sp[i] = (pval[k] && ch < CC) ? in[(size_t)ch * V + poff[k]] : 0.f;
            }
        }
        if (tid < 162) {
            int half = tid / 81;
            int t = tid - half * 81;
            int ch = 2 * c + half;
            sw[tid] = (ch < CC) ? w[((size_t)(t / 27) * CC + ch) * 27 + (t % 27)] : 0.f;
        }
        __syncthreads();
#pragma unroll
        for (int kz = 0; kz < 3; kz++)
#pragma unroll
            for (int ky = 0; ky < 3; ky++) {
                int base = ((tz + kz) * 6 + (ty + ky)) * 34 + tx;
#pragma unroll
                for (int kx = 0; kx < 3; kx++) {
                    int wt = (kz * 3 + ky) * 3 + kx;
                    float ve = sp[base + kx];
                    float vo = sp[816 + base + kx];
#pragma unroll
                    for (int co = 0; co < 3; co++)
                        acc[co] += sw[co * 27 + wt] * ve + sw[81 + co * 27 + wt] * vo;
                }
            }
    }
    int p = ((z0 + tz) << 10) + ((y0 + ty) << 5) + tx;
#pragma unroll
    for (int co = 0; co < 3; co++) out[(size_t)co * V + p] = acc[co] + bias[co];
}

// ======================= launch =======================
extern "C" void kernel_launch(void* const* d_in, const int* in_sizes, int n_in,
                              void* d_out, int out_size) {
    (void)in_sizes; (void)n_in; (void)out_size;
    const float* src   = (const float*)d_in[0];
    const float* tgt   = (const float*)d_in[1];
    const float* C     = (const float*)d_in[2];
    const float* up_w  = (const float*)d_in[3];
    const float* c1_w  = (const float*)d_in[5];
    const float* c1_b  = (const float*)d_in[6];
    const float* c2_w  = (const float*)d_in[7];
    const float* c2_b  = (const float*)d_in[8];
    const float* out_w = (const float*)d_in[9];
    const float* out_b = (const float*)d_in[10];
    float* dout = (float*)d_out;

    float *gx = nullptr, *gy = nullptr;
    cudaGetSymbolAddress((void**)&gx, g_x);
    cudaGetSymbolAddress((void**)&gy, g_y);

    const int CONV_SMEM = 82176;   // (9792 + 2*5376) uint32 words
    const int UP_SMEM = 85120;     // (4896 + 2*8192) uint32 words
    cudaFuncSetAttribute(conv3_mma_kernel, cudaFuncAttributeMaxDynamicSharedMemorySize, CONV_SMEM);
    cudaFuncSetAttribute(upsample_mma_kernel, cudaFuncAttributeMaxDynamicSharedMemorySize, UP_SMEM);

    // Stage 1: build concat input (224 channels, pads zeroed)
    pad_zero_kernel<<<640, 256>>>();
    copy_kernel<<<2048, 256>>>(tgt, src);
    corr_kernel<<<128, 256>>>(tgt, src);
    reorder_wu_kernel<<<3328, 256>>>(up_w);
    upsample_mma_kernel<<<dim3(32, 8), 256, UP_SMEM>>>(C);

    // IN + leaky on Cup (channels 155..218); raw Cup has no bias — IN cancels it exactly
    stats_kernel<<<64, 256>>>(gx + (size_t)155 * V);
    norm_leaky_kernel<<<dim3(32, 64), 256>>>(gx + (size_t)155 * V);

    // conv1 (fp16 HMMA, 2 CTAs/SM) + IN + leaky
    reorder_w_kernel<<<2646, 256>>>(c1_w);
    conv3_mma_kernel<<<dim3(256, 2), 256, CONV_SMEM>>>(gx, c1_b, gy);
    stats_kernel<<<CC, 256>>>(gy);
    norm_leaky_kernel<<<dim3(32, CC), 256>>>(gy);

    // conv2 (fp16 HMMA, 2 CTAs/SM) + IN + leaky  -> Cn in d_out[0 .. 219*V)
    reorder_w_kernel<<<2646, 256>>>(c2_w);
    conv3_mma_kernel<<<dim3(256, 2), 256, CONV_SMEM>>>(gy, c2_b, dout);
    stats_kernel<<<CC, 256>>>(dout);
    norm_leaky_kernel<<<dim3(32, CC), 256>>>(dout);

    // output conv -> d_out[219*V .. 222*V)
    conv_out_kernel<<<128, 256>>>(dout, out_w, out_b, dout + (size_t)CC * V);
}

// round 15
// speedup vs baseline: 5.5334x; 1.0463x over previous
#include <cuda_runtime.h>
#include <cuda_fp16.h>
#include <cstdint>

#define V 32768            // 32*32*32
#define CC 219             // real channels
#define CP 224             // padded channels (multiple of 32)

__device__ float g_x[CP * V];              // concat input [tgt(64), src(64), cost(27), Cup(64), pad(5)=0]
__device__ float g_y[CP * V];              // conv1 output (padded)
__device__ uint32_t g_wh[27 * 7 * 3584];   // conv weights half2-packed, 16B-seg swizzle
__device__ uint32_t g_wu[8 * 13 * 8 * 1024]; // upsample weights per parity

__device__ __forceinline__ uint32_t smem_u32(const void* p) {
    uint32_t a;
    asm("{ .reg .u64 t; cvta.to.shared.u64 t, %1; cvt.u32.u64 %0, t; }" : "=r"(a) : "l"(p));
    return a;
}
__device__ __forceinline__ void cp_async16(uint32_t dst, const void* src) {
    asm volatile("cp.async.cg.shared.global [%0], [%1], 16;" :: "r"(dst), "l"(src));
}
#define CP_COMMIT() asm volatile("cp.async.commit_group;" ::: "memory")
#define CP_WAIT1()  asm volatile("cp.async.wait_group 1;" ::: "memory")

__device__ __forceinline__ void mma_f16(float d[4], const uint32_t a[4], const uint32_t b[2]) {
    asm volatile(
        "mma.sync.aligned.m16n8k16.row.col.f32.f16.f16.f32 "
        "{%0,%1,%2,%3}, {%4,%5,%6,%7}, {%8,%9}, {%0,%1,%2,%3};"
        : "+f"(d[0]), "+f"(d[1]), "+f"(d[2]), "+f"(d[3])
        : "r"(a[0]), "r"(a[1]), "r"(a[2]), "r"(a[3]), "r"(b[0]), "r"(b[1]));
}
__device__ __forceinline__ void ldsm_x4(uint32_t r[4], uint32_t addr) {
    asm volatile("ldmatrix.sync.aligned.m8n8.x4.shared.b16 {%0,%1,%2,%3}, [%4];"
                 : "=r"(r[0]), "=r"(r[1]), "=r"(r[2]), "=r"(r[3]) : "r"(addr));
}
__device__ __forceinline__ void ldsm_x2(uint32_t r[2], uint32_t addr) {
    asm volatile("ldmatrix.sync.aligned.m8n8.x2.shared.b16 {%0,%1}, [%2];"
                 : "=r"(r[0]), "=r"(r[1]) : "r"(addr));
}

// ======================= small kernels =======================
__global__ void pad_zero_kernel() {
    int i = blockIdx.x * 256 + threadIdx.x;      // over 5*V
    g_x[(size_t)CC * V + i] = 0.f;
    g_y[(size_t)CC * V + i] = 0.f;
}

__global__ void copy_kernel(const float* __restrict__ tgt, const float* __restrict__ src) {
    int i = blockIdx.x * 256 + threadIdx.x;   // over 64*V/4 float4
    float4* dx = (float4*)g_x;
    dx[i] = ((const float4*)tgt)[i];
    dx[(64 * V) / 4 + i] = ((const float4*)src)[i];
}

// conv weight reorder: half2 pack + 16B-granular swizzle.
__global__ void reorder_w_kernel(const float* __restrict__ w) {
    int id = blockIdx.x * 256 + threadIdx.x;     // < 27*7*3584 = 677376
    if (id >= 27 * 7 * 3584) return;
    int blob = id / 3584, r = id % 3584;
    int tap = blob / 7, cib = blob % 7;
    int co = r >> 4, jj = r & 15;
    int wlog = (((jj >> 2) ^ ((co >> 1) & 3)) << 2) | (jj & 3);
    int ci0 = cib * 32 + 2 * wlog;
    float v0 = 0.f, v1 = 0.f;
    if (co < CC) {
        if (ci0 < CC)     v0 = w[((size_t)co * CC + ci0) * 27 + tap];
        if (ci0 + 1 < CC) v1 = w[((size_t)co * CC + ci0 + 1) * 27 + tap];
    }
    half2 h = __floats2half2_rn(v0, v1);
    g_wh[id] = *(uint32_t*)&h;
}

// upsample weight reorder: per parity class p, tap t -> (kz,ky,kx) of the 4x4x4 kernel.
__global__ void reorder_wu_kernel(const float* __restrict__ w) {
    int id = blockIdx.x * 256 + threadIdx.x;     // < 851968
    if (id >= 8 * 13 * 8 * 1024) return;
    int jj = id & 15;
    int t = id >> 4;
    int co = t & 63; t >>= 6;
    int tap = t & 7; t >>= 3;
    int cib = t % 13;
    int p = t / 13;
    int pz = p >> 2, py = (p >> 1) & 1, px = p & 1;
    int tz = tap >> 2, ty = (tap >> 1) & 1, tx = tap & 1;
    int kz = (1 - pz) + 2 * tz;
    int ky = (1 - py) + 2 * ty;
    int kx = (1 - px) + 2 * tx;
    int wlog = (((jj >> 2) ^ ((co >> 1) & 3)) << 2) | (jj & 3);
    int ci0 = cib * 32 + 2 * wlog;
    float v0 = 0.f, v1 = 0.f;
    if (ci0 < 411)     v0 = w[((size_t)ci0 * 64 + co) * 64 + kz * 16 + ky * 4 + kx];
    if (ci0 + 1 < 411) v1 = w[((size_t)(ci0 + 1) * 64 + co) * 64 + kz * 16 + ky * 4 + kx];
    half2 h = __floats2half2_rn(v0, v1);
    g_wu[id] = *(uint32_t*)&h;
}

// ======================= correlation volume (4 channels / iteration) =======================
__global__ void __launch_bounds__(256) corr_kernel(const float* __restrict__ tgt,
                                                   const float* __restrict__ src) {
    __shared__ float sp[3264];   // 4 x (4*6*34) patches
    int tid = threadIdx.x;
    int z0 = (blockIdx.x >> 3) * 2;
    int y0 = (blockIdx.x & 7) * 4;
    int tz = tid >> 7, ty = (tid >> 5) & 3, tx = tid & 31;
    int z = z0 + tz, y = y0 + ty;
    int p = (z << 10) + (y << 5) + tx;

    int poff[13]; bool pval[13]; int phalf[13];
#pragma unroll
    for (int k = 0; k < 13; k++) {
        int i = k * 256 + tid;
        int half = i / 816;
        int j = i - half * 816;
        int pz = j / 204, r = j % 204, py = r / 34, px = r % 34;
        int gz = z0 + pz - 1, gy = y0 + py - 1, gx = px - 1;
        pval[k] = (i < 3264) && ((unsigned)gz < 32u) && ((unsigned)gy < 32u) && ((unsigned)gx < 32u);
        poff[k] = (gz << 10) + (gy << 5) + gx;
        phalf[k] = half;
    }

    float acc[27];
#pragma unroll
    for (int d = 0; d < 27; d++) acc[d] = 0.f;

    for (int c = 0; c < 16; c++) {       // 16 iterations x 4 channels
        __syncthreads();
#pragma unroll
        for (int k = 0; k < 13; k++) {
            int i = k * 256 + tid;
            if (i < 3264) sp[i] = pval[k] ? src[(size_t)(4 * c + phalf[k]) * V + poff[k]] : 0.f;
        }
        __syncthreads();
        float t0 = tgt[(size_t)(4 * c) * V + p];
        float t1 = tgt[(size_t)(4 * c + 1) * V + p];
        float t2 = tgt[(size_t)(4 * c + 2) * V + p];
        float t3 = tgt[(size_t)(4 * c + 3) * V + p];
#pragma unroll
        for (int dz = 0; dz < 3; dz++)
#pragma unroll
            for (int dy = 0; dy < 3; dy++) {
                int base = ((tz + dz) * 6 + (ty + dy)) * 34 + tx;
#pragma unroll
                for (int q = 0; q < 3; q++)
                    acc[dz * 9 + dy * 3 + q] += t0 * sp[base + q] + t1 * sp[816 + base + q]
                                              + t2 * sp[1632 + base + q] + t3 * sp[2448 + base + q];
            }
    }
    const float inv = 1.f / 64.f;
#pragma unroll
    for (int d = 0; d < 27; d++) g_x[(size_t)(128 + d) * V + p] = acc[d] * inv;
}

// ======================= upsample as fp16 implicit GEMM (proven R13) =======================
__global__ void __launch_bounds__(256, 2) upsample_mma_kernel(const float* __restrict__ Cin) {
    extern __shared__ uint32_t smem32[];
    uint32_t* P = smem32;                    // 4896 words
    uint32_t sbase = smem_u32(smem32);
    const uint32_t PBYTE = 19584u;

    int tid = threadIdx.x, wid = tid >> 5, lane = tid & 31;
    int a = blockIdx.x >> 1, b0 = (blockIdx.x & 1) * 8;
    int par = blockIdx.y;
    int pz = par >> 2, py = (par >> 1) & 1, px = par & 1;

    int wm = wid >> 1, wn = wid & 1;
    int r4 = lane >> 2, c4 = lane & 3;
    int sub = lane >> 3, l7 = lane & 7;
    int a_lro = ((sub & 1) << 3) + l7;
    int a_sh = sub >> 1;
    int b_segbit = sub & 1;
    int b_ntoff = sub >> 1;
    uint32_t bco[2]; int bsw[2];
#pragma unroll
    for (int t2 = 0; t2 < 2; t2++) {
        int co = wn * 32 + (2 * t2 + b_ntoff) * 8 + l7;
        bco[t2] = (uint32_t)(co << 6);
        bsw[t2] = (co >> 1) & 3;
    }

    float acc[2][4][4];
#pragma unroll
    for (int i = 0; i < 2; i++)
#pragma unroll
        for (int j = 0; j < 4; j++)
#pragma unroll
            for (int k = 0; k < 4; k++) acc[i][j][k] = 0.f;

#define PREFETCH_U(s_, buf_) do { \
        int cib_ = (s_); \
        uint32_t dbase = sbase + PBYTE + (uint32_t)(buf_) * 32768u; \
        _Pragma("unroll") \
        for (int it = 0; it < 8; it++) { \
            int i = tid + it * 256; \
            int tl = i >> 8, rem = i & 255; \
            const uint32_t* src = g_wu + ((size_t)((par * 13 + cib_) * 8 + tl) << 10) + rem * 4; \
            cp_async16(dbase + (uint32_t)((tl << 12) + (rem << 4)), src); \
        } \
        CP_COMMIT(); \
    } while (0)

    PREFETCH_U(0, 0);
    PREFETCH_U(1, 1);

    for (int s = 0; s < 13; s++) {
        int buf = s & 1;
        {
            int cig0 = s * 32;
#pragma unroll 4
            for (int jj = 0; jj < 36; jj++) {
                int pp = wid + jj * 8;           // 0..287
                int wword = pp & 15;
                int rowslot = pp >> 4;           // 0..17
                int slot = rowslot / 9, ry = rowslot - slot * 9;
                int iz = a + pz - 1 + slot;
                int iy = b0 + py - 1 + ry;
                bool rowok = ((unsigned)iz < 16u) && ((unsigned)iy < 16u);
                int c0 = cig0 + 2 * wword;
                const float* s0 = Cin + (size_t)c0 * 4096 + (iz << 8) + (iy << 4);
                if (lane < 17) {
                    int ix = px - 1 + lane;
                    bool ok = rowok && ((unsigned)ix < 16u);
                    float v0 = (ok && c0 < 411) ? __ldg(s0 + ix) : 0.f;
                    float v1 = (ok && c0 + 1 < 411) ? __ldg(s0 + 4096 + ix) : 0.f;
                    half2 h = __floats2half2_rn(v0, v1);
                    int row = slot * 153 + ry * 17 + lane;
                    int st = (((wword >> 2) ^ ((row >> 1) & 3)) << 2) | (wword & 3);
                    P[row * 16 + st] = *(uint32_t*)&h;
                }
            }
        }
        CP_WAIT1();
        __syncthreads();

#pragma unroll
        for (int tap = 0; tap < 8; tap++) {
            int tz = tap >> 2, ty = (tap >> 1) & 1, tx = tap & 1;
            int vb0 = (1 - tz) * 153 + (2 * wm + 1 - ty) * 17 + (1 - tx);
            uint32_t Bbb = sbase + PBYTE + (uint32_t)buf * 32768u + (uint32_t)tap * 4096u;

#pragma unroll
            for (int ks = 0; ks < 2; ks++) {
                uint32_t af[2][4];
#pragma unroll
                for (int mt = 0; mt < 2; mt++) {
                    int v = vb0 + mt * 17 + a_lro;
                    uint32_t ad = sbase + (uint32_t)(v << 6)
                                + (uint32_t)((((ks << 1) + a_sh) ^ ((v >> 1) & 3)) << 4);
                    ldsm_x4(af[mt], ad);
                }
                uint32_t bf[4][2];
#pragma unroll
                for (int t2 = 0; t2 < 2; t2++) {
                    uint32_t r[4];
                    uint32_t ad = Bbb + bco[t2] + (uint32_t)((((ks << 1) + b_segbit) ^ bsw[t2]) << 4);
                    ldsm_x4(r, ad);
                    bf[2 * t2][0] = r[0]; bf[2 * t2][1] = r[1];
                    bf[2 * t2 + 1][0] = r[2]; bf[2 * t2 + 1][1] = r[3];
                }
#pragma unroll
                for (int mt = 0; mt < 2; mt++)
#pragma unroll
                    for (int nt = 0; nt < 4; nt++)
                        mma_f16(acc[mt][nt], af[mt], bf[nt]);
            }
        }
        __syncthreads();
        if (s + 2 < 13) PREFETCH_U(s + 2, buf);
    }

    int oz = 2 * a + pz;
#pragma unroll
    for (int mt = 0; mt < 2; mt++) {
        int bl = 2 * wm + mt;
        int oy = 2 * (b0 + bl) + py;
        int base = (oz << 10) + (oy << 5) + px;
#pragma unroll
        for (int nt = 0; nt < 4; nt++) {
            int co = wn * 32 + (nt << 3) + (c4 << 1);
            size_t ch0 = (size_t)(155 + co) * V;
            size_t ch1 = (size_t)(156 + co) * V;
            int o1 = base + 2 * r4, o2 = base + 2 * (r4 + 8);
            g_x[ch0 + o1] = acc[mt][nt][0];
            g_x[ch0 + o2] = acc[mt][nt][2];
            g_x[ch1 + o1] = acc[mt][nt][1];
            g_x[ch1 + o2] = acc[mt][nt][3];
        }
    }
}

// ======================= fused instance norm: stats + normalize + leaky ====
__global__ void __launch_bounds__(256) instnorm_kernel(float* __restrict__ x) {
    int ch = blockIdx.x;
    float4* p4 = (float4*)(x + (size_t)ch * V);
    float s = 0.f, s2 = 0.f;
    for (int i = threadIdx.x; i < V / 4; i += 256) {
        float4 v = p4[i];
        s += v.x + v.y + v.z + v.w;
        s2 += v.x * v.x + v.y * v.y + v.z * v.z + v.w * v.w;
    }
#pragma unroll
    for (int o = 16; o; o >>= 1) {
        s += __shfl_down_sync(0xffffffffu, s, o);
        s2 += __shfl_down_sync(0xffffffffu, s2, o);
    }
    __shared__ float a[8], b[8];
    __shared__ float smr[2];
    int wp = threadIdx.x >> 5, ln = threadIdx.x & 31;
    if (ln == 0) { a[wp] = s; b[wp] = s2; }
    __syncthreads();
    if (threadIdx.x < 8) {
        s = a[threadIdx.x]; s2 = b[threadIdx.x];
#pragma unroll
        for (int o = 4; o; o >>= 1) {
            s += __shfl_down_sync(0xffu, s, o);
            s2 += __shfl_down_sync(0xffu, s2, o);
        }
        if (threadIdx.x == 0) {
            float m = s * (1.f / V);
            float var = s2 * (1.f / V) - m * m;
            smr[0] = m;
            smr[1] = rsqrtf(var + 1e-5f);
        }
    }
    __syncthreads();
    float m = smr[0], r = smr[1];
    for (int i = threadIdx.x; i < V / 4; i += 256) {
        float4 v = p4[i];
        v.x = (v.x - m) * r; v.x = v.x >= 0.f ? v.x : 0.1f * v.x;
        v.y = (v.y - m) * r; v.y = v.y >= 0.f ? v.y : 0.1f * v.y;
        v.z = (v.z - m) * r; v.z = v.z >= 0.f ? v.z : 0.1f * v.z;
        v.w = (v.w - m) * r; v.w = v.w >= 0.f ? v.w : 0.1f * v.w;
        p4[i] = v;
    }
}

// ======================= fp16 HMMA conv3x3x3: 2 CTAs/SM, cp.async 3-tap B groups ========
__global__ void __launch_bounds__(256, 2) conv3_mma_kernel(const float* __restrict__ in,
                                                           const float* __restrict__ bias,
                                                           float* __restrict__ out) {
    extern __shared__ uint32_t smem32[];
    uint32_t* P = smem32;                    // 9792 words
    uint32_t sbase = smem_u32(smem32);
    const uint32_t BBYTE = 9792u * 4u;       // byte offset of B buffers (2 x 21504 B)

    int tid = threadIdx.x, wid = tid >> 5, lane = tid & 31;
    int z = blockIdx.x >> 3, yt = blockIdx.x & 7;
    int y0 = yt * 4;
    int co0 = blockIdx.y * 112;

    int wm = wid >> 1, wn = wid & 1;         // wm = local y row
    int r4 = lane >> 2, c4 = lane & 3;

    int sub = lane >> 3, l7 = lane & 7;
    int a_lro = ((sub & 1) << 3) + l7;
    int a_sh = sub >> 1;
    int b_segbit = sub & 1;
    int b_ntoff = sub >> 1;
    uint32_t bco[4]; int bsw[4];
#pragma unroll
    for (int t = 0; t < 3; t++) {
        int co = wn * 56 + (2 * t + b_ntoff) * 8 + l7;
        bco[t] = (uint32_t)(co << 6);
        bsw[t] = (co >> 1) & 3;
    }
    {
        int co = wn * 56 + 48 + l7;
        bco[3] = (uint32_t)(co << 6);
        bsw[3] = (co >> 1) & 3;
    }

    float acc[2][7][4];
#pragma unroll
    for (int a = 0; a < 2; a++)
#pragma unroll
        for (int b = 0; b < 7; b++)
#pragma unroll
            for (int c = 0; c < 4; c++) acc[a][b][c] = 0.f;

#define PREFETCH_GRP(s_, buf_) do { \
        int cib_ = (s_) / 9, grp_ = (s_) % 9; \
        uint32_t dbase = sbase + BBYTE + (uint32_t)(buf_) * 21504u; \
        _Pragma("unroll") \
        for (int it = 0; it < 6; it++) { \
            int i = tid + it * 256; \
            if (i < 1344) { \
                int tl = i / 448, rem = i - tl * 448; \
                const uint32_t* src = g_wh + (size_t)((grp_ * 3 + tl) * 7 + cib_) * 3584 + co0 * 16 + rem * 4; \
                cp_async16(dbase + (uint32_t)(tl * 7168 + rem * 16), src); \
            } \
        } \
        CP_COMMIT(); \
    } while (0)

    PREFETCH_GRP(0, 0);
    PREFETCH_GRP(1, 1);

    for (int s = 0; s < 63; s++) {
        int cib = s / 9, grp = s - cib * 9;
        int buf = s & 1;

        if (grp == 0) {
            int cig0 = cib * 32;
#pragma unroll 4
            for (int jj = 0; jj < 36; jj++) {
                int p = wid + jj * 8;        // 0..287
                int wword = p & 15;
                int rowid = p >> 4;          // 0..17 (3z x 6y)
                int pz = rowid / 6, py = rowid - pz * 6;
                int gz = z + pz - 1, gy = y0 + py - 1;
                bool rowok = ((unsigned)gz < 32u) && ((unsigned)gy < 32u);
                const float* s0 = in + (size_t)(cig0 + 2 * wword) * V + (gz << 10) + (gy << 5);
#pragma unroll
                for (int q = 0; q < 2; q++) {
                    int px = lane + q * 32;
                    if (px < 34) {
                        int gx = px - 1;
                        bool ok = rowok && ((unsigned)gx < 32u);
                        float v0 = ok ? __ldg(s0 + gx) : 0.f;
                        float v1 = ok ? __ldg(s0 + V + gx) : 0.f;
                        half2 h = __floats2half2_rn(v0, v1);
                        int voxel = rowid * 34 + px;
                        int st = (((wword >> 2) ^ ((voxel >> 1) & 3)) << 2) | (wword & 3);
                        P[voxel * 16 + st] = *(uint32_t*)&h;
                    }
                }
            }
        }

        CP_WAIT1();
        __syncthreads();      // B(buf) ready + patch visible

#pragma unroll
        for (int t = 0; t < 3; t++) {
            int tap = grp * 3 + t;
            int dz = tap / 9, rem = tap - dz * 9;
            int dy = rem / 3, dx = rem - dy * 3;
            int vb = (dz * 6 + wm + dy) * 34 + dx;
            uint32_t Bbb = sbase + BBYTE + (uint32_t)buf * 21504u + (uint32_t)t * 7168u;

#pragma unroll
            for (int ks = 0; ks < 2; ks++) {
                uint32_t af[2][4];
#pragma unroll
                for (int mt = 0; mt < 2; mt++) {
                    int v = vb + a_lro + (mt << 4);
                    uint32_t ad = sbase + (uint32_t)(v << 6)
                                + (uint32_t)((((ks << 1) + a_sh) ^ ((v >> 1) & 3)) << 4);
                    ldsm_x4(af[mt], ad);
                }
                uint32_t bf[7][2];
#pragma unroll
                for (int t2 = 0; t2 < 3; t2++) {
                    uint32_t r[4];
                    uint32_t ad = Bbb + bco[t2] + (uint32_t)((((ks << 1) + b_segbit) ^ bsw[t2]) << 4);
                    ldsm_x4(r, ad);
                    bf[2 * t2][0] = r[0]; bf[2 * t2][1] = r[1];
                    bf[2 * t2 + 1][0] = r[2]; bf[2 * t2 + 1][1] = r[3];
                }
                {
                    uint32_t r2[2];
                    uint32_t ad = Bbb + bco[3] + (uint32_t)((((ks << 1) + b_segbit) ^ bsw[3]) << 4);
                    ldsm_x2(r2, ad);
                    bf[6][0] = r2[0]; bf[6][1] = r2[1];
                }
#pragma unroll
                for (int mt = 0; mt < 2; mt++)
#pragma unroll
                    for (int nt = 0; nt < 7; nt++)
                        mma_f16(acc[mt][nt], af[mt], bf[nt]);
            }
        }

        __syncthreads();
        if (s + 2 < 63) PREFETCH_GRP(s + 2, buf);
    }

    // ---- epilogue ----
    int yg = y0 + wm;
#pragma unroll
    for (int mt = 0; mt < 2; mt++) {
        int x1 = (mt << 4) + r4;
        int pos = (z << 10) + (yg << 5) + x1;
#pragma unroll
        for (int nt = 0; nt < 7; nt++) {
            int c = co0 + wn * 56 + (nt << 3) + (c4 << 1);
            if (c < CC) {
                float bb = bias[c];
                out[(size_t)c * V + pos] = acc[mt][nt][0] + bb;
                out[(size_t)c * V + pos + 8] = acc[mt][nt][2] + bb;
            }
            if (c + 1 < CC) {
                float bb = bias[c + 1];
                out[(size_t)(c + 1) * V + pos] = acc[mt][nt][1] + bb;
                out[(size_t)(c + 1) * V + pos + 8] = acc[mt][nt][3] + bb;
            }
        }
    }
}

// ======================= final 3-channel conv (fp32, 4 channels / iteration) =======================
__global__ void __launch_bounds__(256) conv_out_kernel(const float* __restrict__ in,
                                                       const float* __restrict__ w,
                                                       const float* __restrict__ bias,
                                                       float* __restrict__ out) {
    __shared__ float sp[3264];   // 4 x (4*6*34)
    __shared__ float sw[324];    // 4 x (3 co x 27)
    int tid = threadIdx.x;
    int z0 = (blockIdx.x >> 3) * 2;
    int y0 = (blockIdx.x & 7) * 4;
    int tz = tid >> 7, ty = (tid >> 5) & 3, tx = tid & 31;

    int poff[13]; bool pval[13]; int phalf[13];
#pragma unroll
    for (int k = 0; k < 13; k++) {
        int i = k * 256 + tid;
        int half = i / 816;
        int j = i - half * 816;
        int pz = j / 204, r = j % 204, py = r / 34, px = r % 34;
        int gz = z0 + pz - 1, gy = y0 + py - 1, gx = px - 1;
        pval[k] = (i < 3264) && ((unsigned)gz < 32u) && ((unsigned)gy < 32u) && ((unsigned)gx < 32u);
        poff[k] = (gz << 10) + (gy << 5) + gx;
        phalf[k] = half;
    }

    float acc[3] = {0.f, 0.f, 0.f};
    for (int c = 0; c < 55; c++) {            // quads (4c..4c+3), ci>=219 padded to 0
        __syncthreads();
#pragma unroll
        for (int k = 0; k < 13; k++) {
            int i = k * 256 + tid;
            if (i < 3264) {
                int ch = 4 * c + phalf[k];
                sp[i] = (pval[k] && ch < CC) ? in[(size_t)ch * V + poff[k]] : 0.f;
            }
        }
        // weight stage: 324 entries with 256 threads -> 2 strided passes (bug fix vs R14)
#pragma unroll
        for (int wpass = 0; wpass < 2; wpass++) {
            int i = tid + wpass * 256;
            if (i < 324) {
                int half = i / 81;
                int t = i - half * 81;
                int ch = 4 * c + half;
                sw[i] = (ch < CC) ? w[((size_t)(t / 27) * CC + ch) * 27 + (t % 27)] : 0.f;
            }
        }
        __syncthreads();
#pragma unroll
        for (int kz = 0; kz < 3; kz++)
#pragma unroll
            for (int ky = 0; ky < 3; ky++) {
                int base = ((tz + kz) * 6 + (ty + ky)) * 34 + tx;
#pragma unroll
                for (int kx = 0; kx < 3; kx++) {
                    int wt = (kz * 3 + ky) * 3 + kx;
                    float v0 = sp[base + kx];
                    float v1 = sp[816 + base + kx];
                    float v2 = sp[1632 + base + kx];
                    float v3 = sp[2448 + base + kx];
#pragma unroll
                    for (int co = 0; co < 3; co++)
                        acc[co] += sw[co * 27 + wt] * v0 + sw[81 + co * 27 + wt] * v1
                                 + sw[162 + co * 27 + wt] * v2 + sw[243 + co * 27 + wt] * v3;
                }
            }
    }
    int p = ((z0 + tz) << 10) + ((y0 + ty) << 5) + tx;
#pragma unroll
    for (int co = 0; co < 3; co++) out[(size_t)co * V + p] = acc[co] + bias[co];
}

// ======================= launch =======================
extern "C" void kernel_launch(void* const* d_in, const int* in_sizes, int n_in,
                              void* d_out, int out_size) {
    (void)in_sizes; (void)n_in; (void)out_size;
    const float* src   = (const float*)d_in[0];
    const float* tgt   = (const float*)d_in[1];
    const float* C     = (const float*)d_in[2];
    const float* up_w  = (const float*)d_in[3];
    const float* c1_w  = (const float*)d_in[5];
    const float* c1_b  = (const float*)d_in[6];
    const float* c2_w  = (const float*)d_in[7];
    const float* c2_b  = (const float*)d_in[8];
    const float* out_w = (const float*)d_in[9];
    const float* out_b = (const float*)d_in[10];
    float* dout = (float*)d_out;

    float *gx = nullptr, *gy = nullptr;
    cudaGetSymbolAddress((void**)&gx, g_x);
    cudaGetSymbolAddress((void**)&gy, g_y);

    const int CONV_SMEM = 82176;   // (9792 + 2*5376) uint32 words
    const int UP_SMEM = 85120;     // (4896 + 2*8192) uint32 words
    cudaFuncSetAttribute(conv3_mma_kernel, cudaFuncAttributeMaxDynamicSharedMemorySize, CONV_SMEM);
    cudaFuncSetAttribute(upsample_mma_kernel, cudaFuncAttributeMaxDynamicSharedMemorySize, UP_SMEM);

    // Stage 1: build concat input (224 channels, pads zeroed)
    pad_zero_kernel<<<640, 256>>>();
    copy_kernel<<<2048, 256>>>(tgt, src);
    corr_kernel<<<128, 256>>>(tgt, src);
    reorder_wu_kernel<<<3328, 256>>>(up_w);
    upsample_mma_kernel<<<dim3(32, 8), 256, UP_SMEM>>>(C);

    // IN + leaky on Cup (channels 155..218); raw Cup has no bias — IN cancels it exactly
    instnorm_kernel<<<64, 256>>>(gx + (size_t)155 * V);

    // conv1 (fp16 HMMA, 2 CTAs/SM) + IN + leaky
    reorder_w_kernel<<<2646, 256>>>(c1_w);
    conv3_mma_kernel<<<dim3(256, 2), 256, CONV_SMEM>>>(gx, c1_b, gy);
    instnorm_kernel<<<CC, 256>>>(gy);

    // conv2 (fp16 HMMA, 2 CTAs/SM) + IN + leaky  -> Cn in d_out[0 .. 219*V)
    reorder_w_kernel<<<2646, 256>>>(c2_w);
    conv3_mma_kernel<<<dim3(256, 2), 256, CONV_SMEM>>>(gy, c2_b, dout);
    instnorm_kernel<<<CC, 256>>>(dout);

    // output conv -> d_out[219*V .. 222*V)
    conv_out_kernel<<<128, 256>>>(dout, out_w, out_b, dout + (size_t)CC * V);
}